// round 1
// baseline (speedup 1.0000x reference)
#include <cuda_runtime.h>

// ---------------------------------------------------------------------------
// CTRL transformer forward: B=2, S=1024, D=1280, H=16, DH=80, DFF=8192, L=4
// Round 1: fp32 SIMT GEMMs (128x128x8 tile, 8x8/thread), materialized
// attention, fused epilogues. All scratch in __device__ globals.
// ---------------------------------------------------------------------------

#define BB   2
#define SS   1024
#define DD   1280
#define HH   16
#define DHH  80
#define DFF  8192
#define LL   4
#define MM   (BB * SS)          // 2048 token rows

// scratch (device globals; no allocation allowed)
__device__ float g_x[MM * DD];           // residual stream
__device__ float g_n[MM * DD];           // LN output / ctx buffer
__device__ float g_q[MM * DD];           // q  (also reused for LN2 output)
__device__ float g_k[MM * DD];
__device__ float g_v[MM * DD];
__device__ float g_scores[BB * HH * SS * SS];   // 32 * 1M = 128 MB
__device__ float g_h1[MM * DFF];                // 67 MB
__device__ int   g_ids64;                       // 1 if ids are int64

// ---------------------------------------------------------------------------
// Detect whether input_ids is int64 or int32 (memory-safe: reads first 8 KB,
// valid under both layouts). int64 little-endian => all odd 32-bit words of
// the first 1024 ids are zero (ids in [0, 32000)).
// ---------------------------------------------------------------------------
__global__ void detect_kernel(const unsigned int* __restrict__ w) {
    __shared__ int any;
    if (threadIdx.x == 0) any = 0;
    __syncthreads();
    int loc = 0;
    for (int i = 2 * threadIdx.x + 1; i < 2048; i += 512)
        loc |= (w[i] != 0u);
    if (loc) atomicOr(&any, 1);
    __syncthreads();
    if (threadIdx.x == 0) g_ids64 = any ? 0 : 1;
}

// ---------------------------------------------------------------------------
// Embedding * sqrt(D) + sinusoidal positional encoding
// pe[s, m]      = sin(s * 10000^(-2m/D))      m in [0, 640)
// pe[s, 640+m]  = cos(s * 10000^(-2m/D))
// ---------------------------------------------------------------------------
__global__ void embed_kernel(const unsigned int* __restrict__ idw,
                             const float* __restrict__ emb,
                             float* __restrict__ x) {
    int idx = blockIdx.x * 256 + threadIdx.x;
    if (idx >= MM * DD) return;
    int d   = idx % DD;
    int row = idx / DD;
    int s   = row & (SS - 1);
    int id  = g_ids64 ? (int)idw[2 * row] : (int)idw[row];

    float val = emb[(long long)id * DD + d] * 35.77708763999664f;  // sqrt(1280)

    int m = (d < 640) ? d : d - 640;
    // rate = 10000^(-2m/1280) = exp(-m * 2*ln(10000)/1280)
    float rate = expf(-0.014391156831212787f * (float)m);
    float ang  = (float)s * rate;
    val += (d < 640) ? sinf(ang) : cosf(ang);
    x[idx] = val;
}

// ---------------------------------------------------------------------------
// LayerNorm over D=1280, one block (256 thr) per row, values cached in regs.
// Two-pass (mean, then E[(x-mu)^2]) to match reference numerics.
// ---------------------------------------------------------------------------
__device__ __forceinline__ float warp_sum(float v) {
#pragma unroll
    for (int o = 16; o; o >>= 1) v += __shfl_xor_sync(0xffffffffu, v, o);
    return v;
}

__global__ void layernorm_kernel(const float* __restrict__ x,
                                 float* __restrict__ o,
                                 const float* __restrict__ g,
                                 const float* __restrict__ b) {
    const int row = blockIdx.x;
    const int t   = threadIdx.x;
    const float* xr = x + (long long)row * DD;
    __shared__ float red[8];

    float v[5];
    float s = 0.0f;
#pragma unroll
    for (int i = 0; i < 5; i++) { v[i] = xr[t + 256 * i]; s += v[i]; }
    s = warp_sum(s);
    if ((t & 31) == 0) red[t >> 5] = s;
    __syncthreads();
    float mu = (red[0] + red[1] + red[2] + red[3] +
                red[4] + red[5] + red[6] + red[7]) * (1.0f / 1280.0f);
    __syncthreads();

    float q = 0.0f;
#pragma unroll
    for (int i = 0; i < 5; i++) { float dv = v[i] - mu; q += dv * dv; }
    q = warp_sum(q);
    if ((t & 31) == 0) red[t >> 5] = q;
    __syncthreads();
    float var = (red[0] + red[1] + red[2] + red[3] +
                 red[4] + red[5] + red[6] + red[7]) * (1.0f / 1280.0f);
    float rstd = rsqrtf(var + 1e-6f);

    float* orow = o + (long long)row * DD;
#pragma unroll
    for (int i = 0; i < 5; i++) {
        int c = t + 256 * i;
        orow[c] = (v[i] - mu) * rstd * g[c] + b[c];
    }
}

// ---------------------------------------------------------------------------
// Row softmax over 1024 columns (scores buffer), one block per row.
// ---------------------------------------------------------------------------
__global__ void softmax_kernel(float* __restrict__ sc) {
    const long long row = blockIdx.x;
    float* p = sc + row * (long long)SS;
    const int t = threadIdx.x;
    __shared__ float red[8];

    float v[4];
    float mx = -3.4e38f;
#pragma unroll
    for (int i = 0; i < 4; i++) { v[i] = p[t + 256 * i]; mx = fmaxf(mx, v[i]); }
#pragma unroll
    for (int o = 16; o; o >>= 1) mx = fmaxf(mx, __shfl_xor_sync(0xffffffffu, mx, o));
    if ((t & 31) == 0) red[t >> 5] = mx;
    __syncthreads();
    mx = fmaxf(fmaxf(fmaxf(red[0], red[1]), fmaxf(red[2], red[3])),
               fmaxf(fmaxf(red[4], red[5]), fmaxf(red[6], red[7])));
    __syncthreads();

    float s = 0.0f;
#pragma unroll
    for (int i = 0; i < 4; i++) { v[i] = expf(v[i] - mx); s += v[i]; }
    s = warp_sum(s);
    if ((t & 31) == 0) red[t >> 5] = s;
    __syncthreads();
    s = red[0] + red[1] + red[2] + red[3] + red[4] + red[5] + red[6] + red[7];
    float inv = 1.0f / s;
#pragma unroll
    for (int i = 0; i < 4; i++) p[t + 256 * i] = v[i] * inv;
}

// ---------------------------------------------------------------------------
// General fp32 GEMM: C = alpha * A @ B(^T) [+ bias] [+ causal mask] [relu]
//                        [+ resid], batched via blockIdx.z with (z/16, z%16)
// offset decomposition (strides per operand). Tile 128x128x8, 256 threads,
// 8x8 accumulators per thread. M and K must be multiples of 128 / 8 (true
// for every call here); N is guarded.
// ---------------------------------------------------------------------------
template <bool TRANSB, bool RELU, bool MASK>
__global__ void __launch_bounds__(256)
gemm_kernel(const float* __restrict__ A, const float* __restrict__ B,
            float* __restrict__ C,
            const float* __restrict__ bias, const float* __restrict__ resid,
            int M, int N, int K, int lda, int ldb, int ldc,
            long long sA1, long long sA2, long long sB1, long long sB2,
            long long sC1, long long sC2, float alpha) {
    const int z  = blockIdx.z;
    const int zb = z >> 4;
    const int zh = z & 15;
    A += zb * sA1 + zh * sA2;
    B += zb * sB1 + zh * sB2;
    const long long coff = zb * sC1 + zh * sC2;
    C += coff;
    if (resid) resid += coff;

    __shared__ float As[8][132];
    __shared__ float Bs[8][132];

    const int tid = threadIdx.x;
    const int m0 = blockIdx.y * 128;
    const int n0 = blockIdx.x * 128;

    const int la_m = tid >> 1;             // 0..127
    const int la_k = (tid & 1) << 2;       // 0 or 4
    const int tr = (tid >> 4) << 3;        // thread row base
    const int tc = (tid & 15) << 3;        // thread col base

    float acc[8][8] = {};

    for (int k0 = 0; k0 < K; k0 += 8) {
        // A tile: 128(m) x 8(k), float4 along K, stored transposed [k][m]
        {
            float4 av = *reinterpret_cast<const float4*>(
                A + (long long)(m0 + la_m) * lda + k0 + la_k);
            As[la_k + 0][la_m] = av.x;
            As[la_k + 1][la_m] = av.y;
            As[la_k + 2][la_m] = av.z;
            As[la_k + 3][la_m] = av.w;
        }
        if (!TRANSB) {
            // B tile: 8(k) x 128(n), row-major, float4 along N (N-guarded)
            const int bk = tid >> 5;
            const int bn = (tid & 31) << 2;
            const int n = n0 + bn;
            const float* bp = B + (long long)(k0 + bk) * ldb + n;
            float4 bv;
            if (n + 3 < N) {
                bv = *reinterpret_cast<const float4*>(bp);
            } else {
                bv.x = (n + 0 < N) ? bp[0] : 0.0f;
                bv.y = (n + 1 < N) ? bp[1] : 0.0f;
                bv.z = (n + 2 < N) ? bp[2] : 0.0f;
                bv.w = (n + 3 < N) ? bp[3] : 0.0f;
            }
            *reinterpret_cast<float4*>(&Bs[bk][bn]) = bv;
        } else {
            // B is [N, K]: tile 128(n) x 8(k), float4 along K, transposed store
            const int bn = tid >> 1;
            const int bk = (tid & 1) << 2;
            float4 bv = *reinterpret_cast<const float4*>(
                B + (long long)(n0 + bn) * ldb + k0 + bk);
            Bs[bk + 0][bn] = bv.x;
            Bs[bk + 1][bn] = bv.y;
            Bs[bk + 2][bn] = bv.z;
            Bs[bk + 3][bn] = bv.w;
        }
        __syncthreads();

#pragma unroll
        for (int kk = 0; kk < 8; kk++) {
            float a[8], bf[8];
#pragma unroll
            for (int i = 0; i < 8; i++) a[i] = As[kk][tr + i];
#pragma unroll
            for (int j = 0; j < 8; j++) bf[j] = Bs[kk][tc + j];
#pragma unroll
            for (int i = 0; i < 8; i++)
#pragma unroll
                for (int j = 0; j < 8; j++)
                    acc[i][j] = fmaf(a[i], bf[j], acc[i][j]);
        }
        __syncthreads();
    }

#pragma unroll
    for (int i = 0; i < 8; i++) {
        const int m = m0 + tr + i;
#pragma unroll
        for (int j = 0; j < 8; j++) {
            const int n = n0 + tc + j;
            if (n < N) {
                float vv = acc[i][j] * alpha;
                if (bias) vv += bias[n];
                if (MASK) { if (n > m) vv += -10000.0f; }
                if (RELU) vv = fmaxf(vv, 0.0f);
                long long ci = (long long)m * ldc + n;
                if (resid) vv += resid[ci];
                C[ci] = vv;
            }
        }
    }
}

// ---------------------------------------------------------------------------
// Host launcher: 43 kernel launches on the legacy default stream. No sync,
// no allocation — graph-capturable.
// ---------------------------------------------------------------------------
extern "C" void kernel_launch(void* const* d_in, const int* in_sizes, int n_in,
                              void* d_out, int out_size) {
    const unsigned int* idw = (const unsigned int*)d_in[0];
    const float* emb  = (const float*)d_in[1];
    const float* Wq   = (const float*)d_in[2];
    const float* Wk   = (const float*)d_in[3];
    const float* Wv   = (const float*)d_in[4];
    const float* Wo   = (const float*)d_in[5];
    const float* pbq  = (const float*)d_in[6];
    const float* pbk  = (const float*)d_in[7];
    const float* pbv  = (const float*)d_in[8];
    const float* pbo  = (const float*)d_in[9];
    const float* W1   = (const float*)d_in[10];
    const float* pb1  = (const float*)d_in[11];
    const float* W2   = (const float*)d_in[12];
    const float* pb2  = (const float*)d_in[13];
    const float* ln1g = (const float*)d_in[14];
    const float* ln1b = (const float*)d_in[15];
    const float* ln2g = (const float*)d_in[16];
    const float* ln2b = (const float*)d_in[17];
    const float* lnfg = (const float*)d_in[18];
    const float* lnfb = (const float*)d_in[19];

    float *px, *pn, *pq, *pk, *pv, *ps, *ph;
    cudaGetSymbolAddress((void**)&px, g_x);
    cudaGetSymbolAddress((void**)&pn, g_n);
    cudaGetSymbolAddress((void**)&pq, g_q);
    cudaGetSymbolAddress((void**)&pk, g_k);
    cudaGetSymbolAddress((void**)&pv, g_v);
    cudaGetSymbolAddress((void**)&ps, g_scores);
    cudaGetSymbolAddress((void**)&ph, g_h1);

    const long long sSD = (long long)SS * DD;       // 1310720
    const long long sHSS = (long long)HH * SS * SS; // 16777216
    const long long sSSq = (long long)SS * SS;      // 1048576

    detect_kernel<<<1, 256>>>(idw);
    embed_kernel<<<(MM * DD + 255) / 256, 256>>>(idw, emb, px);

    const dim3 gProj(DD / 128, MM / 128, 1);   // (10, 16, 1)
    const dim3 gFF1(DFF / 128, MM / 128, 1);   // (64, 16, 1)
    const dim3 gScore(SS / 128, SS / 128, BB * HH);  // (8, 8, 32)
    const dim3 gCtx(1, SS / 128, BB * HH);           // (1, 8, 32)

    for (int l = 0; l < LL; l++) {
        const float* wq = Wq + (size_t)l * DD * DD;
        const float* wk = Wk + (size_t)l * DD * DD;
        const float* wv = Wv + (size_t)l * DD * DD;
        const float* wo = Wo + (size_t)l * DD * DD;
        const float* w1 = W1 + (size_t)l * DD * DFF;
        const float* w2 = W2 + (size_t)l * DFF * DD;

        // ---- attention block ----
        layernorm_kernel<<<MM, 256>>>(px, pn, ln1g + l * DD, ln1b + l * DD);

        gemm_kernel<false, false, false><<<gProj, 256>>>(
            pn, wq, pq, pbq + l * DD, nullptr,
            MM, DD, DD, DD, DD, DD, 0, 0, 0, 0, 0, 0, 1.0f);
        gemm_kernel<false, false, false><<<gProj, 256>>>(
            pn, wk, pk, pbk + l * DD, nullptr,
            MM, DD, DD, DD, DD, DD, 0, 0, 0, 0, 0, 0, 1.0f);
        gemm_kernel<false, false, false><<<gProj, 256>>>(
            pn, wv, pv, pbv + l * DD, nullptr,
            MM, DD, DD, DD, DD, DD, 0, 0, 0, 0, 0, 0, 1.0f);

        // scores[z] = q[z] @ k[z]^T * 1/sqrt(80) + causal mask
        gemm_kernel<true, false, true><<<gScore, 256>>>(
            pq, pk, ps, nullptr, nullptr,
            SS, SS, DHH, DD, DD, SS,
            sSD, (long long)DHH, sSD, (long long)DHH, sHSS, sSSq,
            0.11180339887498949f);

        softmax_kernel<<<BB * HH * SS, 256>>>(ps);

        // ctx[z] = attn[z] @ v[z]  -> written into g_n at [B,S,D] layout
        gemm_kernel<false, false, false><<<gCtx, 256>>>(
            ps, pv, pn, nullptr, nullptr,
            SS, DHH, SS, SS, DD, DD,
            sHSS, sSSq, sSD, (long long)DHH, sSD, (long long)DHH, 1.0f);

        // x = x + ctx @ Wo + bo
        gemm_kernel<false, false, false><<<gProj, 256>>>(
            pn, wo, px, pbo + l * DD, px,
            MM, DD, DD, DD, DD, DD, 0, 0, 0, 0, 0, 0, 1.0f);

        // ---- FFN block ----
        layernorm_kernel<<<MM, 256>>>(px, pq, ln2g + l * DD, ln2b + l * DD);

        gemm_kernel<false, true, false><<<gFF1, 256>>>(
            pq, w1, ph, pb1 + l * DFF, nullptr,
            MM, DFF, DD, DD, DFF, DFF, 0, 0, 0, 0, 0, 0, 1.0f);

        gemm_kernel<false, false, false><<<gProj, 256>>>(
            ph, w2, px, pb2 + l * DD, px,
            MM, DD, DFF, DFF, DD, DD, 0, 0, 0, 0, 0, 0, 1.0f);
    }

    layernorm_kernel<<<MM, 256>>>(px, (float*)d_out, lnfg, lnfb);
}

// round 3
// speedup vs baseline: 1.8098x; 1.8098x over previous
#include <cuda_runtime.h>
#include <cuda_bf16.h>
#include <cstdint>

// ---------------------------------------------------------------------------
// CTRL transformer forward on GB300 (compiled at compute_103 -> no tcgen05).
// Round 3: all GEMMs on mma.sync bf16 (m16n8k16) with 3xBF16 split
// (hi*hi + hi*lo + lo*hi, fp32 accumulate). 128x128 CTA tile, 8 warps
// (4m x 2n), K-chunk 32, double-buffered smem, reg-staged global prefetch.
// ---------------------------------------------------------------------------

#define BB   2
#define SS   1024
#define DD   1280
#define HH   16
#define DHH  80
#define DFF  8192
#define LL   4
#define MM   (BB * SS)

__device__ float g_x[MM * DD];
__device__ float g_n[MM * DD];
__device__ float g_q[MM * DD];
__device__ float g_k[MM * DD];
__device__ float g_v[MM * DD];
__device__ float g_scores[(size_t)BB * HH * SS * SS];
__device__ float g_h1[(size_t)MM * DFF];
__device__ int   g_ids64;

// ---------------------------------------------------------------------------
__device__ __forceinline__ uint32_t smem_u32(const void* p) {
    uint32_t a;
    asm("{ .reg .u64 t; cvta.to.shared.u64 t, %1; cvt.u32.u64 %0, t; }"
        : "=r"(a) : "l"(p));
    return a;
}

__device__ __forceinline__ void ldsm_x4(uint32_t& r0, uint32_t& r1,
                                        uint32_t& r2, uint32_t& r3,
                                        uint32_t addr) {
    asm volatile("ldmatrix.sync.aligned.m8n8.x4.shared.b16 {%0,%1,%2,%3}, [%4];"
                 : "=r"(r0), "=r"(r1), "=r"(r2), "=r"(r3) : "r"(addr));
}

__device__ __forceinline__ void mma_bf16(float* d, const uint32_t* a,
                                         uint32_t b0, uint32_t b1) {
    asm volatile(
        "mma.sync.aligned.m16n8k16.row.col.f32.bf16.bf16.f32 "
        "{%0,%1,%2,%3},{%4,%5,%6,%7},{%8,%9},{%0,%1,%2,%3};"
        : "+f"(d[0]), "+f"(d[1]), "+f"(d[2]), "+f"(d[3])
        : "r"(a[0]), "r"(a[1]), "r"(a[2]), "r"(a[3]), "r"(b0), "r"(b1));
}

__device__ __forceinline__ uint32_t pk(__nv_bfloat16 a, __nv_bfloat16 b) {
    return (uint32_t)__bfloat16_as_ushort(a) | ((uint32_t)__bfloat16_as_ushort(b) << 16);
}

// split 8 fp32 -> hi/lo bf16 packed uint4
__device__ __forceinline__ void split8(const float* f, uint4& hi, uint4& lo) {
    __nv_bfloat16 h[8], l[8];
#pragma unroll
    for (int i = 0; i < 8; i++) {
        h[i] = __float2bfloat16(f[i]);
        l[i] = __float2bfloat16(f[i] - __bfloat162float(h[i]));
    }
    hi = make_uint4(pk(h[0],h[1]), pk(h[2],h[3]), pk(h[4],h[5]), pk(h[6],h[7]));
    lo = make_uint4(pk(l[0],l[1]), pk(l[2],l[3]), pk(l[4],l[5]), pk(l[6],l[7]));
}

// ---------------------------------------------------------------------------
// id-width detect + embedding
// ---------------------------------------------------------------------------
__global__ void detect_kernel(const unsigned int* __restrict__ w) {
    __shared__ int any;
    if (threadIdx.x == 0) any = 0;
    __syncthreads();
    int loc = 0;
    for (int i = 2 * threadIdx.x + 1; i < 2048; i += 512)
        loc |= (w[i] != 0u);
    if (loc) atomicOr(&any, 1);
    __syncthreads();
    if (threadIdx.x == 0) g_ids64 = any ? 0 : 1;
}

__global__ void embed_kernel(const unsigned int* __restrict__ idw,
                             const float* __restrict__ emb,
                             float* __restrict__ x) {
    int idx = blockIdx.x * 256 + threadIdx.x;
    if (idx >= MM * DD) return;
    int d   = idx % DD;
    int row = idx / DD;
    int s   = row & (SS - 1);
    int id  = g_ids64 ? (int)idw[2 * row] : (int)idw[row];
    float val = emb[(long long)id * DD + d] * 35.77708763999664f;  // sqrt(1280)
    int m = (d < 640) ? d : d - 640;
    float rate = expf(-0.014391156831212787f * (float)m);
    float ang  = (float)s * rate;
    val += (d < 640) ? sinf(ang) : cosf(ang);
    x[idx] = val;
}

// ---------------------------------------------------------------------------
// LayerNorm / softmax
// ---------------------------------------------------------------------------
__device__ __forceinline__ float warp_sum(float v) {
#pragma unroll
    for (int o = 16; o; o >>= 1) v += __shfl_xor_sync(0xffffffffu, v, o);
    return v;
}

__global__ void layernorm_kernel(const float* __restrict__ x,
                                 float* __restrict__ o,
                                 const float* __restrict__ g,
                                 const float* __restrict__ b) {
    const int row = blockIdx.x;
    const int t   = threadIdx.x;
    const float* xr = x + (long long)row * DD;
    __shared__ float red[8];
    float v[5];
    float s = 0.0f;
#pragma unroll
    for (int i = 0; i < 5; i++) { v[i] = xr[t + 256 * i]; s += v[i]; }
    s = warp_sum(s);
    if ((t & 31) == 0) red[t >> 5] = s;
    __syncthreads();
    float mu = (red[0] + red[1] + red[2] + red[3] +
                red[4] + red[5] + red[6] + red[7]) * (1.0f / 1280.0f);
    __syncthreads();
    float q = 0.0f;
#pragma unroll
    for (int i = 0; i < 5; i++) { float dv = v[i] - mu; q += dv * dv; }
    q = warp_sum(q);
    if ((t & 31) == 0) red[t >> 5] = q;
    __syncthreads();
    float var = (red[0] + red[1] + red[2] + red[3] +
                 red[4] + red[5] + red[6] + red[7]) * (1.0f / 1280.0f);
    float rstd = rsqrtf(var + 1e-6f);
    float* orow = o + (long long)row * DD;
#pragma unroll
    for (int i = 0; i < 5; i++) {
        int c = t + 256 * i;
        orow[c] = (v[i] - mu) * rstd * g[c] + b[c];
    }
}

__global__ void softmax_kernel(float* __restrict__ sc) {
    const long long row = blockIdx.x;
    float* p = sc + row * (long long)SS;
    const int t = threadIdx.x;
    __shared__ float red[8];
    float v[4];
    float mx = -3.4e38f;
#pragma unroll
    for (int i = 0; i < 4; i++) { v[i] = p[t + 256 * i]; mx = fmaxf(mx, v[i]); }
#pragma unroll
    for (int o = 16; o; o >>= 1) mx = fmaxf(mx, __shfl_xor_sync(0xffffffffu, mx, o));
    if ((t & 31) == 0) red[t >> 5] = mx;
    __syncthreads();
    mx = fmaxf(fmaxf(fmaxf(red[0], red[1]), fmaxf(red[2], red[3])),
               fmaxf(fmaxf(red[4], red[5]), fmaxf(red[6], red[7])));
    __syncthreads();
    float s = 0.0f;
#pragma unroll
    for (int i = 0; i < 4; i++) { v[i] = expf(v[i] - mx); s += v[i]; }
    s = warp_sum(s);
    if ((t & 31) == 0) red[t >> 5] = s;
    __syncthreads();
    s = red[0] + red[1] + red[2] + red[3] + red[4] + red[5] + red[6] + red[7];
    float inv = 1.0f / s;
#pragma unroll
    for (int i = 0; i < 4; i++) p[t + 256 * i] = v[i] * inv;
}

// ---------------------------------------------------------------------------
// mma.sync 3xBF16 GEMM: C = alpha * A @ op(B) [+bias][+mask][relu][+resid]
//   A [M,K] row-major (lda). BTRANS=0: B [N,K] k-contig. BTRANS=1: B [K,N].
//   Batched via blockIdx.z -> (z>>4, z&15). M % 128 == 0, K % 16 == 0.
// smem tile rows: stride 40 bf16 (80 B) => ldmatrix row-starts hit all 32
// banks exactly once (conflict-free).
// ---------------------------------------------------------------------------
#define RSTR   40                 // bf16 elements per smem row
#define T_A_HI 0
#define T_A_LO 10240
#define T_B_HI 20480
#define T_B_LO 30720
#define STAGE  40960
#define SMEM_SZ (2 * STAGE)

template <bool BTRANS, bool MASK, bool RELU>
__global__ void __launch_bounds__(256)
mma_gemm(const float* __restrict__ A, const float* __restrict__ B,
         float* __restrict__ C,
         const float* __restrict__ bias, const float* __restrict__ resid,
         int M, int N, int K, int lda, int ldb, int ldc,
         long long sA1, long long sA2, long long sB1, long long sB2,
         long long sC1, long long sC2, float alpha) {
    extern __shared__ char sm[];
    const uint32_t smb = smem_u32(sm);

    const int tid  = threadIdx.x;
    const int wid  = tid >> 5;
    const int lane = tid & 31;
    const int wm   = wid >> 1;           // 0..3 (32 rows each)
    const int wn   = wid & 1;            // 0..1 (64 cols each)

    const int z = blockIdx.z, zb = z >> 4, zh = z & 15;
    A += zb * sA1 + zh * sA2;
    B += zb * sB1 + zh * sB2;
    const long long coff = zb * sC1 + zh * sC2;
    C += coff;
    if (resid) resid += coff;

    const int m0 = blockIdx.y * 128;
    const int n0 = blockIdx.x * 128;

    // fill-thread mapping
    const int arow = tid >> 1;
    const int acol = (tid & 1) << 4;     // 0 or 16
    // BTRANS fill mapping
    const int bn   = tid & 127;
    const int bkh  = tid >> 7;           // 0 or 1

    const int nst = (K + 31) >> 5;

    float fa[16], fb[16];

    // ---- global load for stage s into fa/fb ----
    auto gload = [&](int s) {
        const int kbase = s << 5;
        // A: row m0+arow, cols kbase+acol .. +15
        if (kbase + acol < K) {
            const float* p = A + (long long)(m0 + arow) * lda + kbase + acol;
#pragma unroll
            for (int i = 0; i < 4; i++)
                *(float4*)(fa + 4 * i) = *(const float4*)(p + 4 * i);
        } else {
#pragma unroll
            for (int i = 0; i < 16; i++) fa[i] = 0.0f;
        }
        if (!BTRANS) {
            if (kbase + acol < K) {
                const float* p = B + (long long)(n0 + arow) * ldb + kbase + acol;
#pragma unroll
                for (int i = 0; i < 4; i++)
                    *(float4*)(fb + 4 * i) = *(const float4*)(p + 4 * i);
            } else {
#pragma unroll
                for (int i = 0; i < 16; i++) fb[i] = 0.0f;
            }
        } else {
            const int k0 = kbase + (bkh << 4);
            const int gn = n0 + bn;
            if (k0 < K && gn < N) {
                const float* p = B + (long long)k0 * ldb + gn;
#pragma unroll
                for (int i = 0; i < 16; i++) { fb[i] = *p; p += ldb; }
            } else {
#pragma unroll
                for (int i = 0; i < 16; i++) fb[i] = 0.0f;
            }
        }
    };

    // ---- convert + store fa/fb into smem buffer (s&1) ----
    auto sts = [&](int s) {
        const uint32_t sb = smb + (uint32_t)((s & 1) * STAGE);
        uint4 h0, l0, h1, l1;
        split8(fa, h0, l0);
        split8(fa + 8, h1, l1);
        {
            uint32_t a = sb + (uint32_t)(arow * (RSTR * 2) + acol * 2);
            *(uint4*)(uintptr_t)0; // (no-op placeholder removed by compiler)
            *reinterpret_cast<uint4*>(sm + (a - smb) + T_A_HI) = h0;
            *reinterpret_cast<uint4*>(sm + (a - smb) + T_A_HI + 16) = h1;
            *reinterpret_cast<uint4*>(sm + (a - smb) + T_A_LO) = l0;
            *reinterpret_cast<uint4*>(sm + (a - smb) + T_A_LO + 16) = l1;
        }
        split8(fb, h0, l0);
        split8(fb + 8, h1, l1);
        if (!BTRANS) {
            uint32_t a = (uint32_t)((s & 1) * STAGE + arow * (RSTR * 2) + acol * 2);
            *reinterpret_cast<uint4*>(sm + a + T_B_HI) = h0;
            *reinterpret_cast<uint4*>(sm + a + T_B_HI + 16) = h1;
            *reinterpret_cast<uint4*>(sm + a + T_B_LO) = l0;
            *reinterpret_cast<uint4*>(sm + a + T_B_LO + 16) = l1;
        } else {
            uint32_t a = (uint32_t)((s & 1) * STAGE + bn * (RSTR * 2) + (bkh << 5));
            *reinterpret_cast<uint4*>(sm + a + T_B_HI) = h0;
            *reinterpret_cast<uint4*>(sm + a + T_B_HI + 16) = h1;
            *reinterpret_cast<uint4*>(sm + a + T_B_LO) = l0;
            *reinterpret_cast<uint4*>(sm + a + T_B_LO + 16) = l1;
        }
    };

    float acc[2][8][4] = {};

    gload(0);
    sts(0);
    __syncthreads();

    // ldmatrix lane addressing
    const int lrow = lane & 15;
    const int lcol = (lane >> 4) << 3;

    for (int s = 0; s < nst; s++) {
        if (s + 1 < nst) gload(s + 1);

        const uint32_t sb = smb + (uint32_t)((s & 1) * STAGE);
#pragma unroll
        for (int ks = 0; ks < 2; ks++) {
            const int kk = ks << 4;
            uint32_t ahi[2][4], alo[2][4];
#pragma unroll
            for (int mf = 0; mf < 2; mf++) {
                uint32_t ra = sb + (uint32_t)((wm * 32 + mf * 16 + lrow) * (RSTR * 2)
                                              + (kk + lcol) * 2);
                ldsm_x4(ahi[mf][0], ahi[mf][1], ahi[mf][2], ahi[mf][3], ra + T_A_HI);
                ldsm_x4(alo[mf][0], alo[mf][1], alo[mf][2], alo[mf][3], ra + T_A_LO);
            }
#pragma unroll
            for (int nfp = 0; nfp < 4; nfp++) {
                uint32_t rb = sb + (uint32_t)((wn * 64 + nfp * 16 + lrow) * (RSTR * 2)
                                              + (kk + lcol) * 2);
                uint32_t bh[4], bl[4];
                ldsm_x4(bh[0], bh[1], bh[2], bh[3], rb + T_B_HI);
                ldsm_x4(bl[0], bl[1], bl[2], bl[3], rb + T_B_LO);
#pragma unroll
                for (int mf = 0; mf < 2; mf++) {
                    float* d0 = acc[mf][2 * nfp];
                    float* d1 = acc[mf][2 * nfp + 1];
                    mma_bf16(d0, ahi[mf], bh[0], bh[2]);
                    mma_bf16(d0, ahi[mf], bl[0], bl[2]);
                    mma_bf16(d0, alo[mf], bh[0], bh[2]);
                    mma_bf16(d1, ahi[mf], bh[1], bh[3]);
                    mma_bf16(d1, ahi[mf], bl[1], bl[3]);
                    mma_bf16(d1, alo[mf], bh[1], bh[3]);
                }
            }
        }

        if (s + 1 < nst) {
            sts(s + 1);
            __syncthreads();
        }
    }

    // ---- epilogue ----
    const int g = lane >> 2;
    const int t = lane & 3;
#pragma unroll
    for (int mf = 0; mf < 2; mf++) {
        const int gm0 = m0 + wm * 32 + mf * 16 + g;
        const int gm1 = gm0 + 8;
        const long long ro0 = (long long)gm0 * ldc;
        const long long ro1 = (long long)gm1 * ldc;
#pragma unroll
        for (int nf = 0; nf < 8; nf++) {
            const int gn = n0 + wn * 64 + nf * 8 + t * 2;
            if (gn < N) {
                float c0 = acc[mf][nf][0] * alpha;
                float c1 = acc[mf][nf][1] * alpha;
                float c2 = acc[mf][nf][2] * alpha;
                float c3 = acc[mf][nf][3] * alpha;
                if (bias) {
                    float b0 = bias[gn], b1 = bias[gn + 1];
                    c0 += b0; c1 += b1; c2 += b0; c3 += b1;
                }
                if (MASK) {
                    if (gn > gm0)     c0 += -10000.0f;
                    if (gn + 1 > gm0) c1 += -10000.0f;
                    if (gn > gm1)     c2 += -10000.0f;
                    if (gn + 1 > gm1) c3 += -10000.0f;
                }
                if (RELU) {
                    c0 = fmaxf(c0, 0.0f); c1 = fmaxf(c1, 0.0f);
                    c2 = fmaxf(c2, 0.0f); c3 = fmaxf(c3, 0.0f);
                }
                if (resid) {
                    c0 += resid[ro0 + gn]; c1 += resid[ro0 + gn + 1];
                    c2 += resid[ro1 + gn]; c3 += resid[ro1 + gn + 1];
                }
                *(float2*)(C + ro0 + gn) = make_float2(c0, c1);
                *(float2*)(C + ro1 + gn) = make_float2(c2, c3);
            }
        }
    }
}

// ---------------------------------------------------------------------------
// Host launcher (graph-capturable)
// ---------------------------------------------------------------------------
extern "C" void kernel_launch(void* const* d_in, const int* in_sizes, int n_in,
                              void* d_out, int out_size) {
    const unsigned int* idw = (const unsigned int*)d_in[0];
    const float* emb  = (const float*)d_in[1];
    const float* Wq   = (const float*)d_in[2];
    const float* Wk   = (const float*)d_in[3];
    const float* Wv   = (const float*)d_in[4];
    const float* Wo   = (const float*)d_in[5];
    const float* pbq  = (const float*)d_in[6];
    const float* pbk  = (const float*)d_in[7];
    const float* pbv  = (const float*)d_in[8];
    const float* pbo  = (const float*)d_in[9];
    const float* W1   = (const float*)d_in[10];
    const float* pb1  = (const float*)d_in[11];
    const float* W2   = (const float*)d_in[12];
    const float* pb2  = (const float*)d_in[13];
    const float* ln1g = (const float*)d_in[14];
    const float* ln1b = (const float*)d_in[15];
    const float* ln2g = (const float*)d_in[16];
    const float* ln2b = (const float*)d_in[17];
    const float* lnfg = (const float*)d_in[18];
    const float* lnfb = (const float*)d_in[19];

    float *px, *pn, *pq, *pk, *pv, *ps, *ph;
    cudaGetSymbolAddress((void**)&px, g_x);
    cudaGetSymbolAddress((void**)&pn, g_n);
    cudaGetSymbolAddress((void**)&pq, g_q);
    cudaGetSymbolAddress((void**)&pk, g_k);
    cudaGetSymbolAddress((void**)&pv, g_v);
    cudaGetSymbolAddress((void**)&ps, g_scores);
    cudaGetSymbolAddress((void**)&ph, g_h1);

    cudaFuncSetAttribute(mma_gemm<true,  false, false>,
                         cudaFuncAttributeMaxDynamicSharedMemorySize, SMEM_SZ);
    cudaFuncSetAttribute(mma_gemm<false, true,  false>,
                         cudaFuncAttributeMaxDynamicSharedMemorySize, SMEM_SZ);
    cudaFuncSetAttribute(mma_gemm<true,  false, true>,
                         cudaFuncAttributeMaxDynamicSharedMemorySize, SMEM_SZ);

    const long long sSD  = (long long)SS * DD;
    const long long sHSS = (long long)HH * SS * SS;
    const long long sSSq = (long long)SS * SS;

    detect_kernel<<<1, 256>>>(idw);
    embed_kernel<<<(MM * DD + 255) / 256, 256>>>(idw, emb, px);

    const dim3 gProj(DD / 128, MM / 128, 1);         // (10, 16)
    const dim3 gFF1(DFF / 128, MM / 128, 1);         // (64, 16)
    const dim3 gScore(SS / 128, SS / 128, BB * HH);  // (8, 8, 32)
    const dim3 gCtx(1, SS / 128, BB * HH);           // (1, 8, 32)

    for (int l = 0; l < LL; l++) {
        const float* wq = Wq + (size_t)l * DD * DD;
        const float* wk = Wk + (size_t)l * DD * DD;
        const float* wv = Wv + (size_t)l * DD * DD;
        const float* wo = Wo + (size_t)l * DD * DD;
        const float* w1 = W1 + (size_t)l * DD * DFF;
        const float* w2 = W2 + (size_t)l * DFF * DD;

        layernorm_kernel<<<MM, 256>>>(px, pn, ln1g + l * DD, ln1b + l * DD);

        mma_gemm<true, false, false><<<gProj, 256, SMEM_SZ>>>(
            pn, wq, pq, pbq + l * DD, nullptr,
            MM, DD, DD, DD, DD, DD, 0, 0, 0, 0, 0, 0, 1.0f);
        mma_gemm<true, false, false><<<gProj, 256, SMEM_SZ>>>(
            pn, wk, pk, pbk + l * DD, nullptr,
            MM, DD, DD, DD, DD, DD, 0, 0, 0, 0, 0, 0, 1.0f);
        mma_gemm<true, false, false><<<gProj, 256, SMEM_SZ>>>(
            pn, wv, pv, pbv + l * DD, nullptr,
            MM, DD, DD, DD, DD, DD, 0, 0, 0, 0, 0, 0, 1.0f);

        // scores = q @ k^T * 1/sqrt(80) + causal mask   (B=[N,K] k-contig)
        mma_gemm<false, true, false><<<gScore, 256, SMEM_SZ>>>(
            pq, pk, ps, nullptr, nullptr,
            SS, SS, DHH, DD, DD, SS,
            sSD, (long long)DHH, sSD, (long long)DHH, sHSS, sSSq,
            0.11180339887498949f);

        softmax_kernel<<<BB * HH * SS, 256>>>(ps);

        // ctx = attn @ v   (B=[K=S, N=80] n-contig => BTRANS)
        mma_gemm<true, false, false><<<gCtx, 256, SMEM_SZ>>>(
            ps, pv, pn, nullptr, nullptr,
            SS, DHH, SS, SS, DD, DD,
            sHSS, sSSq, sSD, (long long)DHH, sSD, (long long)DHH, 1.0f);

        // x = x + ctx @ Wo + bo
        mma_gemm<true, false, false><<<gProj, 256, SMEM_SZ>>>(
            pn, wo, px, pbo + l * DD, px,
            MM, DD, DD, DD, DD, DD, 0, 0, 0, 0, 0, 0, 1.0f);

        layernorm_kernel<<<MM, 256>>>(px, pq, ln2g + l * DD, ln2b + l * DD);

        mma_gemm<true, false, true><<<gFF1, 256, SMEM_SZ>>>(
            pq, w1, ph, pb1 + l * DFF, nullptr,
            MM, DFF, DD, DD, DFF, DFF, 0, 0, 0, 0, 0, 0, 1.0f);

        mma_gemm<true, false, false><<<gProj, 256, SMEM_SZ>>>(
            ph, w2, px, pb2 + l * DD, px,
            MM, DD, DFF, DFF, DD, DD, 0, 0, 0, 0, 0, 0, 1.0f);
    }

    layernorm_kernel<<<MM, 256>>>(px, (float*)d_out, lnfg, lnfb);
}

// round 4
// speedup vs baseline: 2.1459x; 1.1857x over previous
#include <cuda_runtime.h>
#include <cuda_bf16.h>
#include <cstdint>

// ---------------------------------------------------------------------------
// CTRL transformer forward, GB300 (compute_103 -> mma.sync path).
// Round 4: operands pre-split to bf16 hi/lo in gmem (weights transposed once
// per launch; activation producers emit hi/lo pairs). GEMM hot loop is pure
// cp.async fill + ldmatrix + 3x mma.sync (hi*hi + hi*lo + lo*hi), 2-stage
// pipeline, 2 CTAs/SM.
// ---------------------------------------------------------------------------

#define BB   2
#define SS   1024
#define DD   1280
#define HH   16
#define DHH  80
#define DFF  8192
#define LL   4
#define MM   (BB * SS)

typedef __nv_bfloat16 bf16;

// residual / fp32 scratch
__device__ float g_x[MM * DD];
__device__ float g_scores[(size_t)BB * HH * SS * SS];      // 128 MB
// activation hi/lo pairs
__device__ bf16 g_nh[MM * DD],  g_nl[MM * DD];
__device__ bf16 g_qh[MM * DD],  g_ql[MM * DD];
__device__ bf16 g_kh[MM * DD],  g_kl[MM * DD];
__device__ bf16 g_vh[MM * DD],  g_vl[MM * DD];
__device__ bf16 g_vth[DD * MM], g_vtl[DD * MM];            // v transposed
__device__ bf16 g_ch[MM * DD],  g_cl[MM * DD];             // ctx
__device__ bf16 g_ph[(size_t)BB * HH * SS * SS];           // probs hi (64 MB)
__device__ bf16 g_pl[(size_t)BB * HH * SS * SS];
__device__ bf16 g_h1h[(size_t)MM * DFF], g_h1l[(size_t)MM * DFF];
// weights, converted + transposed to [N,K] per layer
__device__ bf16 g_wqh[LL * DD * DD], g_wql[LL * DD * DD];
__device__ bf16 g_wkh[LL * DD * DD], g_wkl[LL * DD * DD];
__device__ bf16 g_wvh[LL * DD * DD], g_wvl[LL * DD * DD];
__device__ bf16 g_woh[LL * DD * DD], g_wol[LL * DD * DD];
__device__ bf16 g_w1h[(size_t)LL * DD * DFF], g_w1l[(size_t)LL * DD * DFF];
__device__ bf16 g_w2h[(size_t)LL * DFF * DD], g_w2l[(size_t)LL * DFF * DD];
__device__ int  g_ids64;

// ---------------------------------------------------------------------------
__device__ __forceinline__ uint32_t smem_u32(const void* p) {
    uint32_t a;
    asm("{ .reg .u64 t; cvta.to.shared.u64 t, %1; cvt.u32.u64 %0, t; }"
        : "=r"(a) : "l"(p));
    return a;
}

__device__ __forceinline__ void ldsm_x4(uint32_t& r0, uint32_t& r1,
                                        uint32_t& r2, uint32_t& r3,
                                        uint32_t addr) {
    asm volatile("ldmatrix.sync.aligned.m8n8.x4.shared.b16 {%0,%1,%2,%3}, [%4];"
                 : "=r"(r0), "=r"(r1), "=r"(r2), "=r"(r3) : "r"(addr));
}

__device__ __forceinline__ void mma_bf16(float* d, const uint32_t* a,
                                         uint32_t b0, uint32_t b1) {
    asm volatile(
        "mma.sync.aligned.m16n8k16.row.col.f32.bf16.bf16.f32 "
        "{%0,%1,%2,%3},{%4,%5,%6,%7},{%8,%9},{%0,%1,%2,%3};"
        : "+f"(d[0]), "+f"(d[1]), "+f"(d[2]), "+f"(d[3])
        : "r"(a[0]), "r"(a[1]), "r"(a[2]), "r"(a[3]), "r"(b0), "r"(b1));
}

__device__ __forceinline__ void cp16(uint32_t dst, const void* src, int sz) {
    asm volatile("cp.async.ca.shared.global [%0], [%1], 16, %2;"
                 :: "r"(dst), "l"(src), "r"(sz) : "memory");
}
#define CP_COMMIT() asm volatile("cp.async.commit_group;" ::: "memory")
#define CP_WAIT0()  asm volatile("cp.async.wait_group 0;" ::: "memory")

__device__ __forceinline__ uint32_t pk2f(float a, float b) {
    __nv_bfloat16 ha = __float2bfloat16(a), hb = __float2bfloat16(b);
    return (uint32_t)__bfloat16_as_ushort(ha) |
           ((uint32_t)__bfloat16_as_ushort(hb) << 16);
}

// ---------------------------------------------------------------------------
// detect + embed
// ---------------------------------------------------------------------------
__global__ void detect_kernel(const unsigned int* __restrict__ w) {
    __shared__ int any;
    if (threadIdx.x == 0) any = 0;
    __syncthreads();
    int loc = 0;
    for (int i = 2 * threadIdx.x + 1; i < 2048; i += 512)
        loc |= (w[i] != 0u);
    if (loc) atomicOr(&any, 1);
    __syncthreads();
    if (threadIdx.x == 0) g_ids64 = any ? 0 : 1;
}

__global__ void embed_kernel(const unsigned int* __restrict__ idw,
                             const float* __restrict__ emb,
                             float* __restrict__ x) {
    int idx = blockIdx.x * 256 + threadIdx.x;
    if (idx >= MM * DD) return;
    int d   = idx % DD;
    int row = idx / DD;
    int s   = row & (SS - 1);
    int id  = g_ids64 ? (int)idw[2 * row] : (int)idw[row];
    float val = emb[(long long)id * DD + d] * 35.77708763999664f;
    int m = (d < 640) ? d : d - 640;
    float rate = expf(-0.014391156831212787f * (float)m);
    float ang  = (float)s * rate;
    val += (d < 640) ? sinf(ang) : cosf(ang);
    x[idx] = val;
}

// ---------------------------------------------------------------------------
// weight convert+transpose: fp32 [K,N] -> bf16 hi/lo [N,K], z = layer
// ---------------------------------------------------------------------------
__global__ void wtrans_kernel(const float* __restrict__ W,
                              bf16* __restrict__ oh, bf16* __restrict__ ol,
                              int K, int N) {
    size_t off = (size_t)blockIdx.z * K * N;
    W += off; oh += off; ol += off;
    __shared__ float tf[32][33];
    const int n0 = blockIdx.x * 32, k0 = blockIdx.y * 32;
    const int tx = threadIdx.x, ty = threadIdx.y;
#pragma unroll
    for (int i = 0; i < 4; i++)
        tf[ty + 8 * i][tx] = W[(long long)(k0 + ty + 8 * i) * N + n0 + tx];
    __syncthreads();
#pragma unroll
    for (int i = 0; i < 4; i++) {
        float v = tf[tx][ty + 8 * i];
        bf16 h = __float2bfloat16(v);
        bf16 l = __float2bfloat16(v - __bfloat162float(h));
        long long o = (long long)(n0 + ty + 8 * i) * K + k0 + tx;
        oh[o] = h; ol[o] = l;
    }
}

// v transpose: bf16 hi/lo [MM,DD] -> [DD,MM]
__global__ void vtrans_kernel(const bf16* __restrict__ ih, const bf16* __restrict__ il,
                              bf16* __restrict__ oh, bf16* __restrict__ ol) {
    __shared__ bf16 th[32][34], tl[32][34];
    const int n0 = blockIdx.x * 32, m0 = blockIdx.y * 32;
    const int tx = threadIdx.x, ty = threadIdx.y;
#pragma unroll
    for (int i = 0; i < 4; i++) {
        long long src = (long long)(m0 + ty + 8 * i) * DD + n0 + tx;
        th[ty + 8 * i][tx] = ih[src];
        tl[ty + 8 * i][tx] = il[src];
    }
    __syncthreads();
#pragma unroll
    for (int i = 0; i < 4; i++) {
        long long dst = (long long)(n0 + ty + 8 * i) * MM + m0 + tx;
        oh[dst] = th[tx][ty + 8 * i];
        ol[dst] = tl[tx][ty + 8 * i];
    }
}

// ---------------------------------------------------------------------------
// LayerNorm: fp32 out  /  bf16-pair out
// ---------------------------------------------------------------------------
__device__ __forceinline__ float warp_sum(float v) {
#pragma unroll
    for (int o = 16; o; o >>= 1) v += __shfl_xor_sync(0xffffffffu, v, o);
    return v;
}

template <bool PAIR>
__global__ void layernorm_kernel(const float* __restrict__ x,
                                 float* __restrict__ o,
                                 bf16* __restrict__ oh, bf16* __restrict__ ol,
                                 const float* __restrict__ g,
                                 const float* __restrict__ b) {
    const int row = blockIdx.x;
    const int t   = threadIdx.x;
    const float* xr = x + (long long)row * DD;
    __shared__ float red[8];
    float v[5];
    float s = 0.0f;
#pragma unroll
    for (int i = 0; i < 5; i++) { v[i] = xr[t + 256 * i]; s += v[i]; }
    s = warp_sum(s);
    if ((t & 31) == 0) red[t >> 5] = s;
    __syncthreads();
    float mu = (red[0] + red[1] + red[2] + red[3] +
                red[4] + red[5] + red[6] + red[7]) * (1.0f / 1280.0f);
    __syncthreads();
    float q = 0.0f;
#pragma unroll
    for (int i = 0; i < 5; i++) { float dv = v[i] - mu; q += dv * dv; }
    q = warp_sum(q);
    if ((t & 31) == 0) red[t >> 5] = q;
    __syncthreads();
    float var = (red[0] + red[1] + red[2] + red[3] +
                 red[4] + red[5] + red[6] + red[7]) * (1.0f / 1280.0f);
    float rstd = rsqrtf(var + 1e-6f);
    const long long ro = (long long)row * DD;
#pragma unroll
    for (int i = 0; i < 5; i++) {
        int c = t + 256 * i;
        float y = (v[i] - mu) * rstd * g[c] + b[c];
        if (PAIR) {
            bf16 h = __float2bfloat16(y);
            oh[ro + c] = h;
            ol[ro + c] = __float2bfloat16(y - __bfloat162float(h));
        } else {
            o[ro + c] = y;
        }
    }
}

// ---------------------------------------------------------------------------
// softmax: fp32 scores in, bf16-pair probs out
// ---------------------------------------------------------------------------
__global__ void softmax_kernel(const float* __restrict__ sc,
                               bf16* __restrict__ ph, bf16* __restrict__ pl) {
    const long long row = blockIdx.x;
    const float* p = sc + row * (long long)SS;
    const int t = threadIdx.x;
    __shared__ float red[8];
    float v[4];
    float mx = -3.4e38f;
#pragma unroll
    for (int i = 0; i < 4; i++) { v[i] = p[t + 256 * i]; mx = fmaxf(mx, v[i]); }
#pragma unroll
    for (int o = 16; o; o >>= 1) mx = fmaxf(mx, __shfl_xor_sync(0xffffffffu, mx, o));
    if ((t & 31) == 0) red[t >> 5] = mx;
    __syncthreads();
    mx = fmaxf(fmaxf(fmaxf(red[0], red[1]), fmaxf(red[2], red[3])),
               fmaxf(fmaxf(red[4], red[5]), fmaxf(red[6], red[7])));
    __syncthreads();
    float s = 0.0f;
#pragma unroll
    for (int i = 0; i < 4; i++) { v[i] = expf(v[i] - mx); s += v[i]; }
    s = warp_sum(s);
    if ((t & 31) == 0) red[t >> 5] = s;
    __syncthreads();
    s = red[0] + red[1] + red[2] + red[3] + red[4] + red[5] + red[6] + red[7];
    float inv = 1.0f / s;
#pragma unroll
    for (int i = 0; i < 4; i++) {
        float y = v[i] * inv;
        bf16 h = __float2bfloat16(y);
        ph[row * SS + t + 256 * i] = h;
        pl[row * SS + t + 256 * i] = __float2bfloat16(y - __bfloat162float(h));
    }
}

// ---------------------------------------------------------------------------
// 3xBF16 GEMM, pre-split operands:
//   C = alpha * A @ B^T [+bias][+mask][relu][+resid]
//   A hi/lo: [M,K] k-contig (lda). B hi/lo: [N,K] k-contig (ldb).
//   Out: fp32 C, or bf16 pair (Ch, Cl). Batched via blockIdx.z (z>>4, z&15).
//   2-stage cp.async pipeline, 128x128 tile, 8 warps (4m x 2n).
// ---------------------------------------------------------------------------
#define RSTR2  80                 // smem row stride bytes (40 bf16)
#define T_A_HI 0
#define T_A_LO 10240
#define T_B_HI 20480
#define T_B_LO 30720
#define STAGE  40960
#define SMEM_SZ (2 * STAGE)

template <bool MASK, bool RELU, bool BF16OUT>
__global__ void __launch_bounds__(256, 2)
gemm3(const bf16* __restrict__ Ah, const bf16* __restrict__ Al,
      const bf16* __restrict__ Bh, const bf16* __restrict__ Bl,
      float* __restrict__ C, bf16* __restrict__ Ch, bf16* __restrict__ Cl,
      const float* __restrict__ bias, const float* __restrict__ resid,
      int M, int N, int K, int lda, int ldb, int ldc,
      long long sA1, long long sA2, long long sB1, long long sB2,
      long long sC1, long long sC2, float alpha) {
    extern __shared__ char sm[];
    const uint32_t smb = smem_u32(sm);

    const int tid  = threadIdx.x;
    const int wid  = tid >> 5;
    const int lane = tid & 31;
    const int wm   = wid >> 1;
    const int wn   = wid & 1;

    const int z = blockIdx.z, zb = z >> 4, zh = z & 15;
    Ah += zb * sA1 + zh * sA2;  Al += zb * sA1 + zh * sA2;
    Bh += zb * sB1 + zh * sB2;  Bl += zb * sB1 + zh * sB2;
    const long long coff = zb * sC1 + zh * sC2;
    if (BF16OUT) { Ch += coff; Cl += coff; }
    else         { C += coff; if (resid) resid += coff; }

    const int m0 = blockIdx.y * 128;
    const int n0 = blockIdx.x * 128;

    const int frow = tid >> 1;          // 0..127
    const int fc2  = (tid & 1) << 1;    // chunk 0 or 2

    const int nst = (K + 31) >> 5;

    // ---- stage fill via cp.async ----
    auto fill = [&](int s) {
        const uint32_t sb = smb + (uint32_t)((s & 1) * STAGE);
        const long long arow = (long long)(m0 + frow) * lda;
        const long long brow = (long long)(n0 + frow) * ldb;
        const int kbase = s << 5;
        const bool brv = (n0 + frow) < N;
#pragma unroll
        for (int c = fc2; c < fc2 + 2; c++) {
            const int col = kbase + (c << 3);
            const int ska = (col < K) ? 16 : 0;
            const int skb = (col < K && brv) ? 16 : 0;
            const uint32_t d = sb + frow * RSTR2 + c * 16;
            cp16(d + T_A_HI, Ah + (ska ? arow + col : 0), ska);
            cp16(d + T_A_LO, Al + (ska ? arow + col : 0), ska);
            cp16(d + T_B_HI, Bh + (skb ? brow + col : 0), skb);
            cp16(d + T_B_LO, Bl + (skb ? brow + col : 0), skb);
        }
    };

    float acc[2][8][4] = {};

    fill(0);
    CP_COMMIT();

    const int lrow = lane & 15;
    const int lcol = (lane >> 4) << 3;

    for (int s = 0; s < nst; s++) {
        CP_WAIT0();
        __syncthreads();
        if (s + 1 < nst) { fill(s + 1); CP_COMMIT(); }

        const uint32_t sb = smb + (uint32_t)((s & 1) * STAGE);
#pragma unroll
        for (int ks = 0; ks < 2; ks++) {
            const int kk = ks << 4;
            uint32_t ahi[2][4], alo[2][4];
#pragma unroll
            for (int mf = 0; mf < 2; mf++) {
                uint32_t ra = sb + (uint32_t)((wm * 32 + mf * 16 + lrow) * RSTR2
                                              + (kk + lcol) * 2);
                ldsm_x4(ahi[mf][0], ahi[mf][1], ahi[mf][2], ahi[mf][3], ra + T_A_HI);
                ldsm_x4(alo[mf][0], alo[mf][1], alo[mf][2], alo[mf][3], ra + T_A_LO);
            }
#pragma unroll
            for (int nfp = 0; nfp < 4; nfp++) {
                uint32_t rb = sb + (uint32_t)((wn * 64 + nfp * 16 + lrow) * RSTR2
                                              + (kk + lcol) * 2);
                uint32_t bh[4], bl[4];
                ldsm_x4(bh[0], bh[1], bh[2], bh[3], rb + T_B_HI);
                ldsm_x4(bl[0], bl[1], bl[2], bl[3], rb + T_B_LO);
#pragma unroll
                for (int mf = 0; mf < 2; mf++) {
                    float* d0 = acc[mf][2 * nfp];
                    float* d1 = acc[mf][2 * nfp + 1];
                    mma_bf16(d0, ahi[mf], bh[0], bh[2]);
                    mma_bf16(d0, ahi[mf], bl[0], bl[2]);
                    mma_bf16(d0, alo[mf], bh[0], bh[2]);
                    mma_bf16(d1, ahi[mf], bh[1], bh[3]);
                    mma_bf16(d1, ahi[mf], bl[1], bl[3]);
                    mma_bf16(d1, alo[mf], bh[1], bh[3]);
                }
            }
        }
    }

    // ---- epilogue ----
    const int g = lane >> 2;
    const int t = lane & 3;
#pragma unroll
    for (int mf = 0; mf < 2; mf++) {
        const int gm0 = m0 + wm * 32 + mf * 16 + g;
        const int gm1 = gm0 + 8;
        const long long ro0 = (long long)gm0 * ldc;
        const long long ro1 = (long long)gm1 * ldc;
#pragma unroll
        for (int nf = 0; nf < 8; nf++) {
            const int gn = n0 + wn * 64 + nf * 8 + t * 2;
            if (gn < N) {
                float c0 = acc[mf][nf][0] * alpha;
                float c1 = acc[mf][nf][1] * alpha;
                float c2 = acc[mf][nf][2] * alpha;
                float c3 = acc[mf][nf][3] * alpha;
                if (bias) {
                    float b0 = bias[gn], b1 = bias[gn + 1];
                    c0 += b0; c1 += b1; c2 += b0; c3 += b1;
                }
                if (MASK) {
                    if (gn > gm0)     c0 += -10000.0f;
                    if (gn + 1 > gm0) c1 += -10000.0f;
                    if (gn > gm1)     c2 += -10000.0f;
                    if (gn + 1 > gm1) c3 += -10000.0f;
                }
                if (RELU) {
                    c0 = fmaxf(c0, 0.0f); c1 = fmaxf(c1, 0.0f);
                    c2 = fmaxf(c2, 0.0f); c3 = fmaxf(c3, 0.0f);
                }
                if (!BF16OUT) {
                    if (resid) {
                        c0 += resid[ro0 + gn]; c1 += resid[ro0 + gn + 1];
                        c2 += resid[ro1 + gn]; c3 += resid[ro1 + gn + 1];
                    }
                    *(float2*)(C + ro0 + gn) = make_float2(c0, c1);
                    *(float2*)(C + ro1 + gn) = make_float2(c2, c3);
                } else {
                    float h0 = __bfloat162float(__float2bfloat16(c0));
                    float h1 = __bfloat162float(__float2bfloat16(c1));
                    float h2 = __bfloat162float(__float2bfloat16(c2));
                    float h3 = __bfloat162float(__float2bfloat16(c3));
                    *(uint32_t*)(Ch + ro0 + gn) = pk2f(c0, c1);
                    *(uint32_t*)(Ch + ro1 + gn) = pk2f(c2, c3);
                    *(uint32_t*)(Cl + ro0 + gn) = pk2f(c0 - h0, c1 - h1);
                    *(uint32_t*)(Cl + ro1 + gn) = pk2f(c2 - h2, c3 - h3);
                }
            }
        }
    }
}

// ---------------------------------------------------------------------------
// Host launcher (graph-capturable: kernel launches only)
// ---------------------------------------------------------------------------
extern "C" void kernel_launch(void* const* d_in, const int* in_sizes, int n_in,
                              void* d_out, int out_size) {
    const unsigned int* idw = (const unsigned int*)d_in[0];
    const float* emb  = (const float*)d_in[1];
    const float* Wq   = (const float*)d_in[2];
    const float* Wk   = (const float*)d_in[3];
    const float* Wv   = (const float*)d_in[4];
    const float* Wo   = (const float*)d_in[5];
    const float* pbq  = (const float*)d_in[6];
    const float* pbk  = (const float*)d_in[7];
    const float* pbv  = (const float*)d_in[8];
    const float* pbo  = (const float*)d_in[9];
    const float* W1   = (const float*)d_in[10];
    const float* pb1  = (const float*)d_in[11];
    const float* W2   = (const float*)d_in[12];
    const float* pb2  = (const float*)d_in[13];
    const float* ln1g = (const float*)d_in[14];
    const float* ln1b = (const float*)d_in[15];
    const float* ln2g = (const float*)d_in[16];
    const float* ln2b = (const float*)d_in[17];
    const float* lnfg = (const float*)d_in[18];
    const float* lnfb = (const float*)d_in[19];

    float *px, *ps;
    bf16 *nh, *nl, *qh, *ql, *kh, *kl, *vh, *vl, *vth, *vtl, *ch, *cl;
    bf16 *ph, *pl, *h1h, *h1l;
    bf16 *wqh, *wql, *wkh, *wkl, *wvh, *wvl, *woh, *wol, *w1h, *w1l, *w2h, *w2l;
    cudaGetSymbolAddress((void**)&px,  g_x);
    cudaGetSymbolAddress((void**)&ps,  g_scores);
    cudaGetSymbolAddress((void**)&nh,  g_nh);   cudaGetSymbolAddress((void**)&nl,  g_nl);
    cudaGetSymbolAddress((void**)&qh,  g_qh);   cudaGetSymbolAddress((void**)&ql,  g_ql);
    cudaGetSymbolAddress((void**)&kh,  g_kh);   cudaGetSymbolAddress((void**)&kl,  g_kl);
    cudaGetSymbolAddress((void**)&vh,  g_vh);   cudaGetSymbolAddress((void**)&vl,  g_vl);
    cudaGetSymbolAddress((void**)&vth, g_vth);  cudaGetSymbolAddress((void**)&vtl, g_vtl);
    cudaGetSymbolAddress((void**)&ch,  g_ch);   cudaGetSymbolAddress((void**)&cl,  g_cl);
    cudaGetSymbolAddress((void**)&ph,  g_ph);   cudaGetSymbolAddress((void**)&pl,  g_pl);
    cudaGetSymbolAddress((void**)&h1h, g_h1h);  cudaGetSymbolAddress((void**)&h1l, g_h1l);
    cudaGetSymbolAddress((void**)&wqh, g_wqh);  cudaGetSymbolAddress((void**)&wql, g_wql);
    cudaGetSymbolAddress((void**)&wkh, g_wkh);  cudaGetSymbolAddress((void**)&wkl, g_wkl);
    cudaGetSymbolAddress((void**)&wvh, g_wvh);  cudaGetSymbolAddress((void**)&wvl, g_wvl);
    cudaGetSymbolAddress((void**)&woh, g_woh);  cudaGetSymbolAddress((void**)&wol, g_wol);
    cudaGetSymbolAddress((void**)&w1h, g_w1h);  cudaGetSymbolAddress((void**)&w1l, g_w1l);
    cudaGetSymbolAddress((void**)&w2h, g_w2h);  cudaGetSymbolAddress((void**)&w2l, g_w2l);

    cudaFuncSetAttribute(gemm3<true,  false, false>,
                         cudaFuncAttributeMaxDynamicSharedMemorySize, SMEM_SZ);
    cudaFuncSetAttribute(gemm3<false, false, false>,
                         cudaFuncAttributeMaxDynamicSharedMemorySize, SMEM_SZ);
    cudaFuncSetAttribute(gemm3<false, false, true>,
                         cudaFuncAttributeMaxDynamicSharedMemorySize, SMEM_SZ);
    cudaFuncSetAttribute(gemm3<false, true,  true>,
                         cudaFuncAttributeMaxDynamicSharedMemorySize, SMEM_SZ);

    detect_kernel<<<1, 256>>>(idw);
    embed_kernel<<<(MM * DD + 255) / 256, 256>>>(idw, emb, px);

    // weight conversion+transpose (all layers up front)
    {
        dim3 blk(32, 8);
        wtrans_kernel<<<dim3(DD / 32, DD / 32, LL), blk>>>(Wq, wqh, wql, DD, DD);
        wtrans_kernel<<<dim3(DD / 32, DD / 32, LL), blk>>>(Wk, wkh, wkl, DD, DD);
        wtrans_kernel<<<dim3(DD / 32, DD / 32, LL), blk>>>(Wv, wvh, wvl, DD, DD);
        wtrans_kernel<<<dim3(DD / 32, DD / 32, LL), blk>>>(Wo, woh, wol, DD, DD);
        wtrans_kernel<<<dim3(DFF / 32, DD / 32, LL), blk>>>(W1, w1h, w1l, DD, DFF);
        wtrans_kernel<<<dim3(DD / 32, DFF / 32, LL), blk>>>(W2, w2h, w2l, DFF, DD);
    }

    const long long sSD  = (long long)SS * DD;
    const long long sHSS = (long long)HH * SS * SS;
    const long long sSSq = (long long)SS * SS;

    const dim3 gProj(DD / 128, MM / 128, 1);
    const dim3 gFF1(DFF / 128, MM / 128, 1);
    const dim3 gScore(SS / 128, SS / 128, BB * HH);
    const dim3 gCtx(1, SS / 128, BB * HH);

    for (int l = 0; l < LL; l++) {
        const size_t wo4 = (size_t)l * DD * DD;
        const size_t wo1 = (size_t)l * DD * DFF;

        layernorm_kernel<true><<<MM, 256>>>(px, nullptr, nh, nl,
                                            ln1g + l * DD, ln1b + l * DD);

        // q/k/v projections -> bf16 pairs
        gemm3<false, false, true><<<gProj, 256, SMEM_SZ>>>(
            nh, nl, wqh + wo4, wql + wo4, nullptr, qh, ql,
            pbq + l * DD, nullptr,
            MM, DD, DD, DD, DD, DD, 0, 0, 0, 0, 0, 0, 1.0f);
        gemm3<false, false, true><<<gProj, 256, SMEM_SZ>>>(
            nh, nl, wkh + wo4, wkl + wo4, nullptr, kh, kl,
            pbk + l * DD, nullptr,
            MM, DD, DD, DD, DD, DD, 0, 0, 0, 0, 0, 0, 1.0f);
        gemm3<false, false, true><<<gProj, 256, SMEM_SZ>>>(
            nh, nl, wvh + wo4, wvl + wo4, nullptr, vh, vl,
            pbv + l * DD, nullptr,
            MM, DD, DD, DD, DD, DD, 0, 0, 0, 0, 0, 0, 1.0f);

        vtrans_kernel<<<dim3(DD / 32, MM / 32), dim3(32, 8)>>>(vh, vl, vth, vtl);

        // scores = q @ k^T * 1/sqrt(80) + causal mask -> fp32
        gemm3<true, false, false><<<gScore, 256, SMEM_SZ>>>(
            qh, ql, kh, kl, ps, nullptr, nullptr, nullptr, nullptr,
            SS, SS, DHH, DD, DD, SS,
            sSD, (long long)DHH, sSD, (long long)DHH, sHSS, sSSq,
            0.11180339887498949f);

        softmax_kernel<<<BB * HH * SS, 256>>>(ps, ph, pl);

        // ctx = probs @ vT -> bf16 pairs at [B,S,D] layout
        gemm3<false, false, true><<<gCtx, 256, SMEM_SZ>>>(
            ph, pl, vth, vtl, nullptr, ch, cl, nullptr, nullptr,
            SS, DHH, SS, SS, MM, DD,
            sHSS, sSSq, (long long)SS, (long long)DHH * MM, sSD, (long long)DHH,
            1.0f);

        // x = x + ctx @ Wo + bo
        gemm3<false, false, false><<<gProj, 256, SMEM_SZ>>>(
            ch, cl, woh + wo4, wol + wo4, px, nullptr, nullptr,
            pbo + l * DD, px,
            MM, DD, DD, DD, DD, DD, 0, 0, 0, 0, 0, 0, 1.0f);

        layernorm_kernel<true><<<MM, 256>>>(px, nullptr, nh, nl,
                                            ln2g + l * DD, ln2b + l * DD);

        // h1 = relu(n @ W1 + b1) -> bf16 pairs
        gemm3<false, true, true><<<gFF1, 256, SMEM_SZ>>>(
            nh, nl, w1h + wo1, w1l + wo1, nullptr, h1h, h1l,
            pb1 + l * DFF, nullptr,
            MM, DFF, DD, DD, DD, DFF, 0, 0, 0, 0, 0, 0, 1.0f);

        // x = x + h1 @ W2 + b2
        gemm3<false, false, false><<<gProj, 256, SMEM_SZ>>>(
            h1h, h1l, w2h + wo1, w2l + wo1, px, nullptr, nullptr,
            pb2 + l * DD, px,
            MM, DD, DFF, DFF, DFF, DD, 0, 0, 0, 0, 0, 0, 1.0f);
    }

    layernorm_kernel<false><<<MM, 256>>>(px, (float*)d_out, nullptr, nullptr,
                                         lnfg, lnfb);
}

// round 5
// speedup vs baseline: 2.6174x; 1.2197x over previous
#include <cuda_runtime.h>
#include <cuda_bf16.h>
#include <cstdint>

// ---------------------------------------------------------------------------
// CTRL transformer forward, GB300 (compute_103 -> mma.sync path).
// Round 5: warp tile 64x64 (intensity 6 mma/ldsm), fused QKV GEMM (grid 480),
// 64x128-tile variant for the N=1280 GEMMs (grid 320). Operands pre-split
// bf16 hi/lo in gmem; hot loop = cp.async fill + ldmatrix + 3x mma.sync.
// ---------------------------------------------------------------------------

#define BB   2
#define SS   1024
#define DD   1280
#define HH   16
#define DHH  80
#define DFF  8192
#define LL   4
#define MM   (BB * SS)

typedef __nv_bfloat16 bf16;

// fp32 scratch
__device__ float g_x[MM * DD];
__device__ float g_scores[(size_t)BB * HH * SS * SS];      // 128 MB
__device__ float g_bqkv[LL * 3 * DD];                      // packed qkv bias
// activation hi/lo pairs
__device__ bf16 g_nh[MM * DD],  g_nl[MM * DD];
__device__ bf16 g_qkvh[(size_t)MM * 3 * DD], g_qkvl[(size_t)MM * 3 * DD];
__device__ bf16 g_vth[(size_t)DD * MM], g_vtl[(size_t)DD * MM];
__device__ bf16 g_ch[MM * DD],  g_cl[MM * DD];
__device__ bf16 g_ph[(size_t)BB * HH * SS * SS];
__device__ bf16 g_pl[(size_t)BB * HH * SS * SS];
__device__ bf16 g_h1h[(size_t)MM * DFF], g_h1l[(size_t)MM * DFF];
// weights [N,K] hi/lo
__device__ bf16 g_wqkvh[(size_t)LL * 3 * DD * DD], g_wqkvl[(size_t)LL * 3 * DD * DD];
__device__ bf16 g_woh[LL * DD * DD], g_wol[LL * DD * DD];
__device__ bf16 g_w1h[(size_t)LL * DD * DFF], g_w1l[(size_t)LL * DD * DFF];
__device__ bf16 g_w2h[(size_t)LL * DFF * DD], g_w2l[(size_t)LL * DFF * DD];
__device__ int  g_ids64;

// ---------------------------------------------------------------------------
__device__ __forceinline__ uint32_t smem_u32(const void* p) {
    uint32_t a;
    asm("{ .reg .u64 t; cvta.to.shared.u64 t, %1; cvt.u32.u64 %0, t; }"
        : "=r"(a) : "l"(p));
    return a;
}

__device__ __forceinline__ void ldsm_x4(uint32_t& r0, uint32_t& r1,
                                        uint32_t& r2, uint32_t& r3,
                                        uint32_t addr) {
    asm volatile("ldmatrix.sync.aligned.m8n8.x4.shared.b16 {%0,%1,%2,%3}, [%4];"
                 : "=r"(r0), "=r"(r1), "=r"(r2), "=r"(r3) : "r"(addr));
}

__device__ __forceinline__ void mma_bf16(float* d, const uint32_t* a,
                                         uint32_t b0, uint32_t b1) {
    asm volatile(
        "mma.sync.aligned.m16n8k16.row.col.f32.bf16.bf16.f32 "
        "{%0,%1,%2,%3},{%4,%5,%6,%7},{%8,%9},{%0,%1,%2,%3};"
        : "+f"(d[0]), "+f"(d[1]), "+f"(d[2]), "+f"(d[3])
        : "r"(a[0]), "r"(a[1]), "r"(a[2]), "r"(a[3]), "r"(b0), "r"(b1));
}

__device__ __forceinline__ void cp16(uint32_t dst, const void* src, int sz) {
    asm volatile("cp.async.cg.shared.global [%0], [%1], 16, %2;"
                 :: "r"(dst), "l"(src), "r"(sz) : "memory");
}
#define CP_COMMIT() asm volatile("cp.async.commit_group;" ::: "memory")
#define CP_WAIT0()  asm volatile("cp.async.wait_group 0;" ::: "memory")

__device__ __forceinline__ uint32_t pk2f(float a, float b) {
    __nv_bfloat16 ha = __float2bfloat16(a), hb = __float2bfloat16(b);
    return (uint32_t)__bfloat16_as_ushort(ha) |
           ((uint32_t)__bfloat16_as_ushort(hb) << 16);
}

// ---------------------------------------------------------------------------
// detect + embed
// ---------------------------------------------------------------------------
__global__ void detect_kernel(const unsigned int* __restrict__ w) {
    __shared__ int any;
    if (threadIdx.x == 0) any = 0;
    __syncthreads();
    int loc = 0;
    for (int i = 2 * threadIdx.x + 1; i < 2048; i += 512)
        loc |= (w[i] != 0u);
    if (loc) atomicOr(&any, 1);
    __syncthreads();
    if (threadIdx.x == 0) g_ids64 = any ? 0 : 1;
}

__global__ void embed_kernel(const unsigned int* __restrict__ idw,
                             const float* __restrict__ emb,
                             float* __restrict__ x) {
    int idx = blockIdx.x * 256 + threadIdx.x;
    if (idx >= MM * DD) return;
    int d   = idx % DD;
    int row = idx / DD;
    int s   = row & (SS - 1);
    int id  = g_ids64 ? (int)idw[2 * row] : (int)idw[row];
    float val = emb[(long long)id * DD + d] * 35.77708763999664f;
    int m = (d < 640) ? d : d - 640;
    float rate = expf(-0.014391156831212787f * (float)m);
    float ang  = (float)s * rate;
    val += (d < 640) ? sinf(ang) : cosf(ang);
    x[idx] = val;
}

// ---------------------------------------------------------------------------
// weight convert+transpose: fp32 [K,N] -> bf16 hi/lo [N,K]; z = layer
// out pointer pre-offset to the section; per-z stride = ostride.
// ---------------------------------------------------------------------------
__global__ void wtrans_kernel(const float* __restrict__ W,
                              bf16* __restrict__ oh, bf16* __restrict__ ol,
                              int K, int N, size_t ostride) {
    W  += (size_t)blockIdx.z * K * N;
    oh += (size_t)blockIdx.z * ostride;
    ol += (size_t)blockIdx.z * ostride;
    __shared__ float tf[32][33];
    const int n0 = blockIdx.x * 32, k0 = blockIdx.y * 32;
    const int tx = threadIdx.x, ty = threadIdx.y;
#pragma unroll
    for (int i = 0; i < 4; i++)
        tf[ty + 8 * i][tx] = W[(long long)(k0 + ty + 8 * i) * N + n0 + tx];
    __syncthreads();
#pragma unroll
    for (int i = 0; i < 4; i++) {
        float v = tf[tx][ty + 8 * i];
        bf16 h = __float2bfloat16(v);
        bf16 l = __float2bfloat16(v - __bfloat162float(h));
        long long o = (long long)(n0 + ty + 8 * i) * K + k0 + tx;
        oh[o] = h; ol[o] = l;
    }
}

// pack qkv bias: [L][3840] from bq,bk,bv
__global__ void packb_kernel(const float* __restrict__ bq,
                             const float* __restrict__ bk,
                             const float* __restrict__ bv,
                             float* __restrict__ o) {
    int i = blockIdx.x * 256 + threadIdx.x;
    if (i >= LL * 3 * DD) return;
    int l = i / (3 * DD), j = i % (3 * DD);
    float v = (j < DD) ? bq[l * DD + j]
            : (j < 2 * DD) ? bk[l * DD + j - DD]
            : bv[l * DD + j - 2 * DD];
    o[i] = v;
}

// v transpose from packed qkv (row stride 3840): hi/lo [MM,DD] -> [DD,MM]
__global__ void vtrans_kernel(const bf16* __restrict__ ih, const bf16* __restrict__ il,
                              bf16* __restrict__ oh, bf16* __restrict__ ol,
                              int istride) {
    __shared__ bf16 th[32][34], tl[32][34];
    const int n0 = blockIdx.x * 32, m0 = blockIdx.y * 32;
    const int tx = threadIdx.x, ty = threadIdx.y;
#pragma unroll
    for (int i = 0; i < 4; i++) {
        long long src = (long long)(m0 + ty + 8 * i) * istride + n0 + tx;
        th[ty + 8 * i][tx] = ih[src];
        tl[ty + 8 * i][tx] = il[src];
    }
    __syncthreads();
#pragma unroll
    for (int i = 0; i < 4; i++) {
        long long dst = (long long)(n0 + ty + 8 * i) * MM + m0 + tx;
        oh[dst] = th[tx][ty + 8 * i];
        ol[dst] = tl[tx][ty + 8 * i];
    }
}

// ---------------------------------------------------------------------------
// LayerNorm / softmax
// ---------------------------------------------------------------------------
__device__ __forceinline__ float warp_sum(float v) {
#pragma unroll
    for (int o = 16; o; o >>= 1) v += __shfl_xor_sync(0xffffffffu, v, o);
    return v;
}

template <bool PAIR>
__global__ void layernorm_kernel(const float* __restrict__ x,
                                 float* __restrict__ o,
                                 bf16* __restrict__ oh, bf16* __restrict__ ol,
                                 const float* __restrict__ g,
                                 const float* __restrict__ b) {
    const int row = blockIdx.x;
    const int t   = threadIdx.x;
    const float* xr = x + (long long)row * DD;
    __shared__ float red[8];
    float v[5];
    float s = 0.0f;
#pragma unroll
    for (int i = 0; i < 5; i++) { v[i] = xr[t + 256 * i]; s += v[i]; }
    s = warp_sum(s);
    if ((t & 31) == 0) red[t >> 5] = s;
    __syncthreads();
    float mu = (red[0] + red[1] + red[2] + red[3] +
                red[4] + red[5] + red[6] + red[7]) * (1.0f / 1280.0f);
    __syncthreads();
    float q = 0.0f;
#pragma unroll
    for (int i = 0; i < 5; i++) { float dv = v[i] - mu; q += dv * dv; }
    q = warp_sum(q);
    if ((t & 31) == 0) red[t >> 5] = q;
    __syncthreads();
    float var = (red[0] + red[1] + red[2] + red[3] +
                 red[4] + red[5] + red[6] + red[7]) * (1.0f / 1280.0f);
    float rstd = rsqrtf(var + 1e-6f);
    const long long ro = (long long)row * DD;
#pragma unroll
    for (int i = 0; i < 5; i++) {
        int c = t + 256 * i;
        float y = (v[i] - mu) * rstd * g[c] + b[c];
        if (PAIR) {
            bf16 h = __float2bfloat16(y);
            oh[ro + c] = h;
            ol[ro + c] = __float2bfloat16(y - __bfloat162float(h));
        } else {
            o[ro + c] = y;
        }
    }
}

__global__ void softmax_kernel(const float* __restrict__ sc,
                               bf16* __restrict__ ph, bf16* __restrict__ pl) {
    const long long row = blockIdx.x;
    const float* p = sc + row * (long long)SS;
    const int t = threadIdx.x;
    __shared__ float red[8];
    float v[4];
    float mx = -3.4e38f;
#pragma unroll
    for (int i = 0; i < 4; i++) { v[i] = p[t + 256 * i]; mx = fmaxf(mx, v[i]); }
#pragma unroll
    for (int o = 16; o; o >>= 1) mx = fmaxf(mx, __shfl_xor_sync(0xffffffffu, mx, o));
    if ((t & 31) == 0) red[t >> 5] = mx;
    __syncthreads();
    mx = fmaxf(fmaxf(fmaxf(red[0], red[1]), fmaxf(red[2], red[3])),
               fmaxf(fmaxf(red[4], red[5]), fmaxf(red[6], red[7])));
    __syncthreads();
    float s = 0.0f;
#pragma unroll
    for (int i = 0; i < 4; i++) { v[i] = expf(v[i] - mx); s += v[i]; }
    s = warp_sum(s);
    if ((t & 31) == 0) red[t >> 5] = s;
    __syncthreads();
    s = red[0] + red[1] + red[2] + red[3] + red[4] + red[5] + red[6] + red[7];
    float inv = 1.0f / s;
#pragma unroll
    for (int i = 0; i < 4; i++) {
        float y = v[i] * inv;
        bf16 h = __float2bfloat16(y);
        ph[row * SS + t + 256 * i] = h;
        pl[row * SS + t + 256 * i] = __float2bfloat16(y - __bfloat162float(h));
    }
}

// ---------------------------------------------------------------------------
// 3xBF16 GEMM, pre-split operands. Warp tile 64x64; MW x NW warps per CTA;
// CTA tile (64*MW) x (64*NW). A hi/lo [M,K] (lda), B hi/lo [N,K] (ldb).
// C = alpha*A@B^T [+bias][+mask][relu][+resid]; fp32 out or bf16-pair out.
// Batched via blockIdx.z -> (z>>4, z&15). M % (64*MW)==0, K % 8 == 0.
// ---------------------------------------------------------------------------
template <int MW, int NW, bool MASK, bool RELU, bool BF16OUT>
__global__ void __launch_bounds__(MW * NW * 32)
gemm3(const bf16* __restrict__ Ah, const bf16* __restrict__ Al,
      const bf16* __restrict__ Bh, const bf16* __restrict__ Bl,
      float* __restrict__ C, bf16* __restrict__ Ch, bf16* __restrict__ Cl,
      const float* __restrict__ bias, const float* __restrict__ resid,
      int M, int N, int K, int lda, int ldb, int ldc,
      long long sA1, long long sA2, long long sB1, long long sB2,
      long long sC1, long long sC2, float alpha) {
    constexpr int AR  = 64 * MW;          // A rows per tile
    constexpr int BR  = 64 * NW;          // B rows per tile
    constexpr int BD  = MW * NW * 32;     // threads
    constexpr int A_HI = 0;
    constexpr int A_LO = AR * 80;
    constexpr int B_HI = 2 * AR * 80;
    constexpr int B_LO = 2 * AR * 80 + BR * 80;
    constexpr int STG  = 2 * (AR + BR) * 80;

    extern __shared__ char sm[];
    const uint32_t smb = smem_u32(sm);

    const int tid  = threadIdx.x;
    const int wid  = tid >> 5;
    const int lane = tid & 31;
    const int wm   = wid / NW;
    const int wn   = wid % NW;

    const int z = blockIdx.z, zb = z >> 4, zh = z & 15;
    Ah += zb * sA1 + zh * sA2;  Al += zb * sA1 + zh * sA2;
    Bh += zb * sB1 + zh * sB2;  Bl += zb * sB1 + zh * sB2;
    const long long coff = zb * sC1 + zh * sC2;
    if (BF16OUT) { Ch += coff; Cl += coff; }
    else         { C += coff; if (resid) resid += coff; }

    const int m0 = blockIdx.y * AR;
    const int n0 = blockIdx.x * BR;

    const int nst = (K + 31) >> 5;

    auto fill = [&](int s) {
        const uint32_t sb = smb + (uint32_t)((s & 1) * STG);
        const int kbase = s << 5;
#pragma unroll
        for (int i = tid; i < AR * 4; i += BD) {
            const int row = i >> 2, c = i & 3;
            const int col = kbase + (c << 3);
            const int sz  = (col < K) ? 16 : 0;
            const long long go = (long long)(m0 + row) * lda + col;
            const uint32_t d = sb + row * 80 + c * 16;
            cp16(d + A_HI, Ah + (sz ? go : 0), sz);
            cp16(d + A_LO, Al + (sz ? go : 0), sz);
        }
#pragma unroll
        for (int i = tid; i < BR * 4; i += BD) {
            const int row = i >> 2, c = i & 3;
            const int col = kbase + (c << 3);
            const int sz  = (col < K && (n0 + row) < N) ? 16 : 0;
            const long long go = (long long)(n0 + row) * ldb + col;
            const uint32_t d = sb + row * 80 + c * 16;
            cp16(d + B_HI, Bh + (sz ? go : 0), sz);
            cp16(d + B_LO, Bl + (sz ? go : 0), sz);
        }
    };

    float acc[4][8][4] = {};

    fill(0);
    CP_COMMIT();

    const int lrow = lane & 15;
    const int lcol = (lane >> 4) << 3;

    for (int s = 0; s < nst; s++) {
        CP_WAIT0();
        __syncthreads();
        if (s + 1 < nst) { fill(s + 1); CP_COMMIT(); }

        const uint32_t sb = smb + (uint32_t)((s & 1) * STG);
#pragma unroll
        for (int ks = 0; ks < 2; ks++) {
            const int kk = ks << 4;
            uint32_t ahi[4][4], alo[4][4];
#pragma unroll
            for (int mf = 0; mf < 4; mf++) {
                uint32_t ra = sb + (uint32_t)((wm * 64 + mf * 16 + lrow) * 80
                                              + (kk + lcol) * 2);
                ldsm_x4(ahi[mf][0], ahi[mf][1], ahi[mf][2], ahi[mf][3], ra + A_HI);
                ldsm_x4(alo[mf][0], alo[mf][1], alo[mf][2], alo[mf][3], ra + A_LO);
            }
#pragma unroll
            for (int nfp = 0; nfp < 4; nfp++) {
                uint32_t rb = sb + (uint32_t)((wn * 64 + nfp * 16 + lrow) * 80
                                              + (kk + lcol) * 2);
                uint32_t bh[4], bl[4];
                ldsm_x4(bh[0], bh[1], bh[2], bh[3], rb + B_HI);
                ldsm_x4(bl[0], bl[1], bl[2], bl[3], rb + B_LO);
#pragma unroll
                for (int mf = 0; mf < 4; mf++) {
                    float* d0 = acc[mf][2 * nfp];
                    float* d1 = acc[mf][2 * nfp + 1];
                    mma_bf16(d0, ahi[mf], bh[0], bh[2]);
                    mma_bf16(d0, ahi[mf], bl[0], bl[2]);
                    mma_bf16(d0, alo[mf], bh[0], bh[2]);
                    mma_bf16(d1, ahi[mf], bh[1], bh[3]);
                    mma_bf16(d1, ahi[mf], bl[1], bl[3]);
                    mma_bf16(d1, alo[mf], bh[1], bh[3]);
                }
            }
        }
    }

    // ---- epilogue ----
    const int g = lane >> 2;
    const int t = lane & 3;
#pragma unroll
    for (int mf = 0; mf < 4; mf++) {
        const int gm0 = m0 + wm * 64 + mf * 16 + g;
        const int gm1 = gm0 + 8;
        const long long ro0 = (long long)gm0 * ldc;
        const long long ro1 = (long long)gm1 * ldc;
#pragma unroll
        for (int nf = 0; nf < 8; nf++) {
            const int gn = n0 + wn * 64 + nf * 8 + t * 2;
            if (gn < N) {
                float c0 = acc[mf][nf][0] * alpha;
                float c1 = acc[mf][nf][1] * alpha;
                float c2 = acc[mf][nf][2] * alpha;
                float c3 = acc[mf][nf][3] * alpha;
                if (bias) {
                    float b0 = bias[gn], b1 = bias[gn + 1];
                    c0 += b0; c1 += b1; c2 += b0; c3 += b1;
                }
                if (MASK) {
                    if (gn > gm0)     c0 += -10000.0f;
                    if (gn + 1 > gm0) c1 += -10000.0f;
                    if (gn > gm1)     c2 += -10000.0f;
                    if (gn + 1 > gm1) c3 += -10000.0f;
                }
                if (RELU) {
                    c0 = fmaxf(c0, 0.0f); c1 = fmaxf(c1, 0.0f);
                    c2 = fmaxf(c2, 0.0f); c3 = fmaxf(c3, 0.0f);
                }
                if (!BF16OUT) {
                    if (resid) {
                        c0 += resid[ro0 + gn]; c1 += resid[ro0 + gn + 1];
                        c2 += resid[ro1 + gn]; c3 += resid[ro1 + gn + 1];
                    }
                    *(float2*)(C + ro0 + gn) = make_float2(c0, c1);
                    *(float2*)(C + ro1 + gn) = make_float2(c2, c3);
                } else {
                    float h0 = __bfloat162float(__float2bfloat16(c0));
                    float h1 = __bfloat162float(__float2bfloat16(c1));
                    float h2 = __bfloat162float(__float2bfloat16(c2));
                    float h3 = __bfloat162float(__float2bfloat16(c3));
                    *(uint32_t*)(Ch + ro0 + gn) = pk2f(c0, c1);
                    *(uint32_t*)(Ch + ro1 + gn) = pk2f(c2, c3);
                    *(uint32_t*)(Cl + ro0 + gn) = pk2f(c0 - h0, c1 - h1);
                    *(uint32_t*)(Cl + ro1 + gn) = pk2f(c2 - h2, c3 - h3);
                }
            }
        }
    }
}

#define SM22 (2 * (128 + 128) * 80 * 2)   // 81920
#define SM12 (2 * (64 + 128) * 80 * 2)    // 61440

// ---------------------------------------------------------------------------
// Host launcher (graph-capturable: kernel launches only)
// ---------------------------------------------------------------------------
extern "C" void kernel_launch(void* const* d_in, const int* in_sizes, int n_in,
                              void* d_out, int out_size) {
    const unsigned int* idw = (const unsigned int*)d_in[0];
    const float* emb  = (const float*)d_in[1];
    const float* Wq   = (const float*)d_in[2];
    const float* Wk   = (const float*)d_in[3];
    const float* Wv   = (const float*)d_in[4];
    const float* Wo   = (const float*)d_in[5];
    const float* pbq  = (const float*)d_in[6];
    const float* pbk  = (const float*)d_in[7];
    const float* pbv  = (const float*)d_in[8];
    const float* pbo  = (const float*)d_in[9];
    const float* W1   = (const float*)d_in[10];
    const float* pb1  = (const float*)d_in[11];
    const float* W2   = (const float*)d_in[12];
    const float* pb2  = (const float*)d_in[13];
    const float* ln1g = (const float*)d_in[14];
    const float* ln1b = (const float*)d_in[15];
    const float* ln2g = (const float*)d_in[16];
    const float* ln2b = (const float*)d_in[17];
    const float* lnfg = (const float*)d_in[18];
    const float* lnfb = (const float*)d_in[19];

    float *px, *ps, *pbqkv;
    bf16 *nh, *nl, *qkvh, *qkvl, *vth, *vtl, *ch, *cl, *ph, *pl, *h1h, *h1l;
    bf16 *wqkvh, *wqkvl, *woh, *wol, *w1h, *w1l, *w2h, *w2l;
    cudaGetSymbolAddress((void**)&px,    g_x);
    cudaGetSymbolAddress((void**)&ps,    g_scores);
    cudaGetSymbolAddress((void**)&pbqkv, g_bqkv);
    cudaGetSymbolAddress((void**)&nh,    g_nh);    cudaGetSymbolAddress((void**)&nl,    g_nl);
    cudaGetSymbolAddress((void**)&qkvh,  g_qkvh);  cudaGetSymbolAddress((void**)&qkvl,  g_qkvl);
    cudaGetSymbolAddress((void**)&vth,   g_vth);   cudaGetSymbolAddress((void**)&vtl,   g_vtl);
    cudaGetSymbolAddress((void**)&ch,    g_ch);    cudaGetSymbolAddress((void**)&cl,    g_cl);
    cudaGetSymbolAddress((void**)&ph,    g_ph);    cudaGetSymbolAddress((void**)&pl,    g_pl);
    cudaGetSymbolAddress((void**)&h1h,   g_h1h);   cudaGetSymbolAddress((void**)&h1l,   g_h1l);
    cudaGetSymbolAddress((void**)&wqkvh, g_wqkvh); cudaGetSymbolAddress((void**)&wqkvl, g_wqkvl);
    cudaGetSymbolAddress((void**)&woh,   g_woh);   cudaGetSymbolAddress((void**)&wol,   g_wol);
    cudaGetSymbolAddress((void**)&w1h,   g_w1h);   cudaGetSymbolAddress((void**)&w1l,   g_w1l);
    cudaGetSymbolAddress((void**)&w2h,   g_w2h);   cudaGetSymbolAddress((void**)&w2l,   g_w2l);

    cudaFuncSetAttribute(gemm3<2, 2, false, false, true>,
                         cudaFuncAttributeMaxDynamicSharedMemorySize, SM22);
    cudaFuncSetAttribute(gemm3<2, 2, true,  false, false>,
                         cudaFuncAttributeMaxDynamicSharedMemorySize, SM22);
    cudaFuncSetAttribute(gemm3<2, 2, false, true,  true>,
                         cudaFuncAttributeMaxDynamicSharedMemorySize, SM22);
    cudaFuncSetAttribute(gemm3<1, 2, false, false, false>,
                         cudaFuncAttributeMaxDynamicSharedMemorySize, SM12);

    detect_kernel<<<1, 256>>>(idw);
    embed_kernel<<<(MM * DD + 255) / 256, 256>>>(idw, emb, px);

    // weight conversion+transpose + bias pack (all layers up front)
    {
        dim3 blk(32, 8);
        const size_t oQKV = (size_t)3 * DD * DD;
        wtrans_kernel<<<dim3(DD / 32, DD / 32, LL), blk>>>(Wq, wqkvh, wqkvl, DD, DD, oQKV);
        wtrans_kernel<<<dim3(DD / 32, DD / 32, LL), blk>>>(
            Wk, wqkvh + (size_t)DD * DD, wqkvl + (size_t)DD * DD, DD, DD, oQKV);
        wtrans_kernel<<<dim3(DD / 32, DD / 32, LL), blk>>>(
            Wv, wqkvh + (size_t)2 * DD * DD, wqkvl + (size_t)2 * DD * DD, DD, DD, oQKV);
        wtrans_kernel<<<dim3(DD / 32, DD / 32, LL), blk>>>(Wo, woh, wol, DD, DD,
                                                           (size_t)DD * DD);
        wtrans_kernel<<<dim3(DFF / 32, DD / 32, LL), blk>>>(W1, w1h, w1l, DD, DFF,
                                                            (size_t)DD * DFF);
        wtrans_kernel<<<dim3(DD / 32, DFF / 32, LL), blk>>>(W2, w2h, w2l, DFF, DD,
                                                            (size_t)DFF * DD);
        packb_kernel<<<(LL * 3 * DD + 255) / 256, 256>>>(pbq, pbk, pbv, pbqkv);
    }

    const long long sSD  = (long long)SS * DD;
    const long long sHSS = (long long)HH * SS * SS;
    const long long sSSq = (long long)SS * SS;
    const int D3 = 3 * DD;                       // 3840

    const dim3 gQKV(D3 / 128, MM / 128);         // (30, 16) = 480
    const dim3 gN64(DD / 128, MM / 64);          // (10, 32) = 320
    const dim3 gFF1(DFF / 128, MM / 128);        // (64, 16) = 1024
    const dim3 gScore(SS / 128, SS / 128, BB * HH);
    const dim3 gCtx(1, SS / 128, BB * HH);

    for (int l = 0; l < LL; l++) {
        const size_t woff4 = (size_t)l * DD * DD;
        const size_t woffQ = (size_t)l * 3 * DD * DD;
        const size_t woff1 = (size_t)l * DD * DFF;

        layernorm_kernel<true><<<MM, 256>>>(px, nullptr, nh, nl,
                                            ln1g + l * DD, ln1b + l * DD);

        // fused qkv projection -> packed [MM, 3840] bf16 pairs
        gemm3<2, 2, false, false, true><<<gQKV, 128, SM22>>>(
            nh, nl, wqkvh + woffQ, wqkvl + woffQ, nullptr, qkvh, qkvl,
            pbqkv + l * D3, nullptr,
            MM, D3, DD, DD, DD, D3, 0, 0, 0, 0, 0, 0, 1.0f);

        vtrans_kernel<<<dim3(DD / 32, MM / 32), dim3(32, 8)>>>(
            qkvh + 2 * DD, qkvl + 2 * DD, vth, vtl, D3);

        // scores = q @ k^T * 1/sqrt(80) + causal mask -> fp32
        gemm3<2, 2, true, false, false><<<gScore, 128, SM22>>>(
            qkvh, qkvl, qkvh + DD, qkvl + DD, ps, nullptr, nullptr,
            nullptr, nullptr,
            SS, SS, DHH, D3, D3, SS,
            (long long)SS * D3, (long long)DHH,
            (long long)SS * D3, (long long)DHH, sHSS, sSSq,
            0.11180339887498949f);

        softmax_kernel<<<BB * HH * SS, 256>>>(ps, ph, pl);

        // ctx = probs @ vT -> bf16 pairs at [B,S,D] layout
        gemm3<2, 2, false, false, true><<<gCtx, 128, SM22>>>(
            ph, pl, vth, vtl, nullptr, ch, cl, nullptr, nullptr,
            SS, DHH, SS, SS, MM, DD,
            sHSS, sSSq, (long long)SS, (long long)DHH * MM, sSD, (long long)DHH,
            1.0f);

        // x = x + ctx @ Wo + bo   (64x128 tiles -> 320 CTAs)
        gemm3<1, 2, false, false, false><<<gN64, 64, SM12>>>(
            ch, cl, woh + woff4, wol + woff4, px, nullptr, nullptr,
            pbo + l * DD, px,
            MM, DD, DD, DD, DD, DD, 0, 0, 0, 0, 0, 0, 1.0f);

        layernorm_kernel<true><<<MM, 256>>>(px, nullptr, nh, nl,
                                            ln2g + l * DD, ln2b + l * DD);

        // h1 = relu(n @ W1 + b1)
        gemm3<2, 2, false, true, true><<<gFF1, 128, SM22>>>(
            nh, nl, w1h + woff1, w1l + woff1, nullptr, h1h, h1l,
            pb1 + l * DFF, nullptr,
            MM, DFF, DD, DD, DD, DFF, 0, 0, 0, 0, 0, 0, 1.0f);

        // x = x + h1 @ W2 + b2   (64x128 tiles -> 320 CTAs)
        gemm3<1, 2, false, false, false><<<gN64, 64, SM12>>>(
            h1h, h1l, w2h + woff1, w2l + woff1, px, nullptr, nullptr,
            pb2 + l * DD, px,
            MM, DD, DFF, DFF, DFF, DD, 0, 0, 0, 0, 0, 0, 1.0f);
    }

    layernorm_kernel<false><<<MM, 256>>>(px, (float*)d_out, nullptr, nullptr,
                                         lnfg, lnfb);
}

// round 7
// speedup vs baseline: 2.6642x; 1.0179x over previous
#include <cuda_runtime.h>
#include <cuda_bf16.h>
#include <cstdint>

// ---------------------------------------------------------------------------
// CTRL transformer forward, GB300 (compute_103 -> mma.sync path).
// Round 7: round 6 with the smem-size macros fixed (2 pipeline buffers =
// 2*STG bytes; round 6 allocated only 1*STG -> OOB smem writes).
// Term-outer MMA ordering, causal tile skip, causal softmax, K-clipped ctx.
// ---------------------------------------------------------------------------

#define BB   2
#define SS   1024
#define DD   1280
#define HH   16
#define DHH  80
#define DFF  8192
#define LL   4
#define MM   (BB * SS)

typedef __nv_bfloat16 bf16;

// fp32 scratch
__device__ float g_x[MM * DD];
__device__ float g_scores[(size_t)BB * HH * SS * SS];      // 128 MB
__device__ float g_bqkv[LL * 3 * DD];                      // packed qkv bias
// activation hi/lo pairs
__device__ bf16 g_nh[MM * DD],  g_nl[MM * DD];
__device__ bf16 g_qkvh[(size_t)MM * 3 * DD], g_qkvl[(size_t)MM * 3 * DD];
__device__ bf16 g_vth[(size_t)DD * MM], g_vtl[(size_t)DD * MM];
__device__ bf16 g_ch[MM * DD],  g_cl[MM * DD];
__device__ bf16 g_ph[(size_t)BB * HH * SS * SS];
__device__ bf16 g_pl[(size_t)BB * HH * SS * SS];
__device__ bf16 g_h1h[(size_t)MM * DFF], g_h1l[(size_t)MM * DFF];
// weights [N,K] hi/lo
__device__ bf16 g_wqkvh[(size_t)LL * 3 * DD * DD], g_wqkvl[(size_t)LL * 3 * DD * DD];
__device__ bf16 g_woh[LL * DD * DD], g_wol[LL * DD * DD];
__device__ bf16 g_w1h[(size_t)LL * DD * DFF], g_w1l[(size_t)LL * DD * DFF];
__device__ bf16 g_w2h[(size_t)LL * DFF * DD], g_w2l[(size_t)LL * DFF * DD];
__device__ int  g_ids64;

// ---------------------------------------------------------------------------
__device__ __forceinline__ uint32_t smem_u32(const void* p) {
    uint32_t a;
    asm("{ .reg .u64 t; cvta.to.shared.u64 t, %1; cvt.u32.u64 %0, t; }"
        : "=r"(a) : "l"(p));
    return a;
}

__device__ __forceinline__ void ldsm_x4(uint32_t& r0, uint32_t& r1,
                                        uint32_t& r2, uint32_t& r3,
                                        uint32_t addr) {
    asm volatile("ldmatrix.sync.aligned.m8n8.x4.shared.b16 {%0,%1,%2,%3}, [%4];"
                 : "=r"(r0), "=r"(r1), "=r"(r2), "=r"(r3) : "r"(addr));
}

__device__ __forceinline__ void mma_bf16(float* d, const uint32_t* a,
                                         uint32_t b0, uint32_t b1) {
    asm volatile(
        "mma.sync.aligned.m16n8k16.row.col.f32.bf16.bf16.f32 "
        "{%0,%1,%2,%3},{%4,%5,%6,%7},{%8,%9},{%0,%1,%2,%3};"
        : "+f"(d[0]), "+f"(d[1]), "+f"(d[2]), "+f"(d[3])
        : "r"(a[0]), "r"(a[1]), "r"(a[2]), "r"(a[3]), "r"(b0), "r"(b1));
}

__device__ __forceinline__ void cp16(uint32_t dst, const void* src, int sz) {
    asm volatile("cp.async.cg.shared.global [%0], [%1], 16, %2;"
                 :: "r"(dst), "l"(src), "r"(sz) : "memory");
}
#define CP_COMMIT() asm volatile("cp.async.commit_group;" ::: "memory")
#define CP_WAIT0()  asm volatile("cp.async.wait_group 0;" ::: "memory")

__device__ __forceinline__ uint32_t pk2f(float a, float b) {
    __nv_bfloat16 ha = __float2bfloat16(a), hb = __float2bfloat16(b);
    return (uint32_t)__bfloat16_as_ushort(ha) |
           ((uint32_t)__bfloat16_as_ushort(hb) << 16);
}

// ---------------------------------------------------------------------------
// detect + embed
// ---------------------------------------------------------------------------
__global__ void detect_kernel(const unsigned int* __restrict__ w) {
    __shared__ int any;
    if (threadIdx.x == 0) any = 0;
    __syncthreads();
    int loc = 0;
    for (int i = 2 * threadIdx.x + 1; i < 2048; i += 512)
        loc |= (w[i] != 0u);
    if (loc) atomicOr(&any, 1);
    __syncthreads();
    if (threadIdx.x == 0) g_ids64 = any ? 0 : 1;
}

__global__ void embed_kernel(const unsigned int* __restrict__ idw,
                             const float* __restrict__ emb,
                             float* __restrict__ x) {
    int idx = blockIdx.x * 256 + threadIdx.x;
    if (idx >= MM * DD) return;
    int d   = idx % DD;
    int row = idx / DD;
    int s   = row & (SS - 1);
    int id  = g_ids64 ? (int)idw[2 * row] : (int)idw[row];
    float val = emb[(long long)id * DD + d] * 35.77708763999664f;
    int m = (d < 640) ? d : d - 640;
    float rate = expf(-0.014391156831212787f * (float)m);
    float ang  = (float)s * rate;
    val += (d < 640) ? sinf(ang) : cosf(ang);
    x[idx] = val;
}

// ---------------------------------------------------------------------------
// weight convert+transpose: fp32 [K,N] -> bf16 hi/lo [N,K]; z = layer
// ---------------------------------------------------------------------------
__global__ void wtrans_kernel(const float* __restrict__ W,
                              bf16* __restrict__ oh, bf16* __restrict__ ol,
                              int K, int N, size_t ostride) {
    W  += (size_t)blockIdx.z * K * N;
    oh += (size_t)blockIdx.z * ostride;
    ol += (size_t)blockIdx.z * ostride;
    __shared__ float tf[32][33];
    const int n0 = blockIdx.x * 32, k0 = blockIdx.y * 32;
    const int tx = threadIdx.x, ty = threadIdx.y;
#pragma unroll
    for (int i = 0; i < 4; i++)
        tf[ty + 8 * i][tx] = W[(long long)(k0 + ty + 8 * i) * N + n0 + tx];
    __syncthreads();
#pragma unroll
    for (int i = 0; i < 4; i++) {
        float v = tf[tx][ty + 8 * i];
        bf16 h = __float2bfloat16(v);
        bf16 l = __float2bfloat16(v - __bfloat162float(h));
        long long o = (long long)(n0 + ty + 8 * i) * K + k0 + tx;
        oh[o] = h; ol[o] = l;
    }
}

// pack qkv bias: [L][3840] from bq,bk,bv
__global__ void packb_kernel(const float* __restrict__ bq,
                             const float* __restrict__ bk,
                             const float* __restrict__ bv,
                             float* __restrict__ o) {
    int i = blockIdx.x * 256 + threadIdx.x;
    if (i >= LL * 3 * DD) return;
    int l = i / (3 * DD), j = i % (3 * DD);
    float v = (j < DD) ? bq[l * DD + j]
            : (j < 2 * DD) ? bk[l * DD + j - DD]
            : bv[l * DD + j - 2 * DD];
    o[i] = v;
}

// v transpose from packed qkv (row stride 3840): hi/lo [MM,DD] -> [DD,MM]
__global__ void vtrans_kernel(const bf16* __restrict__ ih, const bf16* __restrict__ il,
                              bf16* __restrict__ oh, bf16* __restrict__ ol,
                              int istride) {
    __shared__ bf16 th[32][34], tl[32][34];
    const int n0 = blockIdx.x * 32, m0 = blockIdx.y * 32;
    const int tx = threadIdx.x, ty = threadIdx.y;
#pragma unroll
    for (int i = 0; i < 4; i++) {
        long long src = (long long)(m0 + ty + 8 * i) * istride + n0 + tx;
        th[ty + 8 * i][tx] = ih[src];
        tl[ty + 8 * i][tx] = il[src];
    }
    __syncthreads();
#pragma unroll
    for (int i = 0; i < 4; i++) {
        long long dst = (long long)(n0 + ty + 8 * i) * MM + m0 + tx;
        oh[dst] = th[tx][ty + 8 * i];
        ol[dst] = tl[tx][ty + 8 * i];
    }
}

// ---------------------------------------------------------------------------
// LayerNorm / softmax
// ---------------------------------------------------------------------------
__device__ __forceinline__ float warp_sum(float v) {
#pragma unroll
    for (int o = 16; o; o >>= 1) v += __shfl_xor_sync(0xffffffffu, v, o);
    return v;
}

template <bool PAIR>
__global__ void layernorm_kernel(const float* __restrict__ x,
                                 float* __restrict__ o,
                                 bf16* __restrict__ oh, bf16* __restrict__ ol,
                                 const float* __restrict__ g,
                                 const float* __restrict__ b) {
    const int row = blockIdx.x;
    const int t   = threadIdx.x;
    const float* xr = x + (long long)row * DD;
    __shared__ float red[8];
    float v[5];
    float s = 0.0f;
#pragma unroll
    for (int i = 0; i < 5; i++) { v[i] = xr[t + 256 * i]; s += v[i]; }
    s = warp_sum(s);
    if ((t & 31) == 0) red[t >> 5] = s;
    __syncthreads();
    float mu = (red[0] + red[1] + red[2] + red[3] +
                red[4] + red[5] + red[6] + red[7]) * (1.0f / 1280.0f);
    __syncthreads();
    float q = 0.0f;
#pragma unroll
    for (int i = 0; i < 5; i++) { float dv = v[i] - mu; q += dv * dv; }
    q = warp_sum(q);
    if ((t & 31) == 0) red[t >> 5] = q;
    __syncthreads();
    float var = (red[0] + red[1] + red[2] + red[3] +
                 red[4] + red[5] + red[6] + red[7]) * (1.0f / 1280.0f);
    float rstd = rsqrtf(var + 1e-6f);
    const long long ro = (long long)row * DD;
#pragma unroll
    for (int i = 0; i < 5; i++) {
        int c = t + 256 * i;
        float y = (v[i] - mu) * rstd * g[c] + b[c];
        if (PAIR) {
            bf16 h = __float2bfloat16(y);
            oh[ro + c] = h;
            ol[ro + c] = __float2bfloat16(y - __bfloat162float(h));
        } else {
            o[ro + c] = y;
        }
    }
}

// causal softmax: k > q treated as masked (prob exactly 0; matches ref since
// exp(-10000 + O(60)) underflows to 0 in fp32). Skipped score tiles (k-tile
// fully above diagonal) are never read.
__global__ void softmax_kernel(const float* __restrict__ sc,
                               bf16* __restrict__ ph, bf16* __restrict__ pl) {
    const long long row = blockIdx.x;
    const int q = (int)(row & (SS - 1));
    const float* p = sc + row * (long long)SS;
    const int t = threadIdx.x;
    __shared__ float red[8];
    float v[4];
    float mx = -3.4e38f;
#pragma unroll
    for (int i = 0; i < 4; i++) {
        int k = t + 256 * i;
        v[i] = (k <= q) ? p[k] : -3.4e38f;
        mx = fmaxf(mx, v[i]);
    }
#pragma unroll
    for (int o = 16; o; o >>= 1) mx = fmaxf(mx, __shfl_xor_sync(0xffffffffu, mx, o));
    if ((t & 31) == 0) red[t >> 5] = mx;
    __syncthreads();
    mx = fmaxf(fmaxf(fmaxf(red[0], red[1]), fmaxf(red[2], red[3])),
               fmaxf(fmaxf(red[4], red[5]), fmaxf(red[6], red[7])));
    __syncthreads();
    float s = 0.0f;
#pragma unroll
    for (int i = 0; i < 4; i++) {
        int k = t + 256 * i;
        v[i] = (k <= q) ? expf(v[i] - mx) : 0.0f;
        s += v[i];
    }
    s = warp_sum(s);
    if ((t & 31) == 0) red[t >> 5] = s;
    __syncthreads();
    s = red[0] + red[1] + red[2] + red[3] + red[4] + red[5] + red[6] + red[7];
    float inv = 1.0f / s;
#pragma unroll
    for (int i = 0; i < 4; i++) {
        float y = v[i] * inv;
        bf16 h = __float2bfloat16(y);
        ph[row * SS + t + 256 * i] = h;
        pl[row * SS + t + 256 * i] = __float2bfloat16(y - __bfloat162float(h));
    }
}

// ---------------------------------------------------------------------------
// 3xBF16 GEMM, pre-split operands. Warp tile 64x64; CTA tile (64MW)x(64NW).
// A hi/lo [M,K] (lda), B hi/lo [N,K] (ldb). C = alpha*A@B^T [+bias][+mask]
// [relu][+resid]; fp32 or bf16-pair out. Batched via blockIdx.z (z>>4, z&15).
// MASK additionally skips all-masked tiles (n0 > m0+AR-1).
// KCLIP: A cols are zero for k >= m0+AR (causal probs) -> clip the K loop.
// Inner loop is term-outer (hh, hl, lh): same-accumulator MMA reuse distance
// is 8 instructions (covers HMMA RAW latency).
// ---------------------------------------------------------------------------
template <int MW, int NW, bool MASK, bool RELU, bool BF16OUT, bool KCLIP>
__global__ void __launch_bounds__(MW * NW * 32)
gemm3(const bf16* __restrict__ Ah, const bf16* __restrict__ Al,
      const bf16* __restrict__ Bh, const bf16* __restrict__ Bl,
      float* __restrict__ C, bf16* __restrict__ Ch, bf16* __restrict__ Cl,
      const float* __restrict__ bias, const float* __restrict__ resid,
      int M, int N, int K, int lda, int ldb, int ldc,
      long long sA1, long long sA2, long long sB1, long long sB2,
      long long sC1, long long sC2, float alpha) {
    constexpr int AR  = 64 * MW;
    constexpr int BR  = 64 * NW;
    constexpr int BD  = MW * NW * 32;
    constexpr int A_HI = 0;
    constexpr int A_LO = AR * 80;
    constexpr int B_HI = 2 * AR * 80;
    constexpr int B_LO = 2 * AR * 80 + BR * 80;
    constexpr int STG  = 2 * (AR + BR) * 80;

    const int m0 = blockIdx.y * AR;
    const int n0 = blockIdx.x * BR;
    if (MASK && n0 > m0 + (AR - 1)) return;   // fully masked tile

    extern __shared__ char sm[];
    const uint32_t smb = smem_u32(sm);

    const int tid  = threadIdx.x;
    const int wid  = tid >> 5;
    const int lane = tid & 31;
    const int wm   = wid / NW;
    const int wn   = wid % NW;

    const int z = blockIdx.z, zb = z >> 4, zh = z & 15;
    Ah += zb * sA1 + zh * sA2;  Al += zb * sA1 + zh * sA2;
    Bh += zb * sB1 + zh * sB2;  Bl += zb * sB1 + zh * sB2;
    const long long coff = zb * sC1 + zh * sC2;
    if (BF16OUT) { Ch += coff; Cl += coff; }
    else         { C += coff; if (resid) resid += coff; }

    int Keff = K;
    if (KCLIP && m0 + AR < K) Keff = m0 + AR;
    const int nst = (Keff + 31) >> 5;

    auto fill = [&](int s) {
        const uint32_t sb = smb + (uint32_t)((s & 1) * STG);
        const int kbase = s << 5;
#pragma unroll
        for (int i = tid; i < AR * 4; i += BD) {
            const int row = i >> 2, c = i & 3;
            const int col = kbase + (c << 3);
            const int sz  = (col < Keff) ? 16 : 0;
            const long long go = (long long)(m0 + row) * lda + col;
            const uint32_t d = sb + row * 80 + c * 16;
            cp16(d + A_HI, Ah + (sz ? go : 0), sz);
            cp16(d + A_LO, Al + (sz ? go : 0), sz);
        }
#pragma unroll
        for (int i = tid; i < BR * 4; i += BD) {
            const int row = i >> 2, c = i & 3;
            const int col = kbase + (c << 3);
            const int sz  = (col < Keff && (n0 + row) < N) ? 16 : 0;
            const long long go = (long long)(n0 + row) * ldb + col;
            const uint32_t d = sb + row * 80 + c * 16;
            cp16(d + B_HI, Bh + (sz ? go : 0), sz);
            cp16(d + B_LO, Bl + (sz ? go : 0), sz);
        }
    };

    float acc[4][8][4] = {};

    fill(0);
    CP_COMMIT();

    const int lrow = lane & 15;
    const int lcol = (lane >> 4) << 3;

    for (int s = 0; s < nst; s++) {
        CP_WAIT0();
        __syncthreads();
        if (s + 1 < nst) { fill(s + 1); CP_COMMIT(); }

        const uint32_t sb = smb + (uint32_t)((s & 1) * STG);
#pragma unroll
        for (int ks = 0; ks < 2; ks++) {
            const int kk = ks << 4;
            uint32_t ahi[4][4], alo[4][4];
#pragma unroll
            for (int mf = 0; mf < 4; mf++) {
                uint32_t ra = sb + (uint32_t)((wm * 64 + mf * 16 + lrow) * 80
                                              + (kk + lcol) * 2);
                ldsm_x4(ahi[mf][0], ahi[mf][1], ahi[mf][2], ahi[mf][3], ra + A_HI);
                ldsm_x4(alo[mf][0], alo[mf][1], alo[mf][2], alo[mf][3], ra + A_LO);
            }
#pragma unroll
            for (int nfp = 0; nfp < 4; nfp++) {
                uint32_t rb = sb + (uint32_t)((wn * 64 + nfp * 16 + lrow) * 80
                                              + (kk + lcol) * 2);
                uint32_t bh[4], bl[4];
                ldsm_x4(bh[0], bh[1], bh[2], bh[3], rb + B_HI);
                ldsm_x4(bl[0], bl[1], bl[2], bl[3], rb + B_LO);
                // term-outer: same-acc reuse distance = 8 mma
#pragma unroll
                for (int mf = 0; mf < 4; mf++) {
                    mma_bf16(acc[mf][2 * nfp],     ahi[mf], bh[0], bh[2]);
                    mma_bf16(acc[mf][2 * nfp + 1], ahi[mf], bh[1], bh[3]);
                }
#pragma unroll
                for (int mf = 0; mf < 4; mf++) {
                    mma_bf16(acc[mf][2 * nfp],     ahi[mf], bl[0], bl[2]);
                    mma_bf16(acc[mf][2 * nfp + 1], ahi[mf], bl[1], bl[3]);
                }
#pragma unroll
                for (int mf = 0; mf < 4; mf++) {
                    mma_bf16(acc[mf][2 * nfp],     alo[mf], bh[0], bh[2]);
                    mma_bf16(acc[mf][2 * nfp + 1], alo[mf], bh[1], bh[3]);
                }
            }
        }
    }

    // ---- epilogue ----
    const int g = lane >> 2;
    const int t = lane & 3;
#pragma unroll
    for (int mf = 0; mf < 4; mf++) {
        const int gm0 = m0 + wm * 64 + mf * 16 + g;
        const int gm1 = gm0 + 8;
        const long long ro0 = (long long)gm0 * ldc;
        const long long ro1 = (long long)gm1 * ldc;
#pragma unroll
        for (int nf = 0; nf < 8; nf++) {
            const int gn = n0 + wn * 64 + nf * 8 + t * 2;
            if (gn < N) {
                float c0 = acc[mf][nf][0] * alpha;
                float c1 = acc[mf][nf][1] * alpha;
                float c2 = acc[mf][nf][2] * alpha;
                float c3 = acc[mf][nf][3] * alpha;
                if (bias) {
                    float b0 = bias[gn], b1 = bias[gn + 1];
                    c0 += b0; c1 += b1; c2 += b0; c3 += b1;
                }
                if (MASK) {
                    if (gn > gm0)     c0 += -10000.0f;
                    if (gn + 1 > gm0) c1 += -10000.0f;
                    if (gn > gm1)     c2 += -10000.0f;
                    if (gn + 1 > gm1) c3 += -10000.0f;
                }
                if (RELU) {
                    c0 = fmaxf(c0, 0.0f); c1 = fmaxf(c1, 0.0f);
                    c2 = fmaxf(c2, 0.0f); c3 = fmaxf(c3, 0.0f);
                }
                if (!BF16OUT) {
                    if (resid) {
                        c0 += resid[ro0 + gn]; c1 += resid[ro0 + gn + 1];
                        c2 += resid[ro1 + gn]; c3 += resid[ro1 + gn + 1];
                    }
                    *(float2*)(C + ro0 + gn) = make_float2(c0, c1);
                    *(float2*)(C + ro1 + gn) = make_float2(c2, c3);
                } else {
                    float h0 = __bfloat162float(__float2bfloat16(c0));
                    float h1 = __bfloat162float(__float2bfloat16(c1));
                    float h2 = __bfloat162float(__float2bfloat16(c2));
                    float h3 = __bfloat162float(__float2bfloat16(c3));
                    *(uint32_t*)(Ch + ro0 + gn) = pk2f(c0, c1);
                    *(uint32_t*)(Ch + ro1 + gn) = pk2f(c2, c3);
                    *(uint32_t*)(Cl + ro0 + gn) = pk2f(c0 - h0, c1 - h1);
                    *(uint32_t*)(Cl + ro1 + gn) = pk2f(c2 - h2, c3 - h3);
                }
            }
        }
    }
}

// dynamic smem: 2 pipeline buffers of STG bytes each
#define SM22 (2 * 2 * (128 + 128) * 80)   // 81920
#define SM12 (2 * 2 * (64 + 128) * 80)    // 61440

// ---------------------------------------------------------------------------
// Host launcher (graph-capturable: kernel launches only)
// ---------------------------------------------------------------------------
extern "C" void kernel_launch(void* const* d_in, const int* in_sizes, int n_in,
                              void* d_out, int out_size) {
    const unsigned int* idw = (const unsigned int*)d_in[0];
    const float* emb  = (const float*)d_in[1];
    const float* Wq   = (const float*)d_in[2];
    const float* Wk   = (const float*)d_in[3];
    const float* Wv   = (const float*)d_in[4];
    const float* Wo   = (const float*)d_in[5];
    const float* pbq  = (const float*)d_in[6];
    const float* pbk  = (const float*)d_in[7];
    const float* pbv  = (const float*)d_in[8];
    const float* pbo  = (const float*)d_in[9];
    const float* W1   = (const float*)d_in[10];
    const float* pb1  = (const float*)d_in[11];
    const float* W2   = (const float*)d_in[12];
    const float* pb2  = (const float*)d_in[13];
    const float* ln1g = (const float*)d_in[14];
    const float* ln1b = (const float*)d_in[15];
    const float* ln2g = (const float*)d_in[16];
    const float* ln2b = (const float*)d_in[17];
    const float* lnfg = (const float*)d_in[18];
    const float* lnfb = (const float*)d_in[19];

    float *px, *ps, *pbqkv;
    bf16 *nh, *nl, *qkvh, *qkvl, *vth, *vtl, *ch, *cl, *ph, *pl, *h1h, *h1l;
    bf16 *wqkvh, *wqkvl, *woh, *wol, *w1h, *w1l, *w2h, *w2l;
    cudaGetSymbolAddress((void**)&px,    g_x);
    cudaGetSymbolAddress((void**)&ps,    g_scores);
    cudaGetSymbolAddress((void**)&pbqkv, g_bqkv);
    cudaGetSymbolAddress((void**)&nh,    g_nh);    cudaGetSymbolAddress((void**)&nl,    g_nl);
    cudaGetSymbolAddress((void**)&qkvh,  g_qkvh);  cudaGetSymbolAddress((void**)&qkvl,  g_qkvl);
    cudaGetSymbolAddress((void**)&vth,   g_vth);   cudaGetSymbolAddress((void**)&vtl,   g_vtl);
    cudaGetSymbolAddress((void**)&ch,    g_ch);    cudaGetSymbolAddress((void**)&cl,    g_cl);
    cudaGetSymbolAddress((void**)&ph,    g_ph);    cudaGetSymbolAddress((void**)&pl,    g_pl);
    cudaGetSymbolAddress((void**)&h1h,   g_h1h);   cudaGetSymbolAddress((void**)&h1l,   g_h1l);
    cudaGetSymbolAddress((void**)&wqkvh, g_wqkvh); cudaGetSymbolAddress((void**)&wqkvl, g_wqkvl);
    cudaGetSymbolAddress((void**)&woh,   g_woh);   cudaGetSymbolAddress((void**)&wol,   g_wol);
    cudaGetSymbolAddress((void**)&w1h,   g_w1h);   cudaGetSymbolAddress((void**)&w1l,   g_w1l);
    cudaGetSymbolAddress((void**)&w2h,   g_w2h);   cudaGetSymbolAddress((void**)&w2l,   g_w2l);

    cudaFuncSetAttribute(gemm3<2, 2, false, false, true,  false>,
                         cudaFuncAttributeMaxDynamicSharedMemorySize, SM22);
    cudaFuncSetAttribute(gemm3<2, 2, true,  false, false, false>,
                         cudaFuncAttributeMaxDynamicSharedMemorySize, SM22);
    cudaFuncSetAttribute(gemm3<2, 2, false, true,  true,  false>,
                         cudaFuncAttributeMaxDynamicSharedMemorySize, SM22);
    cudaFuncSetAttribute(gemm3<2, 2, false, false, true,  true>,
                         cudaFuncAttributeMaxDynamicSharedMemorySize, SM22);
    cudaFuncSetAttribute(gemm3<1, 2, false, false, false, false>,
                         cudaFuncAttributeMaxDynamicSharedMemorySize, SM12);

    detect_kernel<<<1, 256>>>(idw);
    embed_kernel<<<(MM * DD + 255) / 256, 256>>>(idw, emb, px);

    {
        dim3 blk(32, 8);
        const size_t oQKV = (size_t)3 * DD * DD;
        wtrans_kernel<<<dim3(DD / 32, DD / 32, LL), blk>>>(Wq, wqkvh, wqkvl, DD, DD, oQKV);
        wtrans_kernel<<<dim3(DD / 32, DD / 32, LL), blk>>>(
            Wk, wqkvh + (size_t)DD * DD, wqkvl + (size_t)DD * DD, DD, DD, oQKV);
        wtrans_kernel<<<dim3(DD / 32, DD / 32, LL), blk>>>(
            Wv, wqkvh + (size_t)2 * DD * DD, wqkvl + (size_t)2 * DD * DD, DD, DD, oQKV);
        wtrans_kernel<<<dim3(DD / 32, DD / 32, LL), blk>>>(Wo, woh, wol, DD, DD,
                                                           (size_t)DD * DD);
        wtrans_kernel<<<dim3(DFF / 32, DD / 32, LL), blk>>>(W1, w1h, w1l, DD, DFF,
                                                            (size_t)DD * DFF);
        wtrans_kernel<<<dim3(DD / 32, DFF / 32, LL), blk>>>(W2, w2h, w2l, DFF, DD,
                                                            (size_t)DFF * DD);
        packb_kernel<<<(LL * 3 * DD + 255) / 256, 256>>>(pbq, pbk, pbv, pbqkv);
    }

    const long long sSD  = (long long)SS * DD;
    const long long sHSS = (long long)HH * SS * SS;
    const long long sSSq = (long long)SS * SS;
    const int D3 = 3 * DD;                       // 3840

    const dim3 gQKV(D3 / 128, MM / 128);         // (30, 16) = 480
    const dim3 gN64(DD / 128, MM / 64);          // (10, 32) = 320
    const dim3 gFF1(DFF / 128, MM / 128);        // (64, 16) = 1024
    const dim3 gScore(SS / 128, SS / 128, BB * HH);
    const dim3 gCtx(1, SS / 128, BB * HH);

    for (int l = 0; l < LL; l++) {
        const size_t woff4 = (size_t)l * DD * DD;
        const size_t woffQ = (size_t)l * 3 * DD * DD;
        const size_t woff1 = (size_t)l * DD * DFF;

        layernorm_kernel<true><<<MM, 256>>>(px, nullptr, nh, nl,
                                            ln1g + l * DD, ln1b + l * DD);

        // fused qkv projection -> packed [MM, 3840] bf16 pairs
        gemm3<2, 2, false, false, true, false><<<gQKV, 128, SM22>>>(
            nh, nl, wqkvh + woffQ, wqkvl + woffQ, nullptr, qkvh, qkvl,
            pbqkv + l * D3, nullptr,
            MM, D3, DD, DD, DD, D3, 0, 0, 0, 0, 0, 0, 1.0f);

        vtrans_kernel<<<dim3(DD / 32, MM / 32), dim3(32, 8)>>>(
            qkvh + 2 * DD, qkvl + 2 * DD, vth, vtl, D3);

        // scores = q @ k^T * 1/sqrt(80) + causal mask -> fp32 (skips
        // fully-masked tiles; those are never read by the causal softmax)
        gemm3<2, 2, true, false, false, false><<<gScore, 128, SM22>>>(
            qkvh, qkvl, qkvh + DD, qkvl + DD, ps, nullptr, nullptr,
            nullptr, nullptr,
            SS, SS, DHH, D3, D3, SS,
            (long long)SS * D3, (long long)DHH,
            (long long)SS * D3, (long long)DHH, sHSS, sSSq,
            0.11180339887498949f);

        softmax_kernel<<<BB * HH * SS, 256>>>(ps, ph, pl);

        // ctx = probs @ vT (K clipped causally) -> bf16 pairs at [B,S,D]
        gemm3<2, 2, false, false, true, true><<<gCtx, 128, SM22>>>(
            ph, pl, vth, vtl, nullptr, ch, cl, nullptr, nullptr,
            SS, DHH, SS, SS, MM, DD,
            sHSS, sSSq, (long long)SS, (long long)DHH * MM, sSD, (long long)DHH,
            1.0f);

        // x = x + ctx @ Wo + bo   (64x128 tiles -> 320 CTAs)
        gemm3<1, 2, false, false, false, false><<<gN64, 64, SM12>>>(
            ch, cl, woh + woff4, wol + woff4, px, nullptr, nullptr,
            pbo + l * DD, px,
            MM, DD, DD, DD, DD, DD, 0, 0, 0, 0, 0, 0, 1.0f);

        layernorm_kernel<true><<<MM, 256>>>(px, nullptr, nh, nl,
                                            ln2g + l * DD, ln2b + l * DD);

        // h1 = relu(n @ W1 + b1)
        gemm3<2, 2, false, true, true, false><<<gFF1, 128, SM22>>>(
            nh, nl, w1h + woff1, w1l + woff1, nullptr, h1h, h1l,
            pb1 + l * DFF, nullptr,
            MM, DFF, DD, DD, DD, DFF, 0, 0, 0, 0, 0, 0, 1.0f);

        // x = x + h1 @ W2 + b2   (64x128 tiles -> 320 CTAs)
        gemm3<1, 2, false, false, false, false><<<gN64, 64, SM12>>>(
            h1h, h1l, w2h + woff1, w2l + woff1, px, nullptr, nullptr,
            pb2 + l * DD, px,
            MM, DD, DFF, DFF, DFF, DD, 0, 0, 0, 0, 0, 0, 1.0f);
    }

    layernorm_kernel<false><<<MM, 256>>>(px, (float*)d_out, nullptr, nullptr,
                                         lnfg, lnfb);
}

// round 8
// speedup vs baseline: 3.6954x; 1.3871x over previous
#include <cuda_runtime.h>
#include <cuda_fp16.h>
#include <cstdint>

// ---------------------------------------------------------------------------
// CTRL transformer forward, GB300 (compute_103 -> mma.sync path).
// Round 8: fp16 2-term GEMM. A operand split (hi+lo fp16, error 2^-21),
// B operand single fp16 (error 2^-12 -> ~1e-4 dot rel err, threshold 1e-3).
// C = (Ah + Al) @ Bh^T: 2 mma per k16 (was 3), B smem/traffic halved.
// ---------------------------------------------------------------------------

#define BB   2
#define SS   1024
#define DD   1280
#define HH   16
#define DHH  80
#define DFF  8192
#define LL   4
#define MM   (BB * SS)

typedef __half hf;

// fp32 scratch
__device__ float g_x[MM * DD];
__device__ float g_scores[(size_t)BB * HH * SS * SS];      // 128 MB
__device__ float g_bqkv[LL * 3 * DD];                      // packed qkv bias
// activation hi/lo pairs (A-role operands)
__device__ hf g_nh[MM * DD],  g_nl[MM * DD];
__device__ hf g_qkvh[(size_t)MM * 3 * DD], g_qkvl[(size_t)MM * 3 * DD];
__device__ hf g_vth[(size_t)DD * MM];                      // v transposed (B-role: hi only)
__device__ hf g_ch[MM * DD],  g_cl[MM * DD];
__device__ hf g_ph[(size_t)BB * HH * SS * SS];
__device__ hf g_pl[(size_t)BB * HH * SS * SS];
__device__ hf g_h1h[(size_t)MM * DFF], g_h1l[(size_t)MM * DFF];
// weights [N,K] (B-role: hi only)
__device__ hf g_wqkvh[(size_t)LL * 3 * DD * DD];
__device__ hf g_woh[LL * DD * DD];
__device__ hf g_w1h[(size_t)LL * DD * DFF];
__device__ hf g_w2h[(size_t)LL * DFF * DD];
__device__ int g_ids64;

// ---------------------------------------------------------------------------
__device__ __forceinline__ uint32_t smem_u32(const void* p) {
    uint32_t a;
    asm("{ .reg .u64 t; cvta.to.shared.u64 t, %1; cvt.u32.u64 %0, t; }"
        : "=r"(a) : "l"(p));
    return a;
}

__device__ __forceinline__ void ldsm_x4(uint32_t& r0, uint32_t& r1,
                                        uint32_t& r2, uint32_t& r3,
                                        uint32_t addr) {
    asm volatile("ldmatrix.sync.aligned.m8n8.x4.shared.b16 {%0,%1,%2,%3}, [%4];"
                 : "=r"(r0), "=r"(r1), "=r"(r2), "=r"(r3) : "r"(addr));
}

__device__ __forceinline__ void mma_f16(float* d, const uint32_t* a,
                                        uint32_t b0, uint32_t b1) {
    asm volatile(
        "mma.sync.aligned.m16n8k16.row.col.f32.f16.f16.f32 "
        "{%0,%1,%2,%3},{%4,%5,%6,%7},{%8,%9},{%0,%1,%2,%3};"
        : "+f"(d[0]), "+f"(d[1]), "+f"(d[2]), "+f"(d[3])
        : "r"(a[0]), "r"(a[1]), "r"(a[2]), "r"(a[3]), "r"(b0), "r"(b1));
}

__device__ __forceinline__ void cp16(uint32_t dst, const void* src, int sz) {
    asm volatile("cp.async.cg.shared.global [%0], [%1], 16, %2;"
                 :: "r"(dst), "l"(src), "r"(sz) : "memory");
}
#define CP_COMMIT() asm volatile("cp.async.commit_group;" ::: "memory")
#define CP_WAIT0()  asm volatile("cp.async.wait_group 0;" ::: "memory")

__device__ __forceinline__ uint32_t pk2h(float a, float b) {
    __half2 h = __floats2half2_rn(a, b);
    return *reinterpret_cast<uint32_t*>(&h);
}

// ---------------------------------------------------------------------------
// detect + embed
// ---------------------------------------------------------------------------
__global__ void detect_kernel(const unsigned int* __restrict__ w) {
    __shared__ int any;
    if (threadIdx.x == 0) any = 0;
    __syncthreads();
    int loc = 0;
    for (int i = 2 * threadIdx.x + 1; i < 2048; i += 512)
        loc |= (w[i] != 0u);
    if (loc) atomicOr(&any, 1);
    __syncthreads();
    if (threadIdx.x == 0) g_ids64 = any ? 0 : 1;
}

__global__ void embed_kernel(const unsigned int* __restrict__ idw,
                             const float* __restrict__ emb,
                             float* __restrict__ x) {
    int idx = blockIdx.x * 256 + threadIdx.x;
    if (idx >= MM * DD) return;
    int d   = idx % DD;
    int row = idx / DD;
    int s   = row & (SS - 1);
    int id  = g_ids64 ? (int)idw[2 * row] : (int)idw[row];
    float val = emb[(long long)id * DD + d] * 35.77708763999664f;
    int m = (d < 640) ? d : d - 640;
    float rate = expf(-0.014391156831212787f * (float)m);
    float ang  = (float)s * rate;
    val += (d < 640) ? sinf(ang) : cosf(ang);
    x[idx] = val;
}

// ---------------------------------------------------------------------------
// weight convert+transpose: fp32 [K,N] -> fp16 [N,K]; z = layer
// ---------------------------------------------------------------------------
__global__ void wtrans_kernel(const float* __restrict__ W,
                              hf* __restrict__ oh,
                              int K, int N, size_t ostride) {
    W  += (size_t)blockIdx.z * K * N;
    oh += (size_t)blockIdx.z * ostride;
    __shared__ float tf[32][33];
    const int n0 = blockIdx.x * 32, k0 = blockIdx.y * 32;
    const int tx = threadIdx.x, ty = threadIdx.y;
#pragma unroll
    for (int i = 0; i < 4; i++)
        tf[ty + 8 * i][tx] = W[(long long)(k0 + ty + 8 * i) * N + n0 + tx];
    __syncthreads();
#pragma unroll
    for (int i = 0; i < 4; i++) {
        long long o = (long long)(n0 + ty + 8 * i) * K + k0 + tx;
        oh[o] = __float2half_rn(tf[tx][ty + 8 * i]);
    }
}

// pack qkv bias: [L][3840] from bq,bk,bv
__global__ void packb_kernel(const float* __restrict__ bq,
                             const float* __restrict__ bk,
                             const float* __restrict__ bv,
                             float* __restrict__ o) {
    int i = blockIdx.x * 256 + threadIdx.x;
    if (i >= LL * 3 * DD) return;
    int l = i / (3 * DD), j = i % (3 * DD);
    float v = (j < DD) ? bq[l * DD + j]
            : (j < 2 * DD) ? bk[l * DD + j - DD]
            : bv[l * DD + j - 2 * DD];
    o[i] = v;
}

// v transpose from packed qkv (row stride 3840): hi [MM,DD] -> [DD,MM]
__global__ void vtrans_kernel(const hf* __restrict__ ih,
                              hf* __restrict__ oh, int istride) {
    __shared__ hf th[32][34];
    const int n0 = blockIdx.x * 32, m0 = blockIdx.y * 32;
    const int tx = threadIdx.x, ty = threadIdx.y;
#pragma unroll
    for (int i = 0; i < 4; i++)
        th[ty + 8 * i][tx] = ih[(long long)(m0 + ty + 8 * i) * istride + n0 + tx];
    __syncthreads();
#pragma unroll
    for (int i = 0; i < 4; i++)
        oh[(long long)(n0 + ty + 8 * i) * MM + m0 + tx] = th[tx][ty + 8 * i];
}

// ---------------------------------------------------------------------------
// LayerNorm / softmax
// ---------------------------------------------------------------------------
__device__ __forceinline__ float warp_sum(float v) {
#pragma unroll
    for (int o = 16; o; o >>= 1) v += __shfl_xor_sync(0xffffffffu, v, o);
    return v;
}

template <bool PAIR>
__global__ void layernorm_kernel(const float* __restrict__ x,
                                 float* __restrict__ o,
                                 hf* __restrict__ oh, hf* __restrict__ ol,
                                 const float* __restrict__ g,
                                 const float* __restrict__ b) {
    const int row = blockIdx.x;
    const int t   = threadIdx.x;
    const float* xr = x + (long long)row * DD;
    __shared__ float red[8];
    float v[5];
    float s = 0.0f;
#pragma unroll
    for (int i = 0; i < 5; i++) { v[i] = xr[t + 256 * i]; s += v[i]; }
    s = warp_sum(s);
    if ((t & 31) == 0) red[t >> 5] = s;
    __syncthreads();
    float mu = (red[0] + red[1] + red[2] + red[3] +
                red[4] + red[5] + red[6] + red[7]) * (1.0f / 1280.0f);
    __syncthreads();
    float q = 0.0f;
#pragma unroll
    for (int i = 0; i < 5; i++) { float dv = v[i] - mu; q += dv * dv; }
    q = warp_sum(q);
    if ((t & 31) == 0) red[t >> 5] = q;
    __syncthreads();
    float var = (red[0] + red[1] + red[2] + red[3] +
                 red[4] + red[5] + red[6] + red[7]) * (1.0f / 1280.0f);
    float rstd = rsqrtf(var + 1e-6f);
    const long long ro = (long long)row * DD;
#pragma unroll
    for (int i = 0; i < 5; i++) {
        int c = t + 256 * i;
        float y = (v[i] - mu) * rstd * g[c] + b[c];
        if (PAIR) {
            hf h = __float2half_rn(y);
            oh[ro + c] = h;
            ol[ro + c] = __float2half_rn(y - __half2float(h));
        } else {
            o[ro + c] = y;
        }
    }
}

// causal softmax: k > q masked (prob exactly 0; matches ref since
// exp(-10000 + O(60)) underflows to 0 in fp32). Skipped score tiles never read.
__global__ void softmax_kernel(const float* __restrict__ sc,
                               hf* __restrict__ ph, hf* __restrict__ pl) {
    const long long row = blockIdx.x;
    const int q = (int)(row & (SS - 1));
    const float* p = sc + row * (long long)SS;
    const int t = threadIdx.x;
    __shared__ float red[8];
    float v[4];
    float mx = -3.4e38f;
#pragma unroll
    for (int i = 0; i < 4; i++) {
        int k = t + 256 * i;
        v[i] = (k <= q) ? p[k] : -3.4e38f;
        mx = fmaxf(mx, v[i]);
    }
#pragma unroll
    for (int o = 16; o; o >>= 1) mx = fmaxf(mx, __shfl_xor_sync(0xffffffffu, mx, o));
    if ((t & 31) == 0) red[t >> 5] = mx;
    __syncthreads();
    mx = fmaxf(fmaxf(fmaxf(red[0], red[1]), fmaxf(red[2], red[3])),
               fmaxf(fmaxf(red[4], red[5]), fmaxf(red[6], red[7])));
    __syncthreads();
    float s = 0.0f;
#pragma unroll
    for (int i = 0; i < 4; i++) {
        int k = t + 256 * i;
        v[i] = (k <= q) ? expf(v[i] - mx) : 0.0f;
        s += v[i];
    }
    s = warp_sum(s);
    if ((t & 31) == 0) red[t >> 5] = s;
    __syncthreads();
    s = red[0] + red[1] + red[2] + red[3] + red[4] + red[5] + red[6] + red[7];
    float inv = 1.0f / s;
#pragma unroll
    for (int i = 0; i < 4; i++) {
        float y = v[i] * inv;
        hf h = __float2half_rn(y);
        ph[row * SS + t + 256 * i] = h;
        pl[row * SS + t + 256 * i] = __float2half_rn(y - __half2float(h));
    }
}

// ---------------------------------------------------------------------------
// 2-term fp16 GEMM: C = alpha * (Ah + Al) @ Bh^T [+bias][+mask][relu][+resid]
//   Ah/Al [M,K] (lda), Bh [N,K] (ldb). fp32 out or fp16-pair out.
//   Warp tile 64x64; CTA tile (64MW)x(64NW); batched via blockIdx.z.
//   MASK skips fully-masked tiles; KCLIP clips causal-zero K range.
// ---------------------------------------------------------------------------
template <int MW, int NW, bool MASK, bool RELU, bool PAIROUT, bool KCLIP>
__global__ void __launch_bounds__(MW * NW * 32)
gemm2(const hf* __restrict__ Ah, const hf* __restrict__ Al,
      const hf* __restrict__ Bh,
      float* __restrict__ C, hf* __restrict__ Ch, hf* __restrict__ Cl,
      const float* __restrict__ bias, const float* __restrict__ resid,
      int M, int N, int K, int lda, int ldb, int ldc,
      long long sA1, long long sA2, long long sB1, long long sB2,
      long long sC1, long long sC2, float alpha) {
    constexpr int AR  = 64 * MW;
    constexpr int BR  = 64 * NW;
    constexpr int BD  = MW * NW * 32;
    constexpr int A_HI = 0;
    constexpr int A_LO = AR * 80;
    constexpr int B_HI = 2 * AR * 80;
    constexpr int STG  = (2 * AR + BR) * 80;

    const int m0 = blockIdx.y * AR;
    const int n0 = blockIdx.x * BR;
    if (MASK && n0 > m0 + (AR - 1)) return;

    extern __shared__ char sm[];
    const uint32_t smb = smem_u32(sm);

    const int tid  = threadIdx.x;
    const int wid  = tid >> 5;
    const int lane = tid & 31;
    const int wm   = wid / NW;
    const int wn   = wid % NW;

    const int z = blockIdx.z, zb = z >> 4, zh = z & 15;
    Ah += zb * sA1 + zh * sA2;  Al += zb * sA1 + zh * sA2;
    Bh += zb * sB1 + zh * sB2;
    const long long coff = zb * sC1 + zh * sC2;
    if (PAIROUT) { Ch += coff; Cl += coff; }
    else         { C += coff; if (resid) resid += coff; }

    int Keff = K;
    if (KCLIP && m0 + AR < K) Keff = m0 + AR;
    const int nst = (Keff + 31) >> 5;

    auto fill = [&](int s) {
        const uint32_t sb = smb + (uint32_t)((s & 1) * STG);
        const int kbase = s << 5;
#pragma unroll
        for (int i = tid; i < AR * 4; i += BD) {
            const int row = i >> 2, c = i & 3;
            const int col = kbase + (c << 3);
            const int sz  = (col < Keff) ? 16 : 0;
            const long long go = (long long)(m0 + row) * lda + col;
            const uint32_t d = sb + row * 80 + c * 16;
            cp16(d + A_HI, Ah + (sz ? go : 0), sz);
            cp16(d + A_LO, Al + (sz ? go : 0), sz);
        }
#pragma unroll
        for (int i = tid; i < BR * 4; i += BD) {
            const int row = i >> 2, c = i & 3;
            const int col = kbase + (c << 3);
            const int sz  = (col < Keff && (n0 + row) < N) ? 16 : 0;
            const long long go = (long long)(n0 + row) * ldb + col;
            cp16(sb + row * 80 + c * 16 + B_HI, Bh + (sz ? go : 0), sz);
        }
    };

    float acc[4][8][4] = {};

    fill(0);
    CP_COMMIT();

    const int lrow = lane & 15;
    const int lcol = (lane >> 4) << 3;

    for (int s = 0; s < nst; s++) {
        CP_WAIT0();
        __syncthreads();
        if (s + 1 < nst) { fill(s + 1); CP_COMMIT(); }

        const uint32_t sb = smb + (uint32_t)((s & 1) * STG);
#pragma unroll
        for (int ks = 0; ks < 2; ks++) {
            const int kk = ks << 4;
            uint32_t ahi[4][4], alo[4][4];
#pragma unroll
            for (int mf = 0; mf < 4; mf++) {
                uint32_t ra = sb + (uint32_t)((wm * 64 + mf * 16 + lrow) * 80
                                              + (kk + lcol) * 2);
                ldsm_x4(ahi[mf][0], ahi[mf][1], ahi[mf][2], ahi[mf][3], ra + A_HI);
                ldsm_x4(alo[mf][0], alo[mf][1], alo[mf][2], alo[mf][3], ra + A_LO);
            }
#pragma unroll
            for (int nfp = 0; nfp < 4; nfp++) {
                uint32_t rb = sb + (uint32_t)((wn * 64 + nfp * 16 + lrow) * 80
                                              + (kk + lcol) * 2);
                uint32_t bh[4];
                ldsm_x4(bh[0], bh[1], bh[2], bh[3], rb + B_HI);
                // term-outer: same-acc reuse distance = 8 mma
#pragma unroll
                for (int mf = 0; mf < 4; mf++) {
                    mma_f16(acc[mf][2 * nfp],     ahi[mf], bh[0], bh[2]);
                    mma_f16(acc[mf][2 * nfp + 1], ahi[mf], bh[1], bh[3]);
                }
#pragma unroll
                for (int mf = 0; mf < 4; mf++) {
                    mma_f16(acc[mf][2 * nfp],     alo[mf], bh[0], bh[2]);
                    mma_f16(acc[mf][2 * nfp + 1], alo[mf], bh[1], bh[3]);
                }
            }
        }
    }

    // ---- epilogue ----
    const int g = lane >> 2;
    const int t = lane & 3;
#pragma unroll
    for (int mf = 0; mf < 4; mf++) {
        const int gm0 = m0 + wm * 64 + mf * 16 + g;
        const int gm1 = gm0 + 8;
        const long long ro0 = (long long)gm0 * ldc;
        const long long ro1 = (long long)gm1 * ldc;
#pragma unroll
        for (int nf = 0; nf < 8; nf++) {
            const int gn = n0 + wn * 64 + nf * 8 + t * 2;
            if (gn < N) {
                float c0 = acc[mf][nf][0] * alpha;
                float c1 = acc[mf][nf][1] * alpha;
                float c2 = acc[mf][nf][2] * alpha;
                float c3 = acc[mf][nf][3] * alpha;
                if (bias) {
                    float b0 = bias[gn], b1 = bias[gn + 1];
                    c0 += b0; c1 += b1; c2 += b0; c3 += b1;
                }
                if (MASK) {
                    if (gn > gm0)     c0 += -10000.0f;
                    if (gn + 1 > gm0) c1 += -10000.0f;
                    if (gn > gm1)     c2 += -10000.0f;
                    if (gn + 1 > gm1) c3 += -10000.0f;
                }
                if (RELU) {
                    c0 = fmaxf(c0, 0.0f); c1 = fmaxf(c1, 0.0f);
                    c2 = fmaxf(c2, 0.0f); c3 = fmaxf(c3, 0.0f);
                }
                if (!PAIROUT) {
                    if (resid) {
                        c0 += resid[ro0 + gn]; c1 += resid[ro0 + gn + 1];
                        c2 += resid[ro1 + gn]; c3 += resid[ro1 + gn + 1];
                    }
                    *(float2*)(C + ro0 + gn) = make_float2(c0, c1);
                    *(float2*)(C + ro1 + gn) = make_float2(c2, c3);
                } else {
                    float h0 = __half2float(__float2half_rn(c0));
                    float h1 = __half2float(__float2half_rn(c1));
                    float h2 = __half2float(__float2half_rn(c2));
                    float h3 = __half2float(__float2half_rn(c3));
                    *(uint32_t*)(Ch + ro0 + gn) = pk2h(c0, c1);
                    *(uint32_t*)(Ch + ro1 + gn) = pk2h(c2, c3);
                    *(uint32_t*)(Cl + ro0 + gn) = pk2h(c0 - h0, c1 - h1);
                    *(uint32_t*)(Cl + ro1 + gn) = pk2h(c2 - h2, c3 - h3);
                }
            }
        }
    }
}

// dynamic smem: 2 pipeline buffers of STG bytes each
#define SM22 (2 * (2 * 128 + 128) * 80)   // 61440
#define SM12 (2 * (2 * 64 + 128) * 80)    // 40960

// ---------------------------------------------------------------------------
// Host launcher (graph-capturable: kernel launches only)
// ---------------------------------------------------------------------------
extern "C" void kernel_launch(void* const* d_in, const int* in_sizes, int n_in,
                              void* d_out, int out_size) {
    const unsigned int* idw = (const unsigned int*)d_in[0];
    const float* emb  = (const float*)d_in[1];
    const float* Wq   = (const float*)d_in[2];
    const float* Wk   = (const float*)d_in[3];
    const float* Wv   = (const float*)d_in[4];
    const float* Wo   = (const float*)d_in[5];
    const float* pbq  = (const float*)d_in[6];
    const float* pbk  = (const float*)d_in[7];
    const float* pbv  = (const float*)d_in[8];
    const float* pbo  = (const float*)d_in[9];
    const float* W1   = (const float*)d_in[10];
    const float* pb1  = (const float*)d_in[11];
    const float* W2   = (const float*)d_in[12];
    const float* pb2  = (const float*)d_in[13];
    const float* ln1g = (const float*)d_in[14];
    const float* ln1b = (const float*)d_in[15];
    const float* ln2g = (const float*)d_in[16];
    const float* ln2b = (const float*)d_in[17];
    const float* lnfg = (const float*)d_in[18];
    const float* lnfb = (const float*)d_in[19];

    float *px, *ps, *pbqkv;
    hf *nh, *nl, *qkvh, *qkvl, *vth, *ch, *cl, *ph, *pl, *h1h, *h1l;
    hf *wqkvh, *woh, *w1h, *w2h;
    cudaGetSymbolAddress((void**)&px,    g_x);
    cudaGetSymbolAddress((void**)&ps,    g_scores);
    cudaGetSymbolAddress((void**)&pbqkv, g_bqkv);
    cudaGetSymbolAddress((void**)&nh,    g_nh);    cudaGetSymbolAddress((void**)&nl,    g_nl);
    cudaGetSymbolAddress((void**)&qkvh,  g_qkvh);  cudaGetSymbolAddress((void**)&qkvl,  g_qkvl);
    cudaGetSymbolAddress((void**)&vth,   g_vth);
    cudaGetSymbolAddress((void**)&ch,    g_ch);    cudaGetSymbolAddress((void**)&cl,    g_cl);
    cudaGetSymbolAddress((void**)&ph,    g_ph);    cudaGetSymbolAddress((void**)&pl,    g_pl);
    cudaGetSymbolAddress((void**)&h1h,   g_h1h);   cudaGetSymbolAddress((void**)&h1l,   g_h1l);
    cudaGetSymbolAddress((void**)&wqkvh, g_wqkvh);
    cudaGetSymbolAddress((void**)&woh,   g_woh);
    cudaGetSymbolAddress((void**)&w1h,   g_w1h);
    cudaGetSymbolAddress((void**)&w2h,   g_w2h);

    cudaFuncSetAttribute(gemm2<2, 2, false, false, true,  false>,
                         cudaFuncAttributeMaxDynamicSharedMemorySize, SM22);
    cudaFuncSetAttribute(gemm2<2, 2, true,  false, false, false>,
                         cudaFuncAttributeMaxDynamicSharedMemorySize, SM22);
    cudaFuncSetAttribute(gemm2<2, 2, false, true,  true,  false>,
                         cudaFuncAttributeMaxDynamicSharedMemorySize, SM22);
    cudaFuncSetAttribute(gemm2<2, 2, false, false, true,  true>,
                         cudaFuncAttributeMaxDynamicSharedMemorySize, SM22);
    cudaFuncSetAttribute(gemm2<1, 2, false, false, false, false>,
                         cudaFuncAttributeMaxDynamicSharedMemorySize, SM12);

    detect_kernel<<<1, 256>>>(idw);
    embed_kernel<<<(MM * DD + 255) / 256, 256>>>(idw, emb, px);

    {
        dim3 blk(32, 8);
        const size_t oQKV = (size_t)3 * DD * DD;
        wtrans_kernel<<<dim3(DD / 32, DD / 32, LL), blk>>>(Wq, wqkvh, DD, DD, oQKV);
        wtrans_kernel<<<dim3(DD / 32, DD / 32, LL), blk>>>(
            Wk, wqkvh + (size_t)DD * DD, DD, DD, oQKV);
        wtrans_kernel<<<dim3(DD / 32, DD / 32, LL), blk>>>(
            Wv, wqkvh + (size_t)2 * DD * DD, DD, DD, oQKV);
        wtrans_kernel<<<dim3(DD / 32, DD / 32, LL), blk>>>(Wo, woh, DD, DD,
                                                           (size_t)DD * DD);
        wtrans_kernel<<<dim3(DFF / 32, DD / 32, LL), blk>>>(W1, w1h, DD, DFF,
                                                            (size_t)DD * DFF);
        wtrans_kernel<<<dim3(DD / 32, DFF / 32, LL), blk>>>(W2, w2h, DFF, DD,
                                                            (size_t)DFF * DD);
        packb_kernel<<<(LL * 3 * DD + 255) / 256, 256>>>(pbq, pbk, pbv, pbqkv);
    }

    const long long sSD  = (long long)SS * DD;
    const long long sHSS = (long long)HH * SS * SS;
    const long long sSSq = (long long)SS * SS;
    const int D3 = 3 * DD;                       // 3840

    const dim3 gQKV(D3 / 128, MM / 128);         // 480
    const dim3 gN64(DD / 128, MM / 64);          // 320
    const dim3 gFF1(DFF / 128, MM / 128);        // 1024
    const dim3 gScore(SS / 128, SS / 128, BB * HH);
    const dim3 gCtx(1, SS / 128, BB * HH);

    for (int l = 0; l < LL; l++) {
        const size_t woff4 = (size_t)l * DD * DD;
        const size_t woffQ = (size_t)l * 3 * DD * DD;
        const size_t woff1 = (size_t)l * DD * DFF;

        layernorm_kernel<true><<<MM, 256>>>(px, nullptr, nh, nl,
                                            ln1g + l * DD, ln1b + l * DD);

        // fused qkv projection -> packed [MM, 3840] fp16 pairs
        gemm2<2, 2, false, false, true, false><<<gQKV, 128, SM22>>>(
            nh, nl, wqkvh + woffQ, nullptr, qkvh, qkvl,
            pbqkv + l * D3, nullptr,
            MM, D3, DD, DD, DD, D3, 0, 0, 0, 0, 0, 0, 1.0f);

        vtrans_kernel<<<dim3(DD / 32, MM / 32), dim3(32, 8)>>>(
            qkvh + 2 * DD, vth, D3);

        // scores = q @ k^T * 1/sqrt(80) + causal mask -> fp32
        gemm2<2, 2, true, false, false, false><<<gScore, 128, SM22>>>(
            qkvh, qkvl, qkvh + DD, ps, nullptr, nullptr,
            nullptr, nullptr,
            SS, SS, DHH, D3, D3, SS,
            (long long)SS * D3, (long long)DHH,
            (long long)SS * D3, (long long)DHH, sHSS, sSSq,
            0.11180339887498949f);

        softmax_kernel<<<BB * HH * SS, 256>>>(ps, ph, pl);

        // ctx = probs @ vT (K clipped causally) -> fp16 pairs at [B,S,D]
        gemm2<2, 2, false, false, true, true><<<gCtx, 128, SM22>>>(
            ph, pl, vth, nullptr, ch, cl, nullptr, nullptr,
            SS, DHH, SS, SS, MM, DD,
            sHSS, sSSq, (long long)SS, (long long)DHH * MM, sSD, (long long)DHH,
            1.0f);

        // x = x + ctx @ Wo + bo
        gemm2<1, 2, false, false, false, false><<<gN64, 64, SM12>>>(
            ch, cl, woh + woff4, px, nullptr, nullptr,
            pbo + l * DD, px,
            MM, DD, DD, DD, DD, DD, 0, 0, 0, 0, 0, 0, 1.0f);

        layernorm_kernel<true><<<MM, 256>>>(px, nullptr, nh, nl,
                                            ln2g + l * DD, ln2b + l * DD);

        // h1 = relu(n @ W1 + b1)
        gemm2<2, 2, false, true, true, false><<<gFF1, 128, SM22>>>(
            nh, nl, w1h + woff1, nullptr, h1h, h1l,
            pb1 + l * DFF, nullptr,
            MM, DFF, DD, DD, DD, DFF, 0, 0, 0, 0, 0, 0, 1.0f);

        // x = x + h1 @ W2 + b2
        gemm2<1, 2, false, false, false, false><<<gN64, 64, SM12>>>(
            h1h, h1l, w2h + woff1, px, nullptr, nullptr,
            pb2 + l * DD, px,
            MM, DD, DFF, DFF, DFF, DD, 0, 0, 0, 0, 0, 0, 1.0f);
    }

    layernorm_kernel<false><<<MM, 256>>>(px, (float*)d_out, nullptr, nullptr,
                                         lnfg, lnfb);
}

// round 9
// speedup vs baseline: 6.1803x; 1.6724x over previous
#include <cuda_runtime.h>
#include <cuda_fp16.h>
#include <cstdint>

// ---------------------------------------------------------------------------
// CTRL transformer forward, GB300 (compute_103 -> mma.sync path).
// Round 9: pure 1-term fp16 GEMM (both operands rounded to fp16, fp32
// accumulate) -> half the tensor work of round 8. Predicted rel_err ~5e-4
// vs 1e-3 threshold. All lo-buffers removed.
// ---------------------------------------------------------------------------

#define BB   2
#define SS   1024
#define DD   1280
#define HH   16
#define DHH  80
#define DFF  8192
#define LL   4
#define MM   (BB * SS)

typedef __half hf;

// fp32 scratch
__device__ float g_x[MM * DD];
__device__ float g_scores[(size_t)BB * HH * SS * SS];      // 128 MB
__device__ float g_bqkv[LL * 3 * DD];                      // packed qkv bias
// fp16 activations
__device__ hf g_n[MM * DD];
__device__ hf g_qkv[(size_t)MM * 3 * DD];
__device__ hf g_vt[(size_t)DD * MM];                       // v transposed
__device__ hf g_c[MM * DD];
__device__ hf g_p[(size_t)BB * HH * SS * SS];
__device__ hf g_h1[(size_t)MM * DFF];
// fp16 weights [N,K]
__device__ hf g_wqkv[(size_t)LL * 3 * DD * DD];
__device__ hf g_wo[LL * DD * DD];
__device__ hf g_w1[(size_t)LL * DD * DFF];
__device__ hf g_w2[(size_t)LL * DFF * DD];
__device__ int g_ids64;

// ---------------------------------------------------------------------------
__device__ __forceinline__ uint32_t smem_u32(const void* p) {
    uint32_t a;
    asm("{ .reg .u64 t; cvta.to.shared.u64 t, %1; cvt.u32.u64 %0, t; }"
        : "=r"(a) : "l"(p));
    return a;
}

__device__ __forceinline__ void ldsm_x4(uint32_t& r0, uint32_t& r1,
                                        uint32_t& r2, uint32_t& r3,
                                        uint32_t addr) {
    asm volatile("ldmatrix.sync.aligned.m8n8.x4.shared.b16 {%0,%1,%2,%3}, [%4];"
                 : "=r"(r0), "=r"(r1), "=r"(r2), "=r"(r3) : "r"(addr));
}

__device__ __forceinline__ void mma_f16(float* d, const uint32_t* a,
                                        uint32_t b0, uint32_t b1) {
    asm volatile(
        "mma.sync.aligned.m16n8k16.row.col.f32.f16.f16.f32 "
        "{%0,%1,%2,%3},{%4,%5,%6,%7},{%8,%9},{%0,%1,%2,%3};"
        : "+f"(d[0]), "+f"(d[1]), "+f"(d[2]), "+f"(d[3])
        : "r"(a[0]), "r"(a[1]), "r"(a[2]), "r"(a[3]), "r"(b0), "r"(b1));
}

__device__ __forceinline__ void cp16(uint32_t dst, const void* src, int sz) {
    asm volatile("cp.async.cg.shared.global [%0], [%1], 16, %2;"
                 :: "r"(dst), "l"(src), "r"(sz) : "memory");
}
#define CP_COMMIT() asm volatile("cp.async.commit_group;" ::: "memory")
#define CP_WAIT0()  asm volatile("cp.async.wait_group 0;" ::: "memory")

__device__ __forceinline__ uint32_t pk2h(float a, float b) {
    __half2 h = __floats2half2_rn(a, b);
    return *reinterpret_cast<uint32_t*>(&h);
}

// ---------------------------------------------------------------------------
// detect + embed
// ---------------------------------------------------------------------------
__global__ void detect_kernel(const unsigned int* __restrict__ w) {
    __shared__ int any;
    if (threadIdx.x == 0) any = 0;
    __syncthreads();
    int loc = 0;
    for (int i = 2 * threadIdx.x + 1; i < 2048; i += 512)
        loc |= (w[i] != 0u);
    if (loc) atomicOr(&any, 1);
    __syncthreads();
    if (threadIdx.x == 0) g_ids64 = any ? 0 : 1;
}

__global__ void embed_kernel(const unsigned int* __restrict__ idw,
                             const float* __restrict__ emb,
                             float* __restrict__ x) {
    int idx = blockIdx.x * 256 + threadIdx.x;
    if (idx >= MM * DD) return;
    int d   = idx % DD;
    int row = idx / DD;
    int s   = row & (SS - 1);
    int id  = g_ids64 ? (int)idw[2 * row] : (int)idw[row];
    float val = emb[(long long)id * DD + d] * 35.77708763999664f;
    int m = (d < 640) ? d : d - 640;
    float rate = expf(-0.014391156831212787f * (float)m);
    float ang  = (float)s * rate;
    val += (d < 640) ? sinf(ang) : cosf(ang);
    x[idx] = val;
}

// ---------------------------------------------------------------------------
// weight convert+transpose: fp32 [K,N] -> fp16 [N,K]; z = layer
// ---------------------------------------------------------------------------
__global__ void wtrans_kernel(const float* __restrict__ W,
                              hf* __restrict__ oh,
                              int K, int N, size_t ostride) {
    W  += (size_t)blockIdx.z * K * N;
    oh += (size_t)blockIdx.z * ostride;
    __shared__ float tf[32][33];
    const int n0 = blockIdx.x * 32, k0 = blockIdx.y * 32;
    const int tx = threadIdx.x, ty = threadIdx.y;
#pragma unroll
    for (int i = 0; i < 4; i++)
        tf[ty + 8 * i][tx] = W[(long long)(k0 + ty + 8 * i) * N + n0 + tx];
    __syncthreads();
#pragma unroll
    for (int i = 0; i < 4; i++) {
        long long o = (long long)(n0 + ty + 8 * i) * K + k0 + tx;
        oh[o] = __float2half_rn(tf[tx][ty + 8 * i]);
    }
}

// pack qkv bias: [L][3840] from bq,bk,bv
__global__ void packb_kernel(const float* __restrict__ bq,
                             const float* __restrict__ bk,
                             const float* __restrict__ bv,
                             float* __restrict__ o) {
    int i = blockIdx.x * 256 + threadIdx.x;
    if (i >= LL * 3 * DD) return;
    int l = i / (3 * DD), j = i % (3 * DD);
    float v = (j < DD) ? bq[l * DD + j]
            : (j < 2 * DD) ? bk[l * DD + j - DD]
            : bv[l * DD + j - 2 * DD];
    o[i] = v;
}

// v transpose from packed qkv (row stride 3840): [MM,DD] -> [DD,MM]
__global__ void vtrans_kernel(const hf* __restrict__ ih,
                              hf* __restrict__ oh, int istride) {
    __shared__ hf th[32][34];
    const int n0 = blockIdx.x * 32, m0 = blockIdx.y * 32;
    const int tx = threadIdx.x, ty = threadIdx.y;
#pragma unroll
    for (int i = 0; i < 4; i++)
        th[ty + 8 * i][tx] = ih[(long long)(m0 + ty + 8 * i) * istride + n0 + tx];
    __syncthreads();
#pragma unroll
    for (int i = 0; i < 4; i++)
        oh[(long long)(n0 + ty + 8 * i) * MM + m0 + tx] = th[tx][ty + 8 * i];
}

// ---------------------------------------------------------------------------
// LayerNorm / softmax
// ---------------------------------------------------------------------------
__device__ __forceinline__ float warp_sum(float v) {
#pragma unroll
    for (int o = 16; o; o >>= 1) v += __shfl_xor_sync(0xffffffffu, v, o);
    return v;
}

template <bool HOUT>
__global__ void layernorm_kernel(const float* __restrict__ x,
                                 float* __restrict__ o,
                                 hf* __restrict__ oh,
                                 const float* __restrict__ g,
                                 const float* __restrict__ b) {
    const int row = blockIdx.x;
    const int t   = threadIdx.x;
    const float* xr = x + (long long)row * DD;
    __shared__ float red[8];
    float v[5];
    float s = 0.0f;
#pragma unroll
    for (int i = 0; i < 5; i++) { v[i] = xr[t + 256 * i]; s += v[i]; }
    s = warp_sum(s);
    if ((t & 31) == 0) red[t >> 5] = s;
    __syncthreads();
    float mu = (red[0] + red[1] + red[2] + red[3] +
                red[4] + red[5] + red[6] + red[7]) * (1.0f / 1280.0f);
    __syncthreads();
    float q = 0.0f;
#pragma unroll
    for (int i = 0; i < 5; i++) { float dv = v[i] - mu; q += dv * dv; }
    q = warp_sum(q);
    if ((t & 31) == 0) red[t >> 5] = q;
    __syncthreads();
    float var = (red[0] + red[1] + red[2] + red[3] +
                 red[4] + red[5] + red[6] + red[7]) * (1.0f / 1280.0f);
    float rstd = rsqrtf(var + 1e-6f);
    const long long ro = (long long)row * DD;
#pragma unroll
    for (int i = 0; i < 5; i++) {
        int c = t + 256 * i;
        float y = (v[i] - mu) * rstd * g[c] + b[c];
        if (HOUT) oh[ro + c] = __float2half_rn(y);
        else      o[ro + c]  = y;
    }
}

// causal softmax: k > q masked (prob exactly 0; matches ref since
// exp(-10000 + O(60)) underflows to 0 in fp32). Skipped score tiles never read.
__global__ void softmax_kernel(const float* __restrict__ sc,
                               hf* __restrict__ ph) {
    const long long row = blockIdx.x;
    const int q = (int)(row & (SS - 1));
    const float* p = sc + row * (long long)SS;
    const int t = threadIdx.x;
    __shared__ float red[8];
    float v[4];
    float mx = -3.4e38f;
#pragma unroll
    for (int i = 0; i < 4; i++) {
        int k = t + 256 * i;
        v[i] = (k <= q) ? p[k] : -3.4e38f;
        mx = fmaxf(mx, v[i]);
    }
#pragma unroll
    for (int o = 16; o; o >>= 1) mx = fmaxf(mx, __shfl_xor_sync(0xffffffffu, mx, o));
    if ((t & 31) == 0) red[t >> 5] = mx;
    __syncthreads();
    mx = fmaxf(fmaxf(fmaxf(red[0], red[1]), fmaxf(red[2], red[3])),
               fmaxf(fmaxf(red[4], red[5]), fmaxf(red[6], red[7])));
    __syncthreads();
    float s = 0.0f;
#pragma unroll
    for (int i = 0; i < 4; i++) {
        int k = t + 256 * i;
        v[i] = (k <= q) ? expf(v[i] - mx) : 0.0f;
        s += v[i];
    }
    s = warp_sum(s);
    if ((t & 31) == 0) red[t >> 5] = s;
    __syncthreads();
    s = red[0] + red[1] + red[2] + red[3] + red[4] + red[5] + red[6] + red[7];
    float inv = 1.0f / s;
#pragma unroll
    for (int i = 0; i < 4; i++)
        ph[row * SS + t + 256 * i] = __float2half_rn(v[i] * inv);
}

// ---------------------------------------------------------------------------
// fp16 GEMM: C = alpha * A @ B^T [+bias][+mask][relu][+resid]
//   A [M,K] (lda), B [N,K] (ldb), fp16; fp32 accumulate.
//   fp32 out or fp16 out. Warp tile 64x64; CTA tile (64MW)x(64NW);
//   batched via blockIdx.z -> (z>>4, z&15).
//   MASK skips fully-masked tiles; KCLIP clips causal-zero K range.
// ---------------------------------------------------------------------------
template <int MW, int NW, bool MASK, bool RELU, bool HOUT, bool KCLIP>
__global__ void __launch_bounds__(MW * NW * 32)
gemm1(const hf* __restrict__ A, const hf* __restrict__ B,
      float* __restrict__ C, hf* __restrict__ Ch,
      const float* __restrict__ bias, const float* __restrict__ resid,
      int M, int N, int K, int lda, int ldb, int ldc,
      long long sA1, long long sA2, long long sB1, long long sB2,
      long long sC1, long long sC2, float alpha) {
    constexpr int AR  = 64 * MW;
    constexpr int BR  = 64 * NW;
    constexpr int BD  = MW * NW * 32;
    constexpr int A_OF = 0;
    constexpr int B_OF = AR * 80;
    constexpr int STG  = (AR + BR) * 80;

    const int m0 = blockIdx.y * AR;
    const int n0 = blockIdx.x * BR;
    if (MASK && n0 > m0 + (AR - 1)) return;

    extern __shared__ char sm[];
    const uint32_t smb = smem_u32(sm);

    const int tid  = threadIdx.x;
    const int wid  = tid >> 5;
    const int lane = tid & 31;
    const int wm   = wid / NW;
    const int wn   = wid % NW;

    const int z = blockIdx.z, zb = z >> 4, zh = z & 15;
    A += zb * sA1 + zh * sA2;
    B += zb * sB1 + zh * sB2;
    const long long coff = zb * sC1 + zh * sC2;
    if (HOUT) Ch += coff;
    else      { C += coff; if (resid) resid += coff; }

    int Keff = K;
    if (KCLIP && m0 + AR < K) Keff = m0 + AR;
    const int nst = (Keff + 31) >> 5;

    auto fill = [&](int s) {
        const uint32_t sb = smb + (uint32_t)((s & 1) * STG);
        const int kbase = s << 5;
#pragma unroll
        for (int i = tid; i < AR * 4; i += BD) {
            const int row = i >> 2, c = i & 3;
            const int col = kbase + (c << 3);
            const int sz  = (col < Keff) ? 16 : 0;
            const long long go = (long long)(m0 + row) * lda + col;
            cp16(sb + row * 80 + c * 16 + A_OF, A + (sz ? go : 0), sz);
        }
#pragma unroll
        for (int i = tid; i < BR * 4; i += BD) {
            const int row = i >> 2, c = i & 3;
            const int col = kbase + (c << 3);
            const int sz  = (col < Keff && (n0 + row) < N) ? 16 : 0;
            const long long go = (long long)(n0 + row) * ldb + col;
            cp16(sb + row * 80 + c * 16 + B_OF, B + (sz ? go : 0), sz);
        }
    };

    float acc[4][8][4] = {};

    fill(0);
    CP_COMMIT();

    const int lrow = lane & 15;
    const int lcol = (lane >> 4) << 3;

    for (int s = 0; s < nst; s++) {
        CP_WAIT0();
        __syncthreads();
        if (s + 1 < nst) { fill(s + 1); CP_COMMIT(); }

        const uint32_t sb = smb + (uint32_t)((s & 1) * STG);
#pragma unroll
        for (int ks = 0; ks < 2; ks++) {
            const int kk = ks << 4;
            uint32_t af[4][4];
#pragma unroll
            for (int mf = 0; mf < 4; mf++) {
                uint32_t ra = sb + (uint32_t)((wm * 64 + mf * 16 + lrow) * 80
                                              + (kk + lcol) * 2);
                ldsm_x4(af[mf][0], af[mf][1], af[mf][2], af[mf][3], ra + A_OF);
            }
#pragma unroll
            for (int nfp = 0; nfp < 4; nfp++) {
                uint32_t rb = sb + (uint32_t)((wn * 64 + nfp * 16 + lrow) * 80
                                              + (kk + lcol) * 2);
                uint32_t bh[4];
                ldsm_x4(bh[0], bh[1], bh[2], bh[3], rb + B_OF);
#pragma unroll
                for (int mf = 0; mf < 4; mf++) {
                    mma_f16(acc[mf][2 * nfp],     af[mf], bh[0], bh[2]);
                    mma_f16(acc[mf][2 * nfp + 1], af[mf], bh[1], bh[3]);
                }
            }
        }
    }

    // ---- epilogue ----
    const int g = lane >> 2;
    const int t = lane & 3;
#pragma unroll
    for (int mf = 0; mf < 4; mf++) {
        const int gm0 = m0 + wm * 64 + mf * 16 + g;
        const int gm1 = gm0 + 8;
        const long long ro0 = (long long)gm0 * ldc;
        const long long ro1 = (long long)gm1 * ldc;
#pragma unroll
        for (int nf = 0; nf < 8; nf++) {
            const int gn = n0 + wn * 64 + nf * 8 + t * 2;
            if (gn < N) {
                float c0 = acc[mf][nf][0] * alpha;
                float c1 = acc[mf][nf][1] * alpha;
                float c2 = acc[mf][nf][2] * alpha;
                float c3 = acc[mf][nf][3] * alpha;
                if (bias) {
                    float b0 = bias[gn], b1 = bias[gn + 1];
                    c0 += b0; c1 += b1; c2 += b0; c3 += b1;
                }
                if (MASK) {
                    if (gn > gm0)     c0 += -10000.0f;
                    if (gn + 1 > gm0) c1 += -10000.0f;
                    if (gn > gm1)     c2 += -10000.0f;
                    if (gn + 1 > gm1) c3 += -10000.0f;
                }
                if (RELU) {
                    c0 = fmaxf(c0, 0.0f); c1 = fmaxf(c1, 0.0f);
                    c2 = fmaxf(c2, 0.0f); c3 = fmaxf(c3, 0.0f);
                }
                if (!HOUT) {
                    if (resid) {
                        c0 += resid[ro0 + gn]; c1 += resid[ro0 + gn + 1];
                        c2 += resid[ro1 + gn]; c3 += resid[ro1 + gn + 1];
                    }
                    *(float2*)(C + ro0 + gn) = make_float2(c0, c1);
                    *(float2*)(C + ro1 + gn) = make_float2(c2, c3);
                } else {
                    *(uint32_t*)(Ch + ro0 + gn) = pk2h(c0, c1);
                    *(uint32_t*)(Ch + ro1 + gn) = pk2h(c2, c3);
                }
            }
        }
    }
}

// dynamic smem: 2 pipeline buffers of STG bytes each
#define SM22 (2 * (128 + 128) * 80)   // 40960
#define SM12 (2 * (64 + 128) * 80)    // 30720

// ---------------------------------------------------------------------------
// Host launcher (graph-capturable: kernel launches only)
// ---------------------------------------------------------------------------
extern "C" void kernel_launch(void* const* d_in, const int* in_sizes, int n_in,
                              void* d_out, int out_size) {
    const unsigned int* idw = (const unsigned int*)d_in[0];
    const float* emb  = (const float*)d_in[1];
    const float* Wq   = (const float*)d_in[2];
    const float* Wk   = (const float*)d_in[3];
    const float* Wv   = (const float*)d_in[4];
    const float* Wo   = (const float*)d_in[5];
    const float* pbq  = (const float*)d_in[6];
    const float* pbk  = (const float*)d_in[7];
    const float* pbv  = (const float*)d_in[8];
    const float* pbo  = (const float*)d_in[9];
    const float* W1   = (const float*)d_in[10];
    const float* pb1  = (const float*)d_in[11];
    const float* W2   = (const float*)d_in[12];
    const float* pb2  = (const float*)d_in[13];
    const float* ln1g = (const float*)d_in[14];
    const float* ln1b = (const float*)d_in[15];
    const float* ln2g = (const float*)d_in[16];
    const float* ln2b = (const float*)d_in[17];
    const float* lnfg = (const float*)d_in[18];
    const float* lnfb = (const float*)d_in[19];

    float *px, *ps, *pbqkv;
    hf *pn, *pqkv, *pvt, *pc, *pp, *ph1;
    hf *pwqkv, *pwo, *pw1, *pw2;
    cudaGetSymbolAddress((void**)&px,    g_x);
    cudaGetSymbolAddress((void**)&ps,    g_scores);
    cudaGetSymbolAddress((void**)&pbqkv, g_bqkv);
    cudaGetSymbolAddress((void**)&pn,    g_n);
    cudaGetSymbolAddress((void**)&pqkv,  g_qkv);
    cudaGetSymbolAddress((void**)&pvt,   g_vt);
    cudaGetSymbolAddress((void**)&pc,    g_c);
    cudaGetSymbolAddress((void**)&pp,    g_p);
    cudaGetSymbolAddress((void**)&ph1,   g_h1);
    cudaGetSymbolAddress((void**)&pwqkv, g_wqkv);
    cudaGetSymbolAddress((void**)&pwo,   g_wo);
    cudaGetSymbolAddress((void**)&pw1,   g_w1);
    cudaGetSymbolAddress((void**)&pw2,   g_w2);

    cudaFuncSetAttribute(gemm1<2, 2, false, false, true,  false>,
                         cudaFuncAttributeMaxDynamicSharedMemorySize, SM22);
    cudaFuncSetAttribute(gemm1<2, 2, true,  false, false, false>,
                         cudaFuncAttributeMaxDynamicSharedMemorySize, SM22);
    cudaFuncSetAttribute(gemm1<2, 2, false, true,  true,  false>,
                         cudaFuncAttributeMaxDynamicSharedMemorySize, SM22);
    cudaFuncSetAttribute(gemm1<2, 2, false, false, true,  true>,
                         cudaFuncAttributeMaxDynamicSharedMemorySize, SM22);
    cudaFuncSetAttribute(gemm1<1, 2, false, false, false, false>,
                         cudaFuncAttributeMaxDynamicSharedMemorySize, SM12);

    detect_kernel<<<1, 256>>>(idw);
    embed_kernel<<<(MM * DD + 255) / 256, 256>>>(idw, emb, px);

    {
        dim3 blk(32, 8);
        const size_t oQKV = (size_t)3 * DD * DD;
        wtrans_kernel<<<dim3(DD / 32, DD / 32, LL), blk>>>(Wq, pwqkv, DD, DD, oQKV);
        wtrans_kernel<<<dim3(DD / 32, DD / 32, LL), blk>>>(
            Wk, pwqkv + (size_t)DD * DD, DD, DD, oQKV);
        wtrans_kernel<<<dim3(DD / 32, DD / 32, LL), blk>>>(
            Wv, pwqkv + (size_t)2 * DD * DD, DD, DD, oQKV);
        wtrans_kernel<<<dim3(DD / 32, DD / 32, LL), blk>>>(Wo, pwo, DD, DD,
                                                           (size_t)DD * DD);
        wtrans_kernel<<<dim3(DFF / 32, DD / 32, LL), blk>>>(W1, pw1, DD, DFF,
                                                            (size_t)DD * DFF);
        wtrans_kernel<<<dim3(DD / 32, DFF / 32, LL), blk>>>(W2, pw2, DFF, DD,
                                                            (size_t)DFF * DD);
        packb_kernel<<<(LL * 3 * DD + 255) / 256, 256>>>(pbq, pbk, pbv, pbqkv);
    }

    const long long sSD  = (long long)SS * DD;
    const long long sHSS = (long long)HH * SS * SS;
    const long long sSSq = (long long)SS * SS;
    const int D3 = 3 * DD;                       // 3840

    const dim3 gQKV(D3 / 128, MM / 128);         // 480
    const dim3 gN64(DD / 128, MM / 64);          // 320
    const dim3 gFF1(DFF / 128, MM / 128);        // 1024
    const dim3 gScore(SS / 128, SS / 128, BB * HH);
    const dim3 gCtx(1, SS / 128, BB * HH);

    for (int l = 0; l < LL; l++) {
        const size_t woff4 = (size_t)l * DD * DD;
        const size_t woffQ = (size_t)l * 3 * DD * DD;
        const size_t woff1 = (size_t)l * DD * DFF;

        layernorm_kernel<true><<<MM, 256>>>(px, nullptr, pn,
                                            ln1g + l * DD, ln1b + l * DD);

        // fused qkv projection -> packed [MM, 3840] fp16
        gemm1<2, 2, false, false, true, false><<<gQKV, 128, SM22>>>(
            pn, pwqkv + woffQ, nullptr, pqkv,
            pbqkv + l * D3, nullptr,
            MM, D3, DD, DD, DD, D3, 0, 0, 0, 0, 0, 0, 1.0f);

        vtrans_kernel<<<dim3(DD / 32, MM / 32), dim3(32, 8)>>>(
            pqkv + 2 * DD, pvt, D3);

        // scores = q @ k^T * 1/sqrt(80) + causal mask -> fp32
        gemm1<2, 2, true, false, false, false><<<gScore, 128, SM22>>>(
            pqkv, pqkv + DD, ps, nullptr,
            nullptr, nullptr,
            SS, SS, DHH, D3, D3, SS,
            (long long)SS * D3, (long long)DHH,
            (long long)SS * D3, (long long)DHH, sHSS, sSSq,
            0.11180339887498949f);

        softmax_kernel<<<BB * HH * SS, 256>>>(ps, pp);

        // ctx = probs @ vT (K clipped causally) -> fp16 at [B,S,D]
        gemm1<2, 2, false, false, true, true><<<gCtx, 128, SM22>>>(
            pp, pvt, nullptr, pc, nullptr, nullptr,
            SS, DHH, SS, SS, MM, DD,
            sHSS, sSSq, (long long)SS, (long long)DHH * MM, sSD, (long long)DHH,
            1.0f);

        // x = x + ctx @ Wo + bo
        gemm1<1, 2, false, false, false, false><<<gN64, 64, SM12>>>(
            pc, pwo + woff4, px, nullptr,
            pbo + l * DD, px,
            MM, DD, DD, DD, DD, DD, 0, 0, 0, 0, 0, 0, 1.0f);

        layernorm_kernel<true><<<MM, 256>>>(px, nullptr, pn,
                                            ln2g + l * DD, ln2b + l * DD);

        // h1 = relu(n @ W1 + b1) -> fp16
        gemm1<2, 2, false, true, true, false><<<gFF1, 128, SM22>>>(
            pn, pw1 + woff1, nullptr, ph1,
            pb1 + l * DFF, nullptr,
            MM, DFF, DD, DD, DD, DFF, 0, 0, 0, 0, 0, 0, 1.0f);

        // x = x + h1 @ W2 + b2
        gemm1<1, 2, false, false, false, false><<<gN64, 64, SM12>>>(
            ph1, pw2 + woff1, px, nullptr,
            pb2 + l * DD, px,
            MM, DD, DFF, DFF, DFF, DD, 0, 0, 0, 0, 0, 0, 1.0f);
    }

    layernorm_kernel<false><<<MM, 256>>>(px, (float*)d_out, nullptr,
                                         lnfg, lnfb);
}

// round 10
// speedup vs baseline: 6.9911x; 1.1312x over previous
#include <cuda_runtime.h>
#include <cuda_fp16.h>
#include <cstdint>

// ---------------------------------------------------------------------------
// CTRL transformer forward, GB300 (compute_103 -> mma.sync path).
// Round 10: flash-attention fused kernel (score + online softmax + ctx in
// one launch; p stays in registers via C-frag == A-frag layout identity).
// GEMMs unchanged from round 9 (1-term fp16, fp32 accum).
// ---------------------------------------------------------------------------

#define BB   2
#define SS   1024
#define DD   1280
#define HH   16
#define DHH  80
#define DFF  8192
#define LL   4
#define MM   (BB * SS)
#define D3   (3 * DD)
#define ALPHA 0.11180339887498949f

typedef __half hf;

// fp32 scratch
__device__ float g_x[MM * DD];
__device__ float g_bqkv[LL * 3 * DD];
// fp16 activations
__device__ hf g_n[MM * DD];
__device__ hf g_qkv[(size_t)MM * 3 * DD];
__device__ hf g_vt[(size_t)DD * MM];                       // v transposed [d][token]
__device__ hf g_c[MM * DD];
__device__ hf g_h1[(size_t)MM * DFF];
// fp16 weights [N,K]
__device__ hf g_wqkv[(size_t)LL * 3 * DD * DD];
__device__ hf g_wo[LL * DD * DD];
__device__ hf g_w1[(size_t)LL * DD * DFF];
__device__ hf g_w2[(size_t)LL * DFF * DD];
__device__ int g_ids64;

// ---------------------------------------------------------------------------
__device__ __forceinline__ uint32_t smem_u32(const void* p) {
    uint32_t a;
    asm("{ .reg .u64 t; cvta.to.shared.u64 t, %1; cvt.u32.u64 %0, t; }"
        : "=r"(a) : "l"(p));
    return a;
}

__device__ __forceinline__ void ldsm_x4(uint32_t& r0, uint32_t& r1,
                                        uint32_t& r2, uint32_t& r3,
                                        uint32_t addr) {
    asm volatile("ldmatrix.sync.aligned.m8n8.x4.shared.b16 {%0,%1,%2,%3}, [%4];"
                 : "=r"(r0), "=r"(r1), "=r"(r2), "=r"(r3) : "r"(addr));
}

__device__ __forceinline__ void mma_f16(float* d, const uint32_t* a,
                                        uint32_t b0, uint32_t b1) {
    asm volatile(
        "mma.sync.aligned.m16n8k16.row.col.f32.f16.f16.f32 "
        "{%0,%1,%2,%3},{%4,%5,%6,%7},{%8,%9},{%0,%1,%2,%3};"
        : "+f"(d[0]), "+f"(d[1]), "+f"(d[2]), "+f"(d[3])
        : "r"(a[0]), "r"(a[1]), "r"(a[2]), "r"(a[3]), "r"(b0), "r"(b1));
}

__device__ __forceinline__ void cp16(uint32_t dst, const void* src, int sz) {
    asm volatile("cp.async.cg.shared.global [%0], [%1], 16, %2;"
                 :: "r"(dst), "l"(src), "r"(sz) : "memory");
}
#define CP_COMMIT() asm volatile("cp.async.commit_group;" ::: "memory")
#define CP_WAIT0()  asm volatile("cp.async.wait_group 0;" ::: "memory")
#define CP_WAIT1()  asm volatile("cp.async.wait_group 1;" ::: "memory")

__device__ __forceinline__ uint32_t pk2h(float a, float b) {
    __half2 h = __floats2half2_rn(a, b);
    return *reinterpret_cast<uint32_t*>(&h);
}

// ---------------------------------------------------------------------------
// detect + embed
// ---------------------------------------------------------------------------
__global__ void detect_kernel(const unsigned int* __restrict__ w) {
    __shared__ int any;
    if (threadIdx.x == 0) any = 0;
    __syncthreads();
    int loc = 0;
    for (int i = 2 * threadIdx.x + 1; i < 2048; i += 512)
        loc |= (w[i] != 0u);
    if (loc) atomicOr(&any, 1);
    __syncthreads();
    if (threadIdx.x == 0) g_ids64 = any ? 0 : 1;
}

__global__ void embed_kernel(const unsigned int* __restrict__ idw,
                             const float* __restrict__ emb,
                             float* __restrict__ x) {
    int idx = blockIdx.x * 256 + threadIdx.x;
    if (idx >= MM * DD) return;
    int d   = idx % DD;
    int row = idx / DD;
    int s   = row & (SS - 1);
    int id  = g_ids64 ? (int)idw[2 * row] : (int)idw[row];
    float val = emb[(long long)id * DD + d] * 35.77708763999664f;
    int m = (d < 640) ? d : d - 640;
    float rate = expf(-0.014391156831212787f * (float)m);
    float ang  = (float)s * rate;
    val += (d < 640) ? sinf(ang) : cosf(ang);
    x[idx] = val;
}

// ---------------------------------------------------------------------------
// weight convert+transpose: fp32 [K,N] -> fp16 [N,K]; z = layer
// ---------------------------------------------------------------------------
__global__ void wtrans_kernel(const float* __restrict__ W,
                              hf* __restrict__ oh,
                              int K, int N, size_t ostride) {
    W  += (size_t)blockIdx.z * K * N;
    oh += (size_t)blockIdx.z * ostride;
    __shared__ float tf[32][33];
    const int n0 = blockIdx.x * 32, k0 = blockIdx.y * 32;
    const int tx = threadIdx.x, ty = threadIdx.y;
#pragma unroll
    for (int i = 0; i < 4; i++)
        tf[ty + 8 * i][tx] = W[(long long)(k0 + ty + 8 * i) * N + n0 + tx];
    __syncthreads();
#pragma unroll
    for (int i = 0; i < 4; i++) {
        long long o = (long long)(n0 + ty + 8 * i) * K + k0 + tx;
        oh[o] = __float2half_rn(tf[tx][ty + 8 * i]);
    }
}

// pack qkv bias: [L][3840] from bq,bk,bv
__global__ void packb_kernel(const float* __restrict__ bq,
                             const float* __restrict__ bk,
                             const float* __restrict__ bv,
                             float* __restrict__ o) {
    int i = blockIdx.x * 256 + threadIdx.x;
    if (i >= LL * 3 * DD) return;
    int l = i / (3 * DD), j = i % (3 * DD);
    float v = (j < DD) ? bq[l * DD + j]
            : (j < 2 * DD) ? bk[l * DD + j - DD]
            : bv[l * DD + j - 2 * DD];
    o[i] = v;
}

// v transpose from packed qkv (row stride 3840): [MM,DD] -> [DD,MM]
__global__ void vtrans_kernel(const hf* __restrict__ ih,
                              hf* __restrict__ oh, int istride) {
    __shared__ hf th[32][34];
    const int n0 = blockIdx.x * 32, m0 = blockIdx.y * 32;
    const int tx = threadIdx.x, ty = threadIdx.y;
#pragma unroll
    for (int i = 0; i < 4; i++)
        th[ty + 8 * i][tx] = ih[(long long)(m0 + ty + 8 * i) * istride + n0 + tx];
    __syncthreads();
#pragma unroll
    for (int i = 0; i < 4; i++)
        oh[(long long)(n0 + ty + 8 * i) * MM + m0 + tx] = th[tx][ty + 8 * i];
}

// ---------------------------------------------------------------------------
// LayerNorm
// ---------------------------------------------------------------------------
__device__ __forceinline__ float warp_sum(float v) {
#pragma unroll
    for (int o = 16; o; o >>= 1) v += __shfl_xor_sync(0xffffffffu, v, o);
    return v;
}

template <bool HOUT>
__global__ void layernorm_kernel(const float* __restrict__ x,
                                 float* __restrict__ o,
                                 hf* __restrict__ oh,
                                 const float* __restrict__ g,
                                 const float* __restrict__ b) {
    const int row = blockIdx.x;
    const int t   = threadIdx.x;
    const float* xr = x + (long long)row * DD;
    __shared__ float red[8];
    float v[5];
    float s = 0.0f;
#pragma unroll
    for (int i = 0; i < 5; i++) { v[i] = xr[t + 256 * i]; s += v[i]; }
    s = warp_sum(s);
    if ((t & 31) == 0) red[t >> 5] = s;
    __syncthreads();
    float mu = (red[0] + red[1] + red[2] + red[3] +
                red[4] + red[5] + red[6] + red[7]) * (1.0f / 1280.0f);
    __syncthreads();
    float q = 0.0f;
#pragma unroll
    for (int i = 0; i < 5; i++) { float dv = v[i] - mu; q += dv * dv; }
    q = warp_sum(q);
    if ((t & 31) == 0) red[t >> 5] = q;
    __syncthreads();
    float var = (red[0] + red[1] + red[2] + red[3] +
                 red[4] + red[5] + red[6] + red[7]) * (1.0f / 1280.0f);
    float rstd = rsqrtf(var + 1e-6f);
    const long long ro = (long long)row * DD;
#pragma unroll
    for (int i = 0; i < 5; i++) {
        int c = t + 256 * i;
        float y = (v[i] - mu) * rstd * g[c] + b[c];
        if (HOUT) oh[ro + c] = __float2half_rn(y);
        else      o[ro + c]  = y;
    }
}

// ---------------------------------------------------------------------------
// Flash attention: one CTA = (batch-head, 128-row q tile). 8 warps x 16 rows.
// s = q@k^T in regs -> online softmax -> p (C-frag == A-frag identity) ->
// o += p @ vt. Causal: tiles j <= qt only; diagonal tile masked elementwise.
// q/k tiles [128 x 80] fp16 row stride 176B; v tile [80 d x 128 tok] 272B.
// ---------------------------------------------------------------------------
#define FQ_OF 0
#define FK_OF 22528
#define FV_OF 67584
#define SMEM_FLASH 111104

__global__ void __launch_bounds__(256, 1)
flash_kernel(const hf* __restrict__ qkv, const hf* __restrict__ vt,
             hf* __restrict__ ctx) {
    const int z  = blockIdx.x;
    const int qt = 7 - (z >> 5);          // largest-work q tiles first
    const int bh = z & 31;
    const int zb = bh >> 4, zh = bh & 15;

    extern __shared__ char sm[];
    const uint32_t smb = smem_u32(sm);

    const int tid = threadIdx.x;
    const int wid = tid >> 5, lane = tid & 31;
    const int g = lane >> 2, t = lane & 3;
    const int lrow = lane & 15, lcol = (lane >> 4) << 3;
    const int wr0 = wid * 16;             // warp's local q-row base

    const long long qtok0 = (long long)zb * SS + qt * 128;
    const hf* qbase = qkv + qtok0 * D3 + zh * DHH;
    const hf* kbase = qkv + (long long)zb * SS * D3 + DD + zh * DHH;
    const hf* vbase = vt + (long long)(zh * DHH) * MM + zb * SS;

    // q fill (once)
    for (int i = tid; i < 1280; i += 256) {
        int r = i / 10, c = i % 10;
        cp16(smb + FQ_OF + r * 176 + c * 16, qbase + (long long)r * D3 + c * 8, 16);
    }
    auto fillK = [&](int j) {
        const uint32_t kb = smb + FK_OF + (j & 1) * 22528;
        const hf* ks = kbase + (long long)(j * 128) * D3;
        for (int i = tid; i < 1280; i += 256) {
            int r = i / 10, c = i % 10;
            cp16(kb + r * 176 + c * 16, ks + (long long)r * D3 + c * 8, 16);
        }
        const uint32_t vb = smb + FV_OF + (j & 1) * 21760;
        const hf* vs = vbase + j * 128;
        for (int i = tid; i < 1280; i += 256) {
            int r = i >> 4, c = i & 15;
            cp16(vb + r * 272 + c * 16, vs + (long long)r * MM + c * 8, 16);
        }
    };
    fillK(0); CP_COMMIT();
    if (qt >= 1) { fillK(1); CP_COMMIT(); }

    float o[10][4] = {};
    float mx0 = -3.4e38f, mx1 = -3.4e38f, sum0 = 0.0f, sum1 = 0.0f;
    const int qrow = qt * 128 + wr0 + g;          // in-sequence q index (row g)

    for (int j = 0; j <= qt; j++) {
        if (j + 1 <= qt) CP_WAIT1(); else CP_WAIT0();
        __syncthreads();

        const uint32_t kb = smb + FK_OF + (j & 1) * 22528;
        const uint32_t vb = smb + FV_OF + (j & 1) * 21760;

        // ---- s = q @ k^T (16 x 128 per warp) ----
        float s[16][4] = {};
#pragma unroll
        for (int kc = 0; kc < 5; kc++) {
            uint32_t a[4];
            ldsm_x4(a[0], a[1], a[2], a[3],
                    smb + FQ_OF + (wr0 + lrow) * 176 + (kc * 16 + lcol) * 2);
#pragma unroll
            for (int nfp = 0; nfp < 8; nfp++) {
                uint32_t b[4];
                ldsm_x4(b[0], b[1], b[2], b[3],
                        kb + (nfp * 16 + lrow) * 176 + (kc * 16 + lcol) * 2);
                mma_f16(s[2 * nfp],     a, b[0], b[2]);
                mma_f16(s[2 * nfp + 1], a, b[1], b[3]);
            }
        }

        // ---- scale + causal mask + tile row-max ----
        const bool diag = (j == qt);
        const int kb0 = j * 128;
        float tm0 = -3.4e38f, tm1 = -3.4e38f;
#pragma unroll
        for (int nf = 0; nf < 16; nf++) {
            const int col = kb0 + nf * 8 + 2 * t;
#pragma unroll
            for (int e = 0; e < 2; e++) {
                float v0 = s[nf][e]     * ALPHA;
                float v1 = s[nf][e + 2] * ALPHA;
                if (diag) {
                    if (col + e > qrow)     v0 = -3.4e38f;
                    if (col + e > qrow + 8) v1 = -3.4e38f;
                }
                s[nf][e] = v0; s[nf][e + 2] = v1;
                tm0 = fmaxf(tm0, v0); tm1 = fmaxf(tm1, v1);
            }
        }
        tm0 = fmaxf(tm0, __shfl_xor_sync(0xffffffffu, tm0, 1));
        tm0 = fmaxf(tm0, __shfl_xor_sync(0xffffffffu, tm0, 2));
        tm1 = fmaxf(tm1, __shfl_xor_sync(0xffffffffu, tm1, 1));
        tm1 = fmaxf(tm1, __shfl_xor_sync(0xffffffffu, tm1, 2));

        const float nmx0 = fmaxf(mx0, tm0), nmx1 = fmaxf(mx1, tm1);
        const float sc0 = expf(mx0 - nmx0), sc1 = expf(mx1 - nmx1);
        mx0 = nmx0; mx1 = nmx1;

        // ---- exp -> p A-frags (C-frag == A-frag identity) + row sums ----
        uint32_t pA[8][4];
        float ts0 = 0.0f, ts1 = 0.0f;
#pragma unroll
        for (int nf = 0; nf < 16; nf++) {
            float e0 = expf(s[nf][0] - mx0);
            float e1 = expf(s[nf][1] - mx0);
            float e2 = expf(s[nf][2] - mx1);
            float e3 = expf(s[nf][3] - mx1);
            ts0 += e0 + e1; ts1 += e2 + e3;
            const int kc2 = nf >> 1, hi = nf & 1;
            pA[kc2][hi * 2]     = pk2h(e0, e1);
            pA[kc2][hi * 2 + 1] = pk2h(e2, e3);
        }
        ts0 += __shfl_xor_sync(0xffffffffu, ts0, 1);
        ts0 += __shfl_xor_sync(0xffffffffu, ts0, 2);
        ts1 += __shfl_xor_sync(0xffffffffu, ts1, 1);
        ts1 += __shfl_xor_sync(0xffffffffu, ts1, 2);
        sum0 = sum0 * sc0 + ts0;
        sum1 = sum1 * sc1 + ts1;

        // ---- rescale o, then o += p @ vt ----
#pragma unroll
        for (int nf = 0; nf < 10; nf++) {
            o[nf][0] *= sc0; o[nf][1] *= sc0;
            o[nf][2] *= sc1; o[nf][3] *= sc1;
        }
#pragma unroll
        for (int nfp2 = 0; nfp2 < 5; nfp2++) {
#pragma unroll
            for (int kc2 = 0; kc2 < 8; kc2++) {
                uint32_t b[4];
                ldsm_x4(b[0], b[1], b[2], b[3],
                        vb + (nfp2 * 16 + lrow) * 272 + (kc2 * 16 + lcol) * 2);
                mma_f16(o[2 * nfp2],     pA[kc2], b[0], b[2]);
                mma_f16(o[2 * nfp2 + 1], pA[kc2], b[1], b[3]);
            }
        }

        __syncthreads();
        if (j + 2 <= qt) { fillK(j + 2); CP_COMMIT(); }
    }

    // ---- normalize + write ctx [token][DD] fp16 ----
    const float inv0 = 1.0f / sum0, inv1 = 1.0f / sum1;
    const long long r0 = (qtok0 + wr0 + g) * DD + zh * DHH;
    const long long r1 = r0 + 8LL * DD;
#pragma unroll
    for (int nf = 0; nf < 10; nf++) {
        const int d = nf * 8 + 2 * t;
        *(uint32_t*)(ctx + r0 + d) = pk2h(o[nf][0] * inv0, o[nf][1] * inv0);
        *(uint32_t*)(ctx + r1 + d) = pk2h(o[nf][2] * inv1, o[nf][3] * inv1);
    }
}

// ---------------------------------------------------------------------------
// fp16 GEMM (unchanged from round 9): C = alpha*A@B^T [+bias][relu][+resid]
// ---------------------------------------------------------------------------
template <int MW, int NW, bool RELU, bool HOUT>
__global__ void __launch_bounds__(MW * NW * 32)
gemm1(const hf* __restrict__ A, const hf* __restrict__ B,
      float* __restrict__ C, hf* __restrict__ Ch,
      const float* __restrict__ bias, const float* __restrict__ resid,
      int M, int N, int K, int lda, int ldb, int ldc, float alpha) {
    constexpr int AR  = 64 * MW;
    constexpr int BR  = 64 * NW;
    constexpr int BD  = MW * NW * 32;
    constexpr int A_OF = 0;
    constexpr int B_OF = AR * 80;
    constexpr int STG  = (AR + BR) * 80;

    const int m0 = blockIdx.y * AR;
    const int n0 = blockIdx.x * BR;

    extern __shared__ char sm[];
    const uint32_t smb = smem_u32(sm);

    const int tid  = threadIdx.x;
    const int wid  = tid >> 5;
    const int lane = tid & 31;
    const int wm   = wid / NW;
    const int wn   = wid % NW;

    const int nst = (K + 31) >> 5;

    auto fill = [&](int s) {
        const uint32_t sb = smb + (uint32_t)((s & 1) * STG);
        const int kbase = s << 5;
#pragma unroll
        for (int i = tid; i < AR * 4; i += BD) {
            const int row = i >> 2, c = i & 3;
            const int col = kbase + (c << 3);
            const int sz  = (col < K) ? 16 : 0;
            const long long go = (long long)(m0 + row) * lda + col;
            cp16(sb + row * 80 + c * 16 + A_OF, A + (sz ? go : 0), sz);
        }
#pragma unroll
        for (int i = tid; i < BR * 4; i += BD) {
            const int row = i >> 2, c = i & 3;
            const int col = kbase + (c << 3);
            const int sz  = (col < K && (n0 + row) < N) ? 16 : 0;
            const long long go = (long long)(n0 + row) * ldb + col;
            cp16(sb + row * 80 + c * 16 + B_OF, B + (sz ? go : 0), sz);
        }
    };

    float acc[4][8][4] = {};

    fill(0);
    CP_COMMIT();

    const int lrow = lane & 15;
    const int lcol = (lane >> 4) << 3;

    for (int s = 0; s < nst; s++) {
        CP_WAIT0();
        __syncthreads();
        if (s + 1 < nst) { fill(s + 1); CP_COMMIT(); }

        const uint32_t sb = smb + (uint32_t)((s & 1) * STG);
#pragma unroll
        for (int ks = 0; ks < 2; ks++) {
            const int kk = ks << 4;
            uint32_t af[4][4];
#pragma unroll
            for (int mf = 0; mf < 4; mf++) {
                uint32_t ra = sb + (uint32_t)((wm * 64 + mf * 16 + lrow) * 80
                                              + (kk + lcol) * 2);
                ldsm_x4(af[mf][0], af[mf][1], af[mf][2], af[mf][3], ra + A_OF);
            }
#pragma unroll
            for (int nfp = 0; nfp < 4; nfp++) {
                uint32_t rb = sb + (uint32_t)((wn * 64 + nfp * 16 + lrow) * 80
                                              + (kk + lcol) * 2);
                uint32_t bh[4];
                ldsm_x4(bh[0], bh[1], bh[2], bh[3], rb + B_OF);
#pragma unroll
                for (int mf = 0; mf < 4; mf++) {
                    mma_f16(acc[mf][2 * nfp],     af[mf], bh[0], bh[2]);
                    mma_f16(acc[mf][2 * nfp + 1], af[mf], bh[1], bh[3]);
                }
            }
        }
    }

    const int g = lane >> 2;
    const int t = lane & 3;
#pragma unroll
    for (int mf = 0; mf < 4; mf++) {
        const int gm0 = m0 + wm * 64 + mf * 16 + g;
        const long long ro0 = (long long)gm0 * ldc;
        const long long ro1 = ro0 + 8LL * ldc;
#pragma unroll
        for (int nf = 0; nf < 8; nf++) {
            const int gn = n0 + wn * 64 + nf * 8 + t * 2;
            if (gn < N) {
                float c0 = acc[mf][nf][0] * alpha;
                float c1 = acc[mf][nf][1] * alpha;
                float c2 = acc[mf][nf][2] * alpha;
                float c3 = acc[mf][nf][3] * alpha;
                if (bias) {
                    float b0 = bias[gn], b1 = bias[gn + 1];
                    c0 += b0; c1 += b1; c2 += b0; c3 += b1;
                }
                if (RELU) {
                    c0 = fmaxf(c0, 0.0f); c1 = fmaxf(c1, 0.0f);
                    c2 = fmaxf(c2, 0.0f); c3 = fmaxf(c3, 0.0f);
                }
                if (!HOUT) {
                    if (resid) {
                        c0 += resid[ro0 + gn]; c1 += resid[ro0 + gn + 1];
                        c2 += resid[ro1 + gn]; c3 += resid[ro1 + gn + 1];
                    }
                    *(float2*)(C + ro0 + gn) = make_float2(c0, c1);
                    *(float2*)(C + ro1 + gn) = make_float2(c2, c3);
                } else {
                    *(uint32_t*)(Ch + ro0 + gn) = pk2h(c0, c1);
                    *(uint32_t*)(Ch + ro1 + gn) = pk2h(c2, c3);
                }
            }
        }
    }
}

#define SM22 (2 * (128 + 128) * 80)   // 40960
#define SM12 (2 * (64 + 128) * 80)    // 30720

// ---------------------------------------------------------------------------
// Host launcher (graph-capturable: kernel launches only)
// ---------------------------------------------------------------------------
extern "C" void kernel_launch(void* const* d_in, const int* in_sizes, int n_in,
                              void* d_out, int out_size) {
    const unsigned int* idw = (const unsigned int*)d_in[0];
    const float* emb  = (const float*)d_in[1];
    const float* Wq   = (const float*)d_in[2];
    const float* Wk   = (const float*)d_in[3];
    const float* Wv   = (const float*)d_in[4];
    const float* Wo   = (const float*)d_in[5];
    const float* pbq  = (const float*)d_in[6];
    const float* pbk  = (const float*)d_in[7];
    const float* pbv  = (const float*)d_in[8];
    const float* pbo  = (const float*)d_in[9];
    const float* W1   = (const float*)d_in[10];
    const float* pb1  = (const float*)d_in[11];
    const float* W2   = (const float*)d_in[12];
    const float* pb2  = (const float*)d_in[13];
    const float* ln1g = (const float*)d_in[14];
    const float* ln1b = (const float*)d_in[15];
    const float* ln2g = (const float*)d_in[16];
    const float* ln2b = (const float*)d_in[17];
    const float* lnfg = (const float*)d_in[18];
    const float* lnfb = (const float*)d_in[19];

    float *px, *pbqkv;
    hf *pn, *pqkv, *pvt, *pc, *ph1;
    hf *pwqkv, *pwo, *pw1, *pw2;
    cudaGetSymbolAddress((void**)&px,    g_x);
    cudaGetSymbolAddress((void**)&pbqkv, g_bqkv);
    cudaGetSymbolAddress((void**)&pn,    g_n);
    cudaGetSymbolAddress((void**)&pqkv,  g_qkv);
    cudaGetSymbolAddress((void**)&pvt,   g_vt);
    cudaGetSymbolAddress((void**)&pc,    g_c);
    cudaGetSymbolAddress((void**)&ph1,   g_h1);
    cudaGetSymbolAddress((void**)&pwqkv, g_wqkv);
    cudaGetSymbolAddress((void**)&pwo,   g_wo);
    cudaGetSymbolAddress((void**)&pw1,   g_w1);
    cudaGetSymbolAddress((void**)&pw2,   g_w2);

    cudaFuncSetAttribute(gemm1<2, 2, false, true>,
                         cudaFuncAttributeMaxDynamicSharedMemorySize, SM22);
    cudaFuncSetAttribute(gemm1<2, 2, true,  true>,
                         cudaFuncAttributeMaxDynamicSharedMemorySize, SM22);
    cudaFuncSetAttribute(gemm1<1, 2, false, false>,
                         cudaFuncAttributeMaxDynamicSharedMemorySize, SM12);
    cudaFuncSetAttribute(flash_kernel,
                         cudaFuncAttributeMaxDynamicSharedMemorySize, SMEM_FLASH);

    detect_kernel<<<1, 256>>>(idw);
    embed_kernel<<<(MM * DD + 255) / 256, 256>>>(idw, emb, px);

    {
        dim3 blk(32, 8);
        const size_t oQKV = (size_t)3 * DD * DD;
        wtrans_kernel<<<dim3(DD / 32, DD / 32, LL), blk>>>(Wq, pwqkv, DD, DD, oQKV);
        wtrans_kernel<<<dim3(DD / 32, DD / 32, LL), blk>>>(
            Wk, pwqkv + (size_t)DD * DD, DD, DD, oQKV);
        wtrans_kernel<<<dim3(DD / 32, DD / 32, LL), blk>>>(
            Wv, pwqkv + (size_t)2 * DD * DD, DD, DD, oQKV);
        wtrans_kernel<<<dim3(DD / 32, DD / 32, LL), blk>>>(Wo, pwo, DD, DD,
                                                           (size_t)DD * DD);
        wtrans_kernel<<<dim3(DFF / 32, DD / 32, LL), blk>>>(W1, pw1, DD, DFF,
                                                            (size_t)DD * DFF);
        wtrans_kernel<<<dim3(DD / 32, DFF / 32, LL), blk>>>(W2, pw2, DFF, DD,
                                                            (size_t)DFF * DD);
        packb_kernel<<<(LL * 3 * DD + 255) / 256, 256>>>(pbq, pbk, pbv, pbqkv);
    }

    const dim3 gQKV(D3 / 128, MM / 128);         // 480
    const dim3 gN64(DD / 128, MM / 64);          // 320
    const dim3 gFF1(DFF / 128, MM / 128);        // 1024

    for (int l = 0; l < LL; l++) {
        const size_t woff4 = (size_t)l * DD * DD;
        const size_t woffQ = (size_t)l * 3 * DD * DD;
        const size_t woff1 = (size_t)l * DD * DFF;

        layernorm_kernel<true><<<MM, 256>>>(px, nullptr, pn,
                                            ln1g + l * DD, ln1b + l * DD);

        // fused qkv projection -> packed [MM, 3840] fp16
        gemm1<2, 2, false, true><<<gQKV, 128, SM22>>>(
            pn, pwqkv + woffQ, nullptr, pqkv,
            pbqkv + l * D3, nullptr,
            MM, D3, DD, DD, DD, D3, 1.0f);

        vtrans_kernel<<<dim3(DD / 32, MM / 32), dim3(32, 8)>>>(
            pqkv + 2 * DD, pvt, D3);

        // fused attention: scores + softmax + ctx
        flash_kernel<<<256, 256, SMEM_FLASH>>>(pqkv, pvt, pc);

        // x = x + ctx @ Wo + bo
        gemm1<1, 2, false, false><<<gN64, 64, SM12>>>(
            pc, pwo + woff4, px, nullptr,
            pbo + l * DD, px,
            MM, DD, DD, DD, DD, DD, 1.0f);

        layernorm_kernel<true><<<MM, 256>>>(px, nullptr, pn,
                                            ln2g + l * DD, ln2b + l * DD);

        // h1 = relu(n @ W1 + b1) -> fp16
        gemm1<2, 2, true, true><<<gFF1, 128, SM22>>>(
            pn, pw1 + woff1, nullptr, ph1,
            pb1 + l * DFF, nullptr,
            MM, DFF, DD, DD, DD, DFF, 1.0f);

        // x = x + h1 @ W2 + b2
        gemm1<1, 2, false, false><<<gN64, 64, SM12>>>(
            ph1, pw2 + woff1, px, nullptr,
            pb2 + l * DD, px,
            MM, DD, DFF, DFF, DFF, DD, 1.0f);
    }

    layernorm_kernel<false><<<MM, 256>>>(px, (float*)d_out, nullptr,
                                         lnfg, lnfb);
}